// round 3
// baseline (speedup 1.0000x reference)
#include <cuda_runtime.h>
#include <math.h>
#include <stdint.h>

#define B_    2
#define T_    4096
#define C_    768
#define H_    12
#define D_    64
#define QKV3  2304
#define NTOK  (B_ * T_)

// Scratch (allocation-free: __device__ globals)
__device__ float g_xh[(size_t)NTOK * C_];
__device__ float g_xl[(size_t)NTOK * C_];
__device__ float g_qkv[(size_t)NTOK * QKV3];
__device__ float g_ah[(size_t)NTOK * C_];
__device__ float g_al[(size_t)NTOK * C_];
__device__ float g_wqh[(size_t)QKV3 * C_];
__device__ float g_wql[(size_t)QKV3 * C_];
__device__ float g_woh[(size_t)C_ * C_];
__device__ float g_wol[(size_t)C_ * C_];

__device__ __forceinline__ uint32_t f2tf(float x) {
    uint32_t r;
    asm("cvt.rna.tf32.f32 %0, %1;" : "=r"(r) : "f"(x));
    return r;
}

__device__ __forceinline__ void mma8(float* d, const uint32_t* a, const uint32_t* b) {
    asm volatile(
        "mma.sync.aligned.m16n8k8.row.col.f32.tf32.tf32.f32 "
        "{%0,%1,%2,%3}, {%4,%5,%6,%7}, {%8,%9}, {%0,%1,%2,%3};\n"
        : "+f"(d[0]), "+f"(d[1]), "+f"(d[2]), "+f"(d[3])
        : "r"(a[0]), "r"(a[1]), "r"(a[2]), "r"(a[3]), "r"(b[0]), "r"(b[1]));
}

// ---------------------------------------------------------------------------
// Weight split: w -> (tf32 hi, tf32 lo)
// ---------------------------------------------------------------------------
__global__ void split_kernel(const float* __restrict__ w,
                             float* __restrict__ hi, float* __restrict__ lo, int n)
{
    int i = blockIdx.x * 256 + threadIdx.x;
    if (i < n) {
        float v = w[i];
        uint32_t h = f2tf(v);
        hi[i] = __uint_as_float(h);
        lo[i] = __uint_as_float(f2tf(v - __uint_as_float(h)));
    }
}

// ---------------------------------------------------------------------------
// LayerNorm -> pre-split (hi, lo) output
// ---------------------------------------------------------------------------
__global__ void __launch_bounds__(256) ln_kernel(
    const float* __restrict__ x, const float* __restrict__ gamma,
    const float* __restrict__ beta, float* __restrict__ oh, float* __restrict__ ol)
{
    int row = blockIdx.x;
    int tid = threadIdx.x;
    const float* xr = x + (size_t)row * C_;
    float v0 = xr[tid], v1 = xr[tid + 256], v2 = xr[tid + 512];
    float s  = v0 + v1 + v2;
    float ss = v0 * v0 + v1 * v1 + v2 * v2;
    #pragma unroll
    for (int o = 16; o > 0; o >>= 1) {
        s  += __shfl_xor_sync(0xffffffffu, s,  o);
        ss += __shfl_xor_sync(0xffffffffu, ss, o);
    }
    __shared__ float sh_s[8], sh_q[8];
    int w = tid >> 5;
    if ((tid & 31) == 0) { sh_s[w] = s; sh_q[w] = ss; }
    __syncthreads();
    float S = 0.f, Q = 0.f;
    #pragma unroll
    for (int i = 0; i < 8; i++) { S += sh_s[i]; Q += sh_q[i]; }
    float mean = S * (1.0f / C_);
    float var  = Q * (1.0f / C_) - mean * mean;
    float rstd = rsqrtf(var + 1e-5f);
    float* ohr = oh + (size_t)row * C_;
    float* olr = ol + (size_t)row * C_;
    float vv[3] = {v0, v1, v2};
    #pragma unroll
    for (int j = 0; j < 3; j++) {
        int c = tid + j * 256;
        float y = (vv[j] - mean) * rstd * gamma[c] + beta[c];
        uint32_t h = f2tf(y);
        ohr[c] = __uint_as_float(h);
        olr[c] = __uint_as_float(f2tf(y - __uint_as_float(h)));
    }
}

// ---------------------------------------------------------------------------
// GEMM NT, 3xTF32, pre-split operands, fragment-ordered smem, double-buffered.
// C[m,n] = sum_k A[m,k]*B[n,k] (+bias). Block 128x128, BK=16, 256 thr, 8 warps.
// smem stage layout (floats): [AH 2048][AL 2048][BH 2048][BL 2048] x 2 stages.
// A frag idx(m,k) = ((m>>4)*2+(k>>3))*128 + (((m&7)<<2)|(k&3))*4 + ((m>>3)&1) + 2*((k>>2)&1)
// B frag idx(n,k) = ((n>>3)*2+(k>>3))*64  + (((n&7)<<2)|(k&3))*2 + ((k>>2)&1)
// ---------------------------------------------------------------------------
__global__ void __launch_bounds__(256, 2) gemm3(
    const float* __restrict__ AHg, const float* __restrict__ ALg,
    const float* __restrict__ BHg, const float* __restrict__ BLg,
    const float* __restrict__ bias, float* __restrict__ Cm,
    int M, int N, int K)
{
    extern __shared__ float smg[];
    int tid  = threadIdx.x;
    int lane = tid & 31, warp = tid >> 5;
    int lr = lane >> 2, lc = lane & 3;
    int wm = (warp & 1) * 64, wn = (warp >> 1) * 32;
    int m0 = blockIdx.y * 128, n0 = blockIdx.x * 128;
    int lrow = tid >> 1, lk = (tid & 1) * 8;

    const float* ApH = AHg + (size_t)(m0 + lrow) * K + lk;
    const float* ApL = ALg + (size_t)(m0 + lrow) * K + lk;
    const float* BpH = BHg + (size_t)(n0 + lrow) * K + lk;
    const float* BpL = BLg + (size_t)(n0 + lrow) * K + lk;

    // per-thread scatter indices (k = lk + j)
    int ia[8], ib[8];
    #pragma unroll
    for (int j = 0; j < 8; j++) {
        int k = lk + j;
        ia[j] = ((lrow >> 4) * 2 + (k >> 3)) * 128 + (((lrow & 7) << 2) | (k & 3)) * 4
              + ((lrow >> 3) & 1) + 2 * ((k >> 2) & 1);
        ib[j] = ((lrow >> 3) * 2 + (k >> 3)) * 64 + (((lrow & 7) << 2) | (k & 3)) * 2
              + ((k >> 2) & 1);
    }

    float acc[4][4][4];
    #pragma unroll
    for (int i = 0; i < 4; i++)
        #pragma unroll
        for (int j = 0; j < 4; j++)
            #pragma unroll
            for (int r = 0; r < 4; r++) acc[i][j][r] = 0.f;

    float4 pah[2], pal[2], pbh[2], pbl[2];
    #define LDG16(k0) do { \
        pah[0] = *(const float4*)(ApH + (k0));     pah[1] = *(const float4*)(ApH + (k0) + 4); \
        pal[0] = *(const float4*)(ApL + (k0));     pal[1] = *(const float4*)(ApL + (k0) + 4); \
        pbh[0] = *(const float4*)(BpH + (k0));     pbh[1] = *(const float4*)(BpH + (k0) + 4); \
        pbl[0] = *(const float4*)(BpL + (k0));     pbl[1] = *(const float4*)(BpL + (k0) + 4); \
    } while (0)
    #define STS16(st) do { \
        float* base = smg + (st) * 8192; \
        const float* ah = (const float*)pah; const float* al = (const float*)pal; \
        const float* bh = (const float*)pbh; const float* bl = (const float*)pbl; \
        _Pragma("unroll") \
        for (int j = 0; j < 8; j++) { \
            base[ia[j]]        = ah[j]; \
            base[2048 + ia[j]] = al[j]; \
            base[4096 + ib[j]] = bh[j]; \
            base[6144 + ib[j]] = bl[j]; \
        } \
    } while (0)

    LDG16(0);
    STS16(0);
    __syncthreads();

    int nk = K / 16;
    for (int it = 0; it < nk; it++) {
        if (it + 1 < nk) LDG16((it + 1) * 16);
        const float* S = smg + (it & 1) * 8192;
        #pragma unroll
        for (int ks = 0; ks < 2; ks++) {
            uint32_t ra[4][4], la[4][4], rb[4][2], lb[4][2];
            #pragma unroll
            for (int mi = 0; mi < 4; mi++) {
                int tm = (wm >> 4) + mi;
                float4 h4 = *(const float4*)&S[(tm * 2 + ks) * 128 + lane * 4];
                float4 l4 = *(const float4*)&S[2048 + (tm * 2 + ks) * 128 + lane * 4];
                ra[mi][0] = __float_as_uint(h4.x); ra[mi][1] = __float_as_uint(h4.y);
                ra[mi][2] = __float_as_uint(h4.z); ra[mi][3] = __float_as_uint(h4.w);
                la[mi][0] = __float_as_uint(l4.x); la[mi][1] = __float_as_uint(l4.y);
                la[mi][2] = __float_as_uint(l4.z); la[mi][3] = __float_as_uint(l4.w);
            }
            #pragma unroll
            for (int nj = 0; nj < 4; nj++) {
                int tn = (wn >> 3) + nj;
                float2 h2 = *(const float2*)&S[4096 + (tn * 2 + ks) * 64 + lane * 2];
                float2 l2 = *(const float2*)&S[6144 + (tn * 2 + ks) * 64 + lane * 2];
                rb[nj][0] = __float_as_uint(h2.x); rb[nj][1] = __float_as_uint(h2.y);
                lb[nj][0] = __float_as_uint(l2.x); lb[nj][1] = __float_as_uint(l2.y);
            }
            #pragma unroll
            for (int mi = 0; mi < 4; mi++)
                #pragma unroll
                for (int nj = 0; nj < 4; nj++) {
                    mma8(acc[mi][nj], ra[mi], rb[nj]);
                    mma8(acc[mi][nj], la[mi], rb[nj]);
                    mma8(acc[mi][nj], ra[mi], lb[nj]);
                }
        }
        if (it + 1 < nk) STS16((it + 1) & 1);
        __syncthreads();
    }

    #pragma unroll
    for (int mi = 0; mi < 4; mi++)
        #pragma unroll
        for (int nj = 0; nj < 4; nj++) {
            int row = m0 + wm + mi * 16 + lr;
            int col = n0 + wn + nj * 8 + 2 * lc;
            float bb0 = bias ? bias[col]     : 0.f;
            float bb1 = bias ? bias[col + 1] : 0.f;
            *(float2*)(Cm + (size_t)row * N + col) =
                make_float2(acc[mi][nj][0] + bb0, acc[mi][nj][1] + bb1);
            *(float2*)(Cm + (size_t)(row + 8) * N + col) =
                make_float2(acc[mi][nj][2] + bb0, acc[mi][nj][3] + bb1);
        }
}

// ---------------------------------------------------------------------------
// Flash attention, tf32 tensor cores. Block = 256 threads (8 warps), q-tile 128.
// K/V in fragment-ordered smem; P per-warp in A-fragment order.
// Block-causal by frame: key loop bound only, no masking.
// Output written pre-split (hi, lo) for the out-projection.
// ---------------------------------------------------------------------------
__global__ void __launch_bounds__(256, 2) attn_tf32(
    const float* __restrict__ qkv, float* __restrict__ oh, float* __restrict__ ol)
{
    extern __shared__ float sm[];
    float* Kf = sm;            // 4096
    float* Vf = sm + 4096;     // 4096
    float* Pf = sm + 8192;     // 8192 (1024 per warp)

    int tid  = threadIdx.x;
    int lane = tid & 31, warp = tid >> 5;
    int lr = lane >> 2, lc = lane & 3;
    int qt = (gridDim.x - 1) - blockIdx.x;   // heavy frames first
    int bh = blockIdx.y;
    int b = bh / H_, h = bh % H_;
    int r0 = qt * 128;
    int q0w = warp * 16;
    const float* base = qkv + (size_t)b * T_ * QKV3 + h * D_;

    // Q fragments straight from global (L2-resident), scale folded
    uint32_t qf[8][4];
    {
        const float* q0 = base + (size_t)(r0 + q0w + lr) * QKV3;
        const float* q1 = base + (size_t)(r0 + q0w + 8 + lr) * QKV3;
        #pragma unroll
        for (int ks = 0; ks < 8; ks++) {
            qf[ks][0] = f2tf(q0[ks * 8 + lc] * 0.125f);
            qf[ks][1] = f2tf(q1[ks * 8 + lc] * 0.125f);
            qf[ks][2] = f2tf(q0[ks * 8 + 4 + lc] * 0.125f);
            qf[ks][3] = f2tf(q1[ks * 8 + 4 + lc] * 0.125f);
        }
    }

    float o[8][4];
    #pragma unroll
    for (int nj = 0; nj < 8; nj++)
        #pragma unroll
        for (int r = 0; r < 4; r++) o[nj][r] = 0.f;
    float m0r = -INFINITY, m1r = -INFINITY, l0 = 0.f, l1 = 0.f;
    float* Pw = Pf + warp * 1024;

    int nkt = ((qt >> 1) + 1) << 2;   // (frame+1)*4 key tiles of 64

    for (int kt = 0; kt < nkt; kt++) {
        __syncthreads();
        // fill K,V fragment smem (tf32)
        #pragma unroll
        for (int c = 0; c < 4; c++) {
            int ss = (tid >> 4) + c * 16;
            int dd = (tid & 15) * 4;
            const float* kp = base + 768  + (size_t)(kt * 64 + ss) * QKV3 + dd;
            const float* vp = base + 1536 + (size_t)(kt * 64 + ss) * QKV3 + dd;
            float4 k4 = *(const float4*)kp;
            float4 v4 = *(const float4*)vp;
            float ka[4] = {k4.x, k4.y, k4.z, k4.w};
            float va[4] = {v4.x, v4.y, v4.z, v4.w};
            #pragma unroll
            for (int j = 0; j < 4; j++) {
                int d = dd + j;
                Kf[((d >> 3) * 8 + (ss >> 3)) * 64 + ((((ss & 7) << 2) | (d & 3)) << 1) + ((d & 7) >> 2)]
                    = __uint_as_float(f2tf(ka[j]));
                Vf[((ss >> 3) * 8 + (d >> 3)) * 64 + ((((d & 7) << 2) | (ss & 3)) << 1) + ((ss & 7) >> 2)]
                    = __uint_as_float(f2tf(va[j]));
            }
        }
        __syncthreads();

        // S = Q K^T (per warp 16x64)
        float s[8][4];
        #pragma unroll
        for (int nj = 0; nj < 8; nj++)
            #pragma unroll
            for (int r = 0; r < 4; r++) s[nj][r] = 0.f;
        #pragma unroll
        for (int ks = 0; ks < 8; ks++)
            #pragma unroll
            for (int nj = 0; nj < 8; nj++) {
                float2 kb = *(const float2*)&Kf[(ks * 8 + nj) * 64 + lane * 2];
                uint32_t bb[2] = {__float_as_uint(kb.x), __float_as_uint(kb.y)};
                mma8(s[nj], qf[ks], bb);
            }

        // online softmax
        float mx0 = -INFINITY, mx1 = -INFINITY;
        #pragma unroll
        for (int nj = 0; nj < 8; nj++) {
            mx0 = fmaxf(mx0, fmaxf(s[nj][0], s[nj][1]));
            mx1 = fmaxf(mx1, fmaxf(s[nj][2], s[nj][3]));
        }
        mx0 = fmaxf(mx0, __shfl_xor_sync(0xffffffffu, mx0, 1));
        mx0 = fmaxf(mx0, __shfl_xor_sync(0xffffffffu, mx0, 2));
        mx1 = fmaxf(mx1, __shfl_xor_sync(0xffffffffu, mx1, 1));
        mx1 = fmaxf(mx1, __shfl_xor_sync(0xffffffffu, mx1, 2));
        float nm0 = fmaxf(m0r, mx0), nm1 = fmaxf(m1r, mx1);
        float al0 = __expf(m0r - nm0), al1 = __expf(m1r - nm1);
        m0r = nm0; m1r = nm1;
        float sum0 = 0.f, sum1 = 0.f;
        #pragma unroll
        for (int nj = 0; nj < 8; nj++) {
            float p0 = __expf(s[nj][0] - nm0);
            float p1 = __expf(s[nj][1] - nm0);
            float p2 = __expf(s[nj][2] - nm1);
            float p3 = __expf(s[nj][3] - nm1);
            sum0 += p0 + p1; sum1 += p2 + p3;
            int cb = nj * 8 + 2 * lc;
            int c0i = cb, c1i = cb + 1;
            Pw[nj * 128 + (((lr & 7) << 2 | (c0i & 3)) << 2) + (((c0i & 7) >> 2) << 1)]
                = __uint_as_float(f2tf(p0));
            Pw[nj * 128 + (((lr & 7) << 2 | (c1i & 3)) << 2) + (((c1i & 7) >> 2) << 1)]
                = __uint_as_float(f2tf(p1));
            Pw[nj * 128 + (((lr & 7) << 2 | (c0i & 3)) << 2) + 1 + (((c0i & 7) >> 2) << 1)]
                = __uint_as_float(f2tf(p2));
            Pw[nj * 128 + (((lr & 7) << 2 | (c1i & 3)) << 2) + 1 + (((c1i & 7) >> 2) << 1)]
                = __uint_as_float(f2tf(p3));
        }
        sum0 += __shfl_xor_sync(0xffffffffu, sum0, 1);
        sum0 += __shfl_xor_sync(0xffffffffu, sum0, 2);
        sum1 += __shfl_xor_sync(0xffffffffu, sum1, 1);
        sum1 += __shfl_xor_sync(0xffffffffu, sum1, 2);
        l0 = l0 * al0 + sum0;
        l1 = l1 * al1 + sum1;
        #pragma unroll
        for (int nj = 0; nj < 8; nj++) {
            o[nj][0] *= al0; o[nj][1] *= al0;
            o[nj][2] *= al1; o[nj][3] *= al1;
        }
        __syncwarp();

        // O += P V
        #pragma unroll
        for (int ks = 0; ks < 8; ks++) {
            float4 pa = *(const float4*)&Pw[ks * 128 + lane * 4];
            uint32_t aa[4] = {__float_as_uint(pa.x), __float_as_uint(pa.y),
                              __float_as_uint(pa.z), __float_as_uint(pa.w)};
            #pragma unroll
            for (int nj = 0; nj < 8; nj++) {
                float2 vb = *(const float2*)&Vf[(ks * 8 + nj) * 64 + lane * 2];
                uint32_t bb[2] = {__float_as_uint(vb.x), __float_as_uint(vb.y)};
                mma8(o[nj], aa, bb);
            }
        }
    }

    // normalize + write pre-split [B,T,H*D]
    float inv0 = 1.0f / l0, inv1 = 1.0f / l1;
    int row = r0 + q0w + lr;
    size_t off = ((size_t)(b * T_ + row)) * C_ + h * D_;
    #pragma unroll
    for (int nj = 0; nj < 8; nj++) {
        int d = nj * 8 + 2 * lc;
        float v00 = o[nj][0] * inv0, v01 = o[nj][1] * inv0;
        float v10 = o[nj][2] * inv1, v11 = o[nj][3] * inv1;
        uint32_t h00 = f2tf(v00), h01 = f2tf(v01), h10 = f2tf(v10), h11 = f2tf(v11);
        *(float2*)(oh + off + d) = make_float2(__uint_as_float(h00), __uint_as_float(h01));
        *(float2*)(ol + off + d) = make_float2(
            __uint_as_float(f2tf(v00 - __uint_as_float(h00))),
            __uint_as_float(f2tf(v01 - __uint_as_float(h01))));
        *(float2*)(oh + off + 8 * C_ + d) = make_float2(__uint_as_float(h10), __uint_as_float(h11));
        *(float2*)(ol + off + 8 * C_ + d) = make_float2(
            __uint_as_float(f2tf(v10 - __uint_as_float(h10))),
            __uint_as_float(f2tf(v11 - __uint_as_float(h11))));
    }
}

// ---------------------------------------------------------------------------
extern "C" void kernel_launch(void* const* d_in, const int* in_sizes, int n_in,
                              void* d_out, int out_size)
{
    const float* x     = (const float*)d_in[0];
    const float* gamma = (const float*)d_in[1];
    const float* beta  = (const float*)d_in[2];
    const float* w_qkv = (const float*)d_in[3];
    const float* w_out = (const float*)d_in[4];
    const float* b_out = (const float*)d_in[5];
    float* out = (float*)d_out;

    float *xh, *xl, *qkv, *ah, *al, *wqh, *wql, *woh, *wol;
    cudaGetSymbolAddress((void**)&xh,  g_xh);
    cudaGetSymbolAddress((void**)&xl,  g_xl);
    cudaGetSymbolAddress((void**)&qkv, g_qkv);
    cudaGetSymbolAddress((void**)&ah,  g_ah);
    cudaGetSymbolAddress((void**)&al,  g_al);
    cudaGetSymbolAddress((void**)&wqh, g_wqh);
    cudaGetSymbolAddress((void**)&wql, g_wql);
    cudaGetSymbolAddress((void**)&woh, g_woh);
    cudaGetSymbolAddress((void**)&wol, g_wol);

    static bool attrs_set = false;
    const int gemm_smem = 65536, att_smem = 65536;
    if (!attrs_set) {
        cudaFuncSetAttribute(gemm3, cudaFuncAttributeMaxDynamicSharedMemorySize, gemm_smem);
        cudaFuncSetAttribute(attn_tf32, cudaFuncAttributeMaxDynamicSharedMemorySize, att_smem);
        attrs_set = true;
    }

    // 0) weight pre-split
    split_kernel<<<(QKV3 * C_ + 255) / 256, 256>>>(w_qkv, wqh, wql, QKV3 * C_);
    split_kernel<<<(C_ * C_ + 255) / 256, 256>>>(w_out, woh, wol, C_ * C_);

    // 1) LayerNorm -> (hi, lo)
    ln_kernel<<<NTOK, 256>>>(x, gamma, beta, xh, xl);

    // 2) QKV projection
    gemm3<<<dim3(QKV3 / 128, NTOK / 128), 256, gemm_smem>>>(
        xh, xl, wqh, wql, nullptr, qkv, NTOK, QKV3, C_);

    // 3) Flash attention -> (hi, lo)
    attn_tf32<<<dim3(T_ / 128, B_ * H_), 256, att_smem>>>(qkv, ah, al);

    // 4) Output projection + bias
    gemm3<<<dim3(C_ / 128, NTOK / 128), 256, gemm_smem>>>(
        ah, al, woh, wol, b_out, out, NTOK, C_, C_);
}

// round 4
// speedup vs baseline: 2.0898x; 2.0898x over previous
#include <cuda_runtime.h>
#include <cuda_fp16.h>
#include <math.h>
#include <stdint.h>

#define B_    2
#define T_    4096
#define C_    768
#define H_    12
#define D_    64
#define QKV3  2304
#define NTOK  (B_ * T_)

// Scratch (allocation-free: __device__ globals)
__device__ float g_xn[(size_t)NTOK * C_];
__device__ float g_qkv[(size_t)NTOK * QKV3];
__device__ float g_attn[(size_t)NTOK * C_];

// pack two floats -> f16x2 (lo = first arg in low 16 bits)
__device__ __forceinline__ uint32_t packh2(float lo, float hi) {
    uint32_t r;
    asm("cvt.rn.f16x2.f32 %0, %1, %2;" : "=r"(r) : "f"(hi), "f"(lo));
    return r;
}
__device__ __forceinline__ float h16(float v) {
    return __half2float(__float2half_rn(v));
}
__device__ __forceinline__ void mma16(float* d, const uint32_t* a, const uint32_t* b) {
    asm volatile(
        "mma.sync.aligned.m16n8k16.row.col.f32.f16.f16.f32 "
        "{%0,%1,%2,%3}, {%4,%5,%6,%7}, {%8,%9}, {%0,%1,%2,%3};\n"
        : "+f"(d[0]), "+f"(d[1]), "+f"(d[2]), "+f"(d[3])
        : "r"(a[0]), "r"(a[1]), "r"(a[2]), "r"(a[3]), "r"(b[0]), "r"(b[1]));
}

// ---------------------------------------------------------------------------
// LayerNorm over last dim (C=768). One block per row.
// ---------------------------------------------------------------------------
__global__ void __launch_bounds__(256) ln_kernel(
    const float* __restrict__ x, const float* __restrict__ gamma,
    const float* __restrict__ beta, float* __restrict__ out)
{
    int row = blockIdx.x;
    int tid = threadIdx.x;
    const float* xr = x + (size_t)row * C_;
    float v0 = xr[tid], v1 = xr[tid + 256], v2 = xr[tid + 512];
    float s  = v0 + v1 + v2;
    float ss = v0 * v0 + v1 * v1 + v2 * v2;
    #pragma unroll
    for (int o = 16; o > 0; o >>= 1) {
        s  += __shfl_xor_sync(0xffffffffu, s,  o);
        ss += __shfl_xor_sync(0xffffffffu, ss, o);
    }
    __shared__ float sh_s[8], sh_q[8];
    int w = tid >> 5;
    if ((tid & 31) == 0) { sh_s[w] = s; sh_q[w] = ss; }
    __syncthreads();
    float S = 0.f, Q = 0.f;
    #pragma unroll
    for (int i = 0; i < 8; i++) { S += sh_s[i]; Q += sh_q[i]; }
    float mean = S * (1.0f / C_);
    float var  = Q * (1.0f / C_) - mean * mean;
    float rstd = rsqrtf(var + 1e-5f);
    float* orow = out + (size_t)row * C_;
    orow[tid]       = (v0 - mean) * rstd * gamma[tid]       + beta[tid];
    orow[tid + 256] = (v1 - mean) * rstd * gamma[tid + 256] + beta[tid + 256];
    orow[tid + 512] = (v2 - mean) * rstd * gamma[tid + 512] + beta[tid + 512];
}

// ---------------------------------------------------------------------------
// GEMM NT, fp16 split x3 (hh+lh+hl ~ fp32 accurate): C[m,n]=sum_k A[m,k]B[n,k]+bias.
// Block 128x128, BK=16, 256 threads (8 warps 2x4), warp 64x32, k16 mma.
// smem u32: Aqh@0 Aql@1056 Bqh@2112 Bql@3168; per kslot stride 264 u32 (8 mod 32
// -> conflict-free uint2 fragment loads). Entry: [slot(=k2&3)*264 + row*2 + (k2>>2)].
// ---------------------------------------------------------------------------
__global__ void __launch_bounds__(256) gemm_f16x3(
    const float* __restrict__ A, const float* __restrict__ Bm,
    const float* __restrict__ bias, float* __restrict__ Cm,
    int M, int N, int K)
{
    __shared__ uint32_t smu[4224];
    int tid  = threadIdx.x;
    int lane = tid & 31, warp = tid >> 5;
    int lr = lane >> 2, lc = lane & 3;
    int wm = (warp & 1) * 64, wn = (warp >> 1) * 32;
    int m0 = blockIdx.y * 128, n0 = blockIdx.x * 128;
    int lrow = tid >> 1, comp = tid & 1;
    int lk = comp * 8;
    int sbase = lrow * 2 + comp;
    const float* Ap = A  + (size_t)(m0 + lrow) * K + lk;
    const float* Bp = Bm + (size_t)(n0 + lrow) * K + lk;

    float acc[4][4][4];
    #pragma unroll
    for (int i = 0; i < 4; i++)
        #pragma unroll
        for (int j = 0; j < 4; j++)
            #pragma unroll
            for (int r = 0; r < 4; r++) acc[i][j][r] = 0.f;

    float4 pa0 = *(const float4*)Ap;
    float4 pa1 = *(const float4*)(Ap + 4);
    float4 pb0 = *(const float4*)Bp;
    float4 pb1 = *(const float4*)(Bp + 4);

    int nk = K / 16;
    for (int it = 0; it < nk; it++) {
        {
            float av[8] = {pa0.x, pa0.y, pa0.z, pa0.w, pa1.x, pa1.y, pa1.z, pa1.w};
            float bv[8] = {pb0.x, pb0.y, pb0.z, pb0.w, pb1.x, pb1.y, pb1.z, pb1.w};
            #pragma unroll
            for (int j = 0; j < 4; j++) {
                float e = av[2 * j], o = av[2 * j + 1];
                float he = h16(e), ho = h16(o);
                smu[j * 264 + sbase]        = packh2(he, ho);
                smu[1056 + j * 264 + sbase] = packh2(e - he, o - ho);
                float eb = bv[2 * j], ob = bv[2 * j + 1];
                float hb = h16(eb), hob = h16(ob);
                smu[2112 + j * 264 + sbase] = packh2(hb, hob);
                smu[3168 + j * 264 + sbase] = packh2(eb - hb, ob - hob);
            }
        }
        __syncthreads();
        if (it + 1 < nk) {
            int k0 = (it + 1) * 16;
            pa0 = *(const float4*)(Ap + k0);
            pa1 = *(const float4*)(Ap + k0 + 4);
            pb0 = *(const float4*)(Bp + k0);
            pb1 = *(const float4*)(Bp + k0 + 4);
        }
        // fragments + 48 mma
        uint32_t ra[4][4], la[4][4], rb[4][2], lb[4][2];
        #pragma unroll
        for (int mi = 0; mi < 4; mi++) {
            int m = wm + 16 * mi;
            uint2 h0 = *(const uint2*)&smu[lc * 264 + (m + lr) * 2];
            uint2 h1 = *(const uint2*)&smu[lc * 264 + (m + 8 + lr) * 2];
            uint2 l0 = *(const uint2*)&smu[1056 + lc * 264 + (m + lr) * 2];
            uint2 l1 = *(const uint2*)&smu[1056 + lc * 264 + (m + 8 + lr) * 2];
            ra[mi][0] = h0.x; ra[mi][1] = h1.x; ra[mi][2] = h0.y; ra[mi][3] = h1.y;
            la[mi][0] = l0.x; la[mi][1] = l1.x; la[mi][2] = l0.y; la[mi][3] = l1.y;
        }
        #pragma unroll
        for (int nj = 0; nj < 4; nj++) {
            int n = wn + 8 * nj;
            uint2 hb2 = *(const uint2*)&smu[2112 + lc * 264 + (n + lr) * 2];
            uint2 lb2 = *(const uint2*)&smu[3168 + lc * 264 + (n + lr) * 2];
            rb[nj][0] = hb2.x; rb[nj][1] = hb2.y;
            lb[nj][0] = lb2.x; lb[nj][1] = lb2.y;
        }
        #pragma unroll
        for (int mi = 0; mi < 4; mi++)
            #pragma unroll
            for (int nj = 0; nj < 4; nj++) {
                mma16(acc[mi][nj], ra[mi], rb[nj]);
                mma16(acc[mi][nj], la[mi], rb[nj]);
                mma16(acc[mi][nj], ra[mi], lb[nj]);
            }
        __syncthreads();
    }

    #pragma unroll
    for (int mi = 0; mi < 4; mi++)
        #pragma unroll
        for (int nj = 0; nj < 4; nj++) {
            int row = m0 + wm + mi * 16 + lr;
            int col = n0 + wn + nj * 8 + 2 * lc;
            float bb0 = bias ? bias[col]     : 0.f;
            float bb1 = bias ? bias[col + 1] : 0.f;
            *(float2*)(Cm + (size_t)row * N + col) =
                make_float2(acc[mi][nj][0] + bb0, acc[mi][nj][1] + bb1);
            *(float2*)(Cm + (size_t)(row + 8) * N + col) =
                make_float2(acc[mi][nj][2] + bb0, acc[mi][nj][3] + bb1);
        }
}

// ---------------------------------------------------------------------------
// Flash attention, fp16 m16n8k16 tensor cores (same 10-bit mantissa as tf32).
// 128 threads (4 warps), q-tile 64, each warp owns 16 q-rows.
// smem u32: Kq [0,2176): [(ks*4+lc)*136 + s*2 + comp], comp=(k2&7)>>2, stride
//   136 (8 mod 32 -> conflict-free uint2). Vq [2176,4352): same, k-dim = s-pairs.
// Pq [4352,7424): per-warp 768 u32, [c2*24 + row] (24: 8 mod 32, conflict-free).
// Q staged fp32 at [0,4352) (freed before main loop). Block-causal via K-loop
// bound only; reversed qt order shrinks the wave tail.
// ---------------------------------------------------------------------------
__global__ void __launch_bounds__(128) attn_f16(
    const float* __restrict__ qkv, float* __restrict__ out)
{
    __shared__ uint32_t smu[7424];
    float* sf = (float*)smu;

    int tid  = threadIdx.x;
    int lane = tid & 31, warp = tid >> 5;
    int lr = lane >> 2, lc = lane & 3;
    int qt = (gridDim.x - 1) - blockIdx.x;
    int bh = blockIdx.y;
    int b = bh / H_, h = bh % H_;
    int r0 = qt * 64;
    int q0w = warp * 16;
    const float* base = qkv + (size_t)b * T_ * QKV3 + h * D_;

    // stage Q fp32 (scaled), then extract fp16 A-fragments
    {
        int rr = tid >> 1, cb = (tid & 1) * 32;
        const float* qp = base + (size_t)(r0 + rr) * QKV3 + cb;
        #pragma unroll
        for (int j = 0; j < 8; j++) {
            float4 q4 = *(const float4*)(qp + 4 * j);
            q4.x *= 0.125f; q4.y *= 0.125f; q4.z *= 0.125f; q4.w *= 0.125f;
            *(float4*)&sf[rr * 68 + cb + 4 * j] = q4;
        }
    }
    __syncthreads();
    uint32_t qf[4][4];
    #pragma unroll
    for (int ks = 0; ks < 4; ks++) {
        float2 e0 = *(const float2*)&sf[(q0w + lr) * 68 + 16 * ks + 2 * lc];
        float2 e1 = *(const float2*)&sf[(q0w + 8 + lr) * 68 + 16 * ks + 2 * lc];
        float2 e2 = *(const float2*)&sf[(q0w + lr) * 68 + 16 * ks + 8 + 2 * lc];
        float2 e3 = *(const float2*)&sf[(q0w + 8 + lr) * 68 + 16 * ks + 8 + 2 * lc];
        qf[ks][0] = packh2(e0.x, e0.y);
        qf[ks][1] = packh2(e1.x, e1.y);
        qf[ks][2] = packh2(e2.x, e2.y);
        qf[ks][3] = packh2(e3.x, e3.y);
    }

    float o[8][4];
    #pragma unroll
    for (int nj = 0; nj < 8; nj++)
        #pragma unroll
        for (int r = 0; r < 4; r++) o[nj][r] = 0.f;
    float m0r = -INFINITY, m1r = -INFINITY, l0 = 0.f, l1 = 0.f;
    int Pbase = 4352 + warp * 768;

    int nkt = ((qt >> 2) + 1) << 2;  // (frame+1)*4 key tiles of 64

    for (int kt = 0; kt < nkt; kt++) {
        __syncthreads();
        // --- K fill (pack pairs along d)
        {
            int ss = tid >> 1, db = (tid & 1) * 32;
            const float* kp = base + 768 + (size_t)(kt * 64 + ss) * QKV3 + db;
            #pragma unroll
            for (int j = 0; j < 8; j++) {
                float4 k4 = *(const float4*)(kp + 4 * j);
                int k2 = (db + 4 * j) >> 1;
                int i0 = ((k2 >> 3) * 4 + (k2 & 3)) * 136 + ss * 2 + ((k2 & 7) >> 2);
                int k2b = k2 + 1;
                int i1 = ((k2b >> 3) * 4 + (k2b & 3)) * 136 + ss * 2 + ((k2b & 7) >> 2);
                smu[i0] = packh2(k4.x, k4.y);
                smu[i1] = packh2(k4.z, k4.w);
            }
        }
        // --- V fill (pack pairs along s)
        {
            int rp = tid >> 2, cb2 = (tid & 3) * 16;
            const float* vp0 = base + 1536 + (size_t)(kt * 64 + 2 * rp) * QKV3 + cb2;
            const float* vp1 = vp0 + QKV3;
            int slotc = 2176 + ((rp >> 3) * 4 + (rp & 3)) * 136 + ((rp & 7) >> 2);
            #pragma unroll
            for (int j = 0; j < 4; j++) {
                float4 v0 = *(const float4*)(vp0 + 4 * j);
                float4 v1 = *(const float4*)(vp1 + 4 * j);
                float a0[4] = {v0.x, v0.y, v0.z, v0.w};
                float a1[4] = {v1.x, v1.y, v1.z, v1.w};
                #pragma unroll
                for (int i = 0; i < 4; i++)
                    smu[slotc + (cb2 + 4 * j + i) * 2] = packh2(a0[i], a1[i]);
            }
        }
        __syncthreads();

        // --- S = Q K^T (warp: 16x64), 32 mma
        float s[8][4];
        #pragma unroll
        for (int nj = 0; nj < 8; nj++)
            #pragma unroll
            for (int r = 0; r < 4; r++) s[nj][r] = 0.f;
        #pragma unroll
        for (int ks = 0; ks < 4; ks++)
            #pragma unroll
            for (int nj = 0; nj < 8; nj++) {
                uint2 kb = *(const uint2*)&smu[(ks * 4 + lc) * 136 + (8 * nj + lr) * 2];
                uint32_t bb[2] = {kb.x, kb.y};
                mma16(s[nj], qf[ks], bb);
            }

        // --- online softmax
        float mx0 = -INFINITY, mx1 = -INFINITY;
        #pragma unroll
        for (int nj = 0; nj < 8; nj++) {
            mx0 = fmaxf(mx0, fmaxf(s[nj][0], s[nj][1]));
            mx1 = fmaxf(mx1, fmaxf(s[nj][2], s[nj][3]));
        }
        mx0 = fmaxf(mx0, __shfl_xor_sync(0xffffffffu, mx0, 1));
        mx0 = fmaxf(mx0, __shfl_xor_sync(0xffffffffu, mx0, 2));
        mx1 = fmaxf(mx1, __shfl_xor_sync(0xffffffffu, mx1, 1));
        mx1 = fmaxf(mx1, __shfl_xor_sync(0xffffffffu, mx1, 2));
        float nm0 = fmaxf(m0r, mx0), nm1 = fmaxf(m1r, mx1);
        float al0 = __expf(m0r - nm0), al1 = __expf(m1r - nm1);
        m0r = nm0; m1r = nm1;
        float sum0 = 0.f, sum1 = 0.f;
        #pragma unroll
        for (int nj = 0; nj < 8; nj++) {
            float p0 = __expf(s[nj][0] - nm0);
            float p1 = __expf(s[nj][1] - nm0);
            float p2 = __expf(s[nj][2] - nm1);
            float p3 = __expf(s[nj][3] - nm1);
            sum0 += p0 + p1; sum1 += p2 + p3;
            int c2 = nj * 4 + lc;
            smu[Pbase + c2 * 24 + lr]     = packh2(p0, p1);
            smu[Pbase + c2 * 24 + 8 + lr] = packh2(p2, p3);
        }
        sum0 += __shfl_xor_sync(0xffffffffu, sum0, 1);
        sum0 += __shfl_xor_sync(0xffffffffu, sum0, 2);
        sum1 += __shfl_xor_sync(0xffffffffu, sum1, 1);
        sum1 += __shfl_xor_sync(0xffffffffu, sum1, 2);
        l0 = l0 * al0 + sum0;
        l1 = l1 * al1 + sum1;
        #pragma unroll
        for (int nj = 0; nj < 8; nj++) {
            o[nj][0] *= al0; o[nj][1] *= al0;
            o[nj][2] *= al1; o[nj][3] *= al1;
        }
        __syncwarp();

        // --- O += P V (warp: 16x64), 32 mma
        #pragma unroll
        for (int ks = 0; ks < 4; ks++) {
            uint32_t pa[4];
            pa[0] = smu[Pbase + (8 * ks + lc) * 24 + lr];
            pa[1] = smu[Pbase + (8 * ks + lc) * 24 + 8 + lr];
            pa[2] = smu[Pbase + (8 * ks + 4 + lc) * 24 + lr];
            pa[3] = smu[Pbase + (8 * ks + 4 + lc) * 24 + 8 + lr];
            #pragma unroll
            for (int nj = 0; nj < 8; nj++) {
                uint2 vb = *(const uint2*)&smu[2176 + (ks * 4 + lc) * 136 + (8 * nj + lr) * 2];
                uint32_t bb[2] = {vb.x, vb.y};
                mma16(o[nj], pa, bb);
            }
        }
    }

    // --- normalize + write [B,T,H*D] fp32
    float inv0 = 1.0f / l0, inv1 = 1.0f / l1;
    int row = r0 + q0w + lr;
    size_t off = ((size_t)(b * T_ + row)) * C_ + h * D_;
    #pragma unroll
    for (int nj = 0; nj < 8; nj++) {
        int d = nj * 8 + 2 * lc;
        *(float2*)(out + off + d) =
            make_float2(o[nj][0] * inv0, o[nj][1] * inv0);
        *(float2*)(out + off + 8 * C_ + d) =
            make_float2(o[nj][2] * inv1, o[nj][3] * inv1);
    }
}

// ---------------------------------------------------------------------------
extern "C" void kernel_launch(void* const* d_in, const int* in_sizes, int n_in,
                              void* d_out, int out_size)
{
    const float* x     = (const float*)d_in[0];
    const float* gamma = (const float*)d_in[1];
    const float* beta  = (const float*)d_in[2];
    const float* w_qkv = (const float*)d_in[3];
    const float* w_out = (const float*)d_in[4];
    const float* b_out = (const float*)d_in[5];
    float* out = (float*)d_out;

    float *xn, *qkv, *attn;
    cudaGetSymbolAddress((void**)&xn,   g_xn);
    cudaGetSymbolAddress((void**)&qkv,  g_qkv);
    cudaGetSymbolAddress((void**)&attn, g_attn);

    // 1) LayerNorm
    ln_kernel<<<NTOK, 256>>>(x, gamma, beta, xn);

    // 2) QKV projection (fp16 split x3, ~fp32 accurate)
    gemm_f16x3<<<dim3(QKV3 / 128, NTOK / 128), 256>>>(
        xn, w_qkv, nullptr, qkv, NTOK, QKV3, C_);

    // 3) Flash attention (fp16 tensor cores, block-causal by frame)
    attn_f16<<<dim3(T_ / 64, B_ * H_), 128>>>(qkv, attn);

    // 4) Output projection + bias (fp16 split x3)
    gemm_f16x3<<<dim3(C_ / 128, NTOK / 128), 256>>>(
        attn, w_out, b_out, out, NTOK, C_, C_);
}

// round 5
// speedup vs baseline: 2.6002x; 1.2442x over previous
#include <cuda_runtime.h>
#include <cuda_fp16.h>
#include <math.h>
#include <stdint.h>

#define B_    2
#define T_    4096
#define C_    768
#define H_    12
#define D_    64
#define QKV3  2304
#define NTOK  (B_ * T_)

// Scratch (allocation-free: __device__ globals)
__device__ float g_xn[(size_t)NTOK * C_];
__device__ float g_qkv[(size_t)NTOK * QKV3];
__device__ float g_attn[(size_t)NTOK * C_];

// pack two floats -> f16x2 (first arg in low 16 bits)
__device__ __forceinline__ uint32_t packh2(float lo, float hi) {
    uint32_t r;
    asm("cvt.rn.f16x2.f32 %0, %1, %2;" : "=r"(r) : "f"(hi), "f"(lo));
    return r;
}
__device__ __forceinline__ float h16(float v) {
    return __half2float(__float2half_rn(v));
}
__device__ __forceinline__ float ex2(float x) {
    float y;
    asm("ex2.approx.f32 %0, %1;" : "=f"(y) : "f"(x));
    return y;
}
__device__ __forceinline__ void mma16(float* d, const uint32_t* a, const uint32_t* b) {
    asm volatile(
        "mma.sync.aligned.m16n8k16.row.col.f32.f16.f16.f32 "
        "{%0,%1,%2,%3}, {%4,%5,%6,%7}, {%8,%9}, {%0,%1,%2,%3};\n"
        : "+f"(d[0]), "+f"(d[1]), "+f"(d[2]), "+f"(d[3])
        : "r"(a[0]), "r"(a[1]), "r"(a[2]), "r"(a[3]), "r"(b[0]), "r"(b[1]));
}

// ---------------------------------------------------------------------------
// LayerNorm, warp-per-row (shuffle-only reduction). 256 thr = 8 rows/block.
// ---------------------------------------------------------------------------
__global__ void __launch_bounds__(256) ln_kernel(
    const float* __restrict__ x, const float* __restrict__ gamma,
    const float* __restrict__ beta, float* __restrict__ out)
{
    int row  = blockIdx.x * 8 + (threadIdx.x >> 5);
    int lane = threadIdx.x & 31;
    const float* xr = x + (size_t)row * C_;
    float4 v[6];
    float s = 0.f, ss = 0.f;
    #pragma unroll
    for (int j = 0; j < 6; j++) {
        v[j] = *(const float4*)(xr + j * 128 + lane * 4);
        s  += v[j].x + v[j].y + v[j].z + v[j].w;
        ss += v[j].x * v[j].x + v[j].y * v[j].y + v[j].z * v[j].z + v[j].w * v[j].w;
    }
    #pragma unroll
    for (int o = 16; o > 0; o >>= 1) {
        s  += __shfl_xor_sync(0xffffffffu, s,  o);
        ss += __shfl_xor_sync(0xffffffffu, ss, o);
    }
    float mean = s * (1.0f / C_);
    float var  = ss * (1.0f / C_) - mean * mean;
    float rstd = rsqrtf(var + 1e-5f);
    float* orow = out + (size_t)row * C_;
    #pragma unroll
    for (int j = 0; j < 6; j++) {
        int c = j * 128 + lane * 4;
        float4 g = *(const float4*)(gamma + c);
        float4 bt = *(const float4*)(beta + c);
        float4 r;
        r.x = (v[j].x - mean) * rstd * g.x + bt.x;
        r.y = (v[j].y - mean) * rstd * g.y + bt.y;
        r.z = (v[j].z - mean) * rstd * g.z + bt.z;
        r.w = (v[j].w - mean) * rstd * g.w + bt.w;
        *(float4*)(orow + c) = r;
    }
}

// ---------------------------------------------------------------------------
// GEMM NT, fp16 split x3 (hh+lh+hl ~ fp32 accurate), double-buffered BK=16.
// Block 128x128, 256 threads (8 warps 2x4), warp 64x32, k16 mma.
// Per-stage smem u32 (4224): Aqh@0 Aql@1056 Bqh@2112 Bql@3168, kslot stride 264.
// ---------------------------------------------------------------------------
__global__ void __launch_bounds__(256) gemm_f16x3(
    const float* __restrict__ A, const float* __restrict__ Bm,
    const float* __restrict__ bias, float* __restrict__ Cm,
    int M, int N, int K)
{
    __shared__ uint32_t smu[8448];
    int tid  = threadIdx.x;
    int lane = tid & 31, warp = tid >> 5;
    int lr = lane >> 2, lc = lane & 3;
    int wm = (warp & 1) * 64, wn = (warp >> 1) * 32;
    int m0 = blockIdx.y * 128, n0 = blockIdx.x * 128;
    int lrow = tid >> 1, comp = tid & 1;
    int lk = comp * 8;
    int sbase = lrow * 2 + comp;
    const float* Ap = A  + (size_t)(m0 + lrow) * K + lk;
    const float* Bp = Bm + (size_t)(n0 + lrow) * K + lk;

    float acc[4][4][4];
    #pragma unroll
    for (int i = 0; i < 4; i++)
        #pragma unroll
        for (int j = 0; j < 4; j++)
            #pragma unroll
            for (int r = 0; r < 4; r++) acc[i][j][r] = 0.f;

    float4 pa0, pa1, pb0, pb1;

    #define STS16(W) do { \
        float av[8] = {pa0.x, pa0.y, pa0.z, pa0.w, pa1.x, pa1.y, pa1.z, pa1.w}; \
        float bv[8] = {pb0.x, pb0.y, pb0.z, pb0.w, pb1.x, pb1.y, pb1.z, pb1.w}; \
        _Pragma("unroll") \
        for (int j = 0; j < 4; j++) { \
            float e = av[2 * j], o = av[2 * j + 1]; \
            float he = h16(e), ho = h16(o); \
            (W)[j * 264 + sbase]        = packh2(he, ho); \
            (W)[1056 + j * 264 + sbase] = packh2(e - he, o - ho); \
            float eb = bv[2 * j], ob = bv[2 * j + 1]; \
            float hb = h16(eb), hob = h16(ob); \
            (W)[2112 + j * 264 + sbase] = packh2(hb, hob); \
            (W)[3168 + j * 264 + sbase] = packh2(eb - hb, ob - hob); \
        } \
    } while (0)

    pa0 = *(const float4*)Ap;       pa1 = *(const float4*)(Ap + 4);
    pb0 = *(const float4*)Bp;       pb1 = *(const float4*)(Bp + 4);
    STS16(smu);
    __syncthreads();

    int nk = K / 16;
    for (int it = 0; it < nk; it++) {
        if (it + 1 < nk) {
            int k0 = (it + 1) * 16;
            pa0 = *(const float4*)(Ap + k0);
            pa1 = *(const float4*)(Ap + k0 + 4);
            pb0 = *(const float4*)(Bp + k0);
            pb1 = *(const float4*)(Bp + k0 + 4);
        }
        const uint32_t* S = smu + (it & 1) * 4224;
        uint32_t ra[4][4], la[4][4], rb[4][2], lb[4][2];
        #pragma unroll
        for (int mi = 0; mi < 4; mi++) {
            int m = wm + 16 * mi;
            uint2 h0 = *(const uint2*)&S[lc * 264 + (m + lr) * 2];
            uint2 h1 = *(const uint2*)&S[lc * 264 + (m + 8 + lr) * 2];
            uint2 l0 = *(const uint2*)&S[1056 + lc * 264 + (m + lr) * 2];
            uint2 l1 = *(const uint2*)&S[1056 + lc * 264 + (m + 8 + lr) * 2];
            ra[mi][0] = h0.x; ra[mi][1] = h1.x; ra[mi][2] = h0.y; ra[mi][3] = h1.y;
            la[mi][0] = l0.x; la[mi][1] = l1.x; la[mi][2] = l0.y; la[mi][3] = l1.y;
        }
        #pragma unroll
        for (int nj = 0; nj < 4; nj++) {
            int n = wn + 8 * nj;
            uint2 hb2 = *(const uint2*)&S[2112 + lc * 264 + (n + lr) * 2];
            uint2 lb2 = *(const uint2*)&S[3168 + lc * 264 + (n + lr) * 2];
            rb[nj][0] = hb2.x; rb[nj][1] = hb2.y;
            lb[nj][0] = lb2.x; lb[nj][1] = lb2.y;
        }
        #pragma unroll
        for (int mi = 0; mi < 4; mi++)
            #pragma unroll
            for (int nj = 0; nj < 4; nj++) {
                mma16(acc[mi][nj], ra[mi], rb[nj]);
                mma16(acc[mi][nj], la[mi], rb[nj]);
                mma16(acc[mi][nj], ra[mi], lb[nj]);
            }
        if (it + 1 < nk) {
            uint32_t* W = smu + ((it + 1) & 1) * 4224;
            STS16(W);
        }
        __syncthreads();
    }

    #pragma unroll
    for (int mi = 0; mi < 4; mi++)
        #pragma unroll
        for (int nj = 0; nj < 4; nj++) {
            int row = m0 + wm + mi * 16 + lr;
            int col = n0 + wn + nj * 8 + 2 * lc;
            float bb0 = bias ? bias[col]     : 0.f;
            float bb1 = bias ? bias[col + 1] : 0.f;
            *(float2*)(Cm + (size_t)row * N + col) =
                make_float2(acc[mi][nj][0] + bb0, acc[mi][nj][1] + bb1);
            *(float2*)(Cm + (size_t)(row + 8) * N + col) =
                make_float2(acc[mi][nj][2] + bb0, acc[mi][nj][3] + bb1);
        }
}

// ---------------------------------------------------------------------------
// Flash attention, fp16 m16n8k16. 256 threads (8 warps), q-tile 128; warp owns
// 16 q-rows. Same smem index formulas as the validated 128-thread version:
//   Kq [0,2176):   [((k2>>3)*4+(k2&3))*136 + s*2 + ((k2&7)>>2)]
//   Vq [2176,4352): same with k-dim = s-pairs
//   Pq [4352,10496): per-warp 768 u32, [c2*24 + row]
// Softmax in exp2 domain (log2e folded into Q scale). Block-causal via K-loop
// bound; reversed qt order shrinks the tail.
// ---------------------------------------------------------------------------
__global__ void __launch_bounds__(256) attn_f16(
    const float* __restrict__ qkv, float* __restrict__ out)
{
    __shared__ uint32_t smu[10496];

    int tid  = threadIdx.x;
    int lane = tid & 31, warp = tid >> 5;
    int lr = lane >> 2, lc = lane & 3;
    int qt = (gridDim.x - 1) - blockIdx.x;
    int bh = blockIdx.y;
    int b = bh / H_, h = bh % H_;
    int r0 = qt * 128;
    int q0w = warp * 16;
    const float* base = qkv + (size_t)b * T_ * QKV3 + h * D_;

    // Q fragments straight from global (L2-resident), scale*log2e folded
    const float QSC = 0.125f * 1.4426950408889634f;
    uint32_t qf[4][4];
    {
        const float* q0 = base + (size_t)(r0 + q0w + lr) * QKV3;
        const float* q1 = q0 + 8 * QKV3;
        #pragma unroll
        for (int ks = 0; ks < 4; ks++) {
            float2 e0 = *(const float2*)(q0 + 16 * ks + 2 * lc);
            float2 e1 = *(const float2*)(q1 + 16 * ks + 2 * lc);
            float2 e2 = *(const float2*)(q0 + 16 * ks + 8 + 2 * lc);
            float2 e3 = *(const float2*)(q1 + 16 * ks + 8 + 2 * lc);
            qf[ks][0] = packh2(e0.x * QSC, e0.y * QSC);
            qf[ks][1] = packh2(e1.x * QSC, e1.y * QSC);
            qf[ks][2] = packh2(e2.x * QSC, e2.y * QSC);
            qf[ks][3] = packh2(e3.x * QSC, e3.y * QSC);
        }
    }

    float o[8][4];
    #pragma unroll
    for (int nj = 0; nj < 8; nj++)
        #pragma unroll
        for (int r = 0; r < 4; r++) o[nj][r] = 0.f;
    float m0r = -INFINITY, m1r = -INFINITY, l0 = 0.f, l1 = 0.f;
    int Pbase = 4352 + warp * 768;

    int nkt = ((qt >> 1) + 1) << 2;   // (frame+1)*4 key tiles of 64

    for (int kt = 0; kt < nkt; kt++) {
        __syncthreads();
        // --- K fill: 4 LDG.128 + 8 STS per thread
        {
            int ss = tid >> 2;
            int db = (tid & 3) * 16;
            const float* kp = base + 768 + (size_t)(kt * 64 + ss) * QKV3 + db;
            #pragma unroll
            for (int j = 0; j < 4; j++) {
                float4 k4 = *(const float4*)(kp + 4 * j);
                int k2 = (db >> 1) + 2 * j;
                int i0 = ((k2 >> 3) * 4 + (k2 & 3)) * 136 + ss * 2 + ((k2 & 7) >> 2);
                int k2b = k2 + 1;
                int i1 = ((k2b >> 3) * 4 + (k2b & 3)) * 136 + ss * 2 + ((k2b & 7) >> 2);
                smu[i0] = packh2(k4.x, k4.y);
                smu[i1] = packh2(k4.z, k4.w);
            }
        }
        // --- V fill: 4 LDG.128 + 8 STS per thread (pairs along s)
        {
            int rp = tid >> 3, cb = (tid & 7) * 8;
            const float* vp0 = base + 1536 + (size_t)(kt * 64 + 2 * rp) * QKV3 + cb;
            const float* vp1 = vp0 + QKV3;
            int slotc = 2176 + ((rp >> 3) * 4 + (rp & 3)) * 136 + ((rp & 7) >> 2);
            #pragma unroll
            for (int j = 0; j < 2; j++) {
                float4 v0 = *(const float4*)(vp0 + 4 * j);
                float4 v1 = *(const float4*)(vp1 + 4 * j);
                float a0[4] = {v0.x, v0.y, v0.z, v0.w};
                float a1[4] = {v1.x, v1.y, v1.z, v1.w};
                #pragma unroll
                for (int i = 0; i < 4; i++)
                    smu[slotc + (cb + 4 * j + i) * 2] = packh2(a0[i], a1[i]);
            }
        }
        __syncthreads();

        // --- S = Q K^T (warp: 16x64), 32 mma (S in log2 domain)
        float s[8][4];
        #pragma unroll
        for (int nj = 0; nj < 8; nj++)
            #pragma unroll
            for (int r = 0; r < 4; r++) s[nj][r] = 0.f;
        #pragma unroll
        for (int ks = 0; ks < 4; ks++)
            #pragma unroll
            for (int nj = 0; nj < 8; nj++) {
                uint2 kb = *(const uint2*)&smu[(ks * 4 + lc) * 136 + (8 * nj + lr) * 2];
                uint32_t bb[2] = {kb.x, kb.y};
                mma16(s[nj], qf[ks], bb);
            }

        // --- online softmax (exp2 domain)
        float mx0 = -INFINITY, mx1 = -INFINITY;
        #pragma unroll
        for (int nj = 0; nj < 8; nj++) {
            mx0 = fmaxf(mx0, fmaxf(s[nj][0], s[nj][1]));
            mx1 = fmaxf(mx1, fmaxf(s[nj][2], s[nj][3]));
        }
        mx0 = fmaxf(mx0, __shfl_xor_sync(0xffffffffu, mx0, 1));
        mx0 = fmaxf(mx0, __shfl_xor_sync(0xffffffffu, mx0, 2));
        mx1 = fmaxf(mx1, __shfl_xor_sync(0xffffffffu, mx1, 1));
        mx1 = fmaxf(mx1, __shfl_xor_sync(0xffffffffu, mx1, 2));
        float nm0 = fmaxf(m0r, mx0), nm1 = fmaxf(m1r, mx1);
        float al0 = ex2(m0r - nm0), al1 = ex2(m1r - nm1);
        m0r = nm0; m1r = nm1;
        float sum0 = 0.f, sum1 = 0.f;
        #pragma unroll
        for (int nj = 0; nj < 8; nj++) {
            float p0 = ex2(s[nj][0] - nm0);
            float p1 = ex2(s[nj][1] - nm0);
            float p2 = ex2(s[nj][2] - nm1);
            float p3 = ex2(s[nj][3] - nm1);
            sum0 += p0 + p1; sum1 += p2 + p3;
            int c2 = nj * 4 + lc;
            smu[Pbase + c2 * 24 + lr]     = packh2(p0, p1);
            smu[Pbase + c2 * 24 + 8 + lr] = packh2(p2, p3);
        }
        sum0 += __shfl_xor_sync(0xffffffffu, sum0, 1);
        sum0 += __shfl_xor_sync(0xffffffffu, sum0, 2);
        sum1 += __shfl_xor_sync(0xffffffffu, sum1, 1);
        sum1 += __shfl_xor_sync(0xffffffffu, sum1, 2);
        l0 = l0 * al0 + sum0;
        l1 = l1 * al1 + sum1;
        #pragma unroll
        for (int nj = 0; nj < 8; nj++) {
            o[nj][0] *= al0; o[nj][1] *= al0;
            o[nj][2] *= al1; o[nj][3] *= al1;
        }
        __syncwarp();

        // --- O += P V (warp: 16x64), 32 mma
        #pragma unroll
        for (int ks = 0; ks < 4; ks++) {
            uint32_t pa[4];
            pa[0] = smu[Pbase + (8 * ks + lc) * 24 + lr];
            pa[1] = smu[Pbase + (8 * ks + lc) * 24 + 8 + lr];
            pa[2] = smu[Pbase + (8 * ks + 4 + lc) * 24 + lr];
            pa[3] = smu[Pbase + (8 * ks + 4 + lc) * 24 + 8 + lr];
            #pragma unroll
            for (int nj = 0; nj < 8; nj++) {
                uint2 vb = *(const uint2*)&smu[2176 + (ks * 4 + lc) * 136 + (8 * nj + lr) * 2];
                uint32_t bb[2] = {vb.x, vb.y};
                mma16(o[nj], pa, bb);
            }
        }
    }

    // --- normalize + write [B,T,H*D] fp32
    float inv0 = 1.0f / l0, inv1 = 1.0f / l1;
    int row = r0 + q0w + lr;
    size_t off = ((size_t)(b * T_ + row)) * C_ + h * D_;
    #pragma unroll
    for (int nj = 0; nj < 8; nj++) {
        int d = nj * 8 + 2 * lc;
        *(float2*)(out + off + d) =
            make_float2(o[nj][0] * inv0, o[nj][1] * inv0);
        *(float2*)(out + off + 8 * C_ + d) =
            make_float2(o[nj][2] * inv1, o[nj][3] * inv1);
    }
}

// ---------------------------------------------------------------------------
extern "C" void kernel_launch(void* const* d_in, const int* in_sizes, int n_in,
                              void* d_out, int out_size)
{
    const float* x     = (const float*)d_in[0];
    const float* gamma = (const float*)d_in[1];
    const float* beta  = (const float*)d_in[2];
    const float* w_qkv = (const float*)d_in[3];
    const float* w_out = (const float*)d_in[4];
    const float* b_out = (const float*)d_in[5];
    float* out = (float*)d_out;

    float *xn, *qkv, *attn;
    cudaGetSymbolAddress((void**)&xn,   g_xn);
    cudaGetSymbolAddress((void**)&qkv,  g_qkv);
    cudaGetSymbolAddress((void**)&attn, g_attn);

    // 1) LayerNorm (warp per row)
    ln_kernel<<<NTOK / 8, 256>>>(x, gamma, beta, xn);

    // 2) QKV projection (fp16 split x3, ~fp32 accurate)
    gemm_f16x3<<<dim3(QKV3 / 128, NTOK / 128), 256>>>(
        xn, w_qkv, nullptr, qkv, NTOK, QKV3, C_);

    // 3) Flash attention (fp16 tensor cores, block-causal by frame)
    attn_f16<<<dim3(T_ / 128, B_ * H_), 256>>>(qkv, attn);

    // 4) Output projection + bias (fp16 split x3)
    gemm_f16x3<<<dim3(C_ / 128, NTOK / 128), 256>>>(
        attn, w_out, b_out, out, NTOK, C_, C_);
}

// round 6
// speedup vs baseline: 2.6991x; 1.0380x over previous
#include <cuda_runtime.h>
#include <cuda_fp16.h>
#include <math.h>
#include <stdint.h>

#define B_    2
#define T_    4096
#define C_    768
#define H_    12
#define D_    64
#define QKV3  2304
#define NTOK  (B_ * T_)
#define C2    384      // C_/2  (u32-packed pairs)
#define QKV32 1152     // QKV3/2

// Packed fp16x2 scratch (allocation-free __device__ globals)
__device__ uint32_t g_xh[(size_t)NTOK * C2];
__device__ uint32_t g_xl[(size_t)NTOK * C2];
__device__ uint32_t g_qh[(size_t)NTOK * QKV32];   // qkv, fp16 hi only
__device__ uint32_t g_ah[(size_t)NTOK * C2];
__device__ uint32_t g_al[(size_t)NTOK * C2];
__device__ uint32_t g_wqh[(size_t)QKV3 * C2];
__device__ uint32_t g_wql[(size_t)QKV3 * C2];
__device__ uint32_t g_woh[(size_t)C_ * C2];
__device__ uint32_t g_wol[(size_t)C_ * C2];

__device__ __forceinline__ uint32_t packh2(float lo, float hi) {
    uint32_t r;
    asm("cvt.rn.f16x2.f32 %0, %1, %2;" : "=r"(r) : "f"(hi), "f"(lo));
    return r;
}
__device__ __forceinline__ float h16(float v) {
    return __half2float(__float2half_rn(v));
}
__device__ __forceinline__ float ex2(float x) {
    float y;
    asm("ex2.approx.f32 %0, %1;" : "=f"(y) : "f"(x));
    return y;
}
__device__ __forceinline__ uint32_t prmt(uint32_t a, uint32_t b, uint32_t sel) {
    uint32_t r;
    asm("prmt.b32 %0, %1, %2, %3;" : "=r"(r) : "r"(a), "r"(b), "r"(sel));
    return r;
}
__device__ __forceinline__ void mma16(float* d, const uint32_t* a, const uint32_t* b) {
    asm volatile(
        "mma.sync.aligned.m16n8k16.row.col.f32.f16.f16.f32 "
        "{%0,%1,%2,%3}, {%4,%5,%6,%7}, {%8,%9}, {%0,%1,%2,%3};\n"
        : "+f"(d[0]), "+f"(d[1]), "+f"(d[2]), "+f"(d[3])
        : "r"(a[0]), "r"(a[1]), "r"(a[2]), "r"(a[3]), "r"(b[0]), "r"(b[1]));
}

// ---------------------------------------------------------------------------
// Weight split: fp32 [O][768] -> packed (hi, lo) fp16x2 u32 [O][384]
// ---------------------------------------------------------------------------
__global__ void wsplit_kernel(const float* __restrict__ w,
                              uint32_t* __restrict__ wh, uint32_t* __restrict__ wl,
                              int n2)
{
    int i = blockIdx.x * 256 + threadIdx.x;
    if (i < n2) {
        float2 v = *(const float2*)(w + 2 * i);
        float hx = h16(v.x), hy = h16(v.y);
        wh[i] = packh2(v.x, v.y);
        wl[i] = packh2(v.x - hx, v.y - hy);
    }
}

// ---------------------------------------------------------------------------
// LayerNorm, warp-per-row -> packed (hi, lo) output
// ---------------------------------------------------------------------------
__global__ void __launch_bounds__(256) ln_kernel(
    const float* __restrict__ x, const float* __restrict__ gamma,
    const float* __restrict__ beta,
    uint32_t* __restrict__ oh, uint32_t* __restrict__ ol)
{
    int row  = blockIdx.x * 8 + (threadIdx.x >> 5);
    int lane = threadIdx.x & 31;
    const float* xr = x + (size_t)row * C_;
    float4 v[6];
    float s = 0.f, ss = 0.f;
    #pragma unroll
    for (int j = 0; j < 6; j++) {
        v[j] = *(const float4*)(xr + j * 128 + lane * 4);
        s  += v[j].x + v[j].y + v[j].z + v[j].w;
        ss += v[j].x * v[j].x + v[j].y * v[j].y + v[j].z * v[j].z + v[j].w * v[j].w;
    }
    #pragma unroll
    for (int o = 16; o > 0; o >>= 1) {
        s  += __shfl_xor_sync(0xffffffffu, s,  o);
        ss += __shfl_xor_sync(0xffffffffu, ss, o);
    }
    float mean = s * (1.0f / C_);
    float var  = ss * (1.0f / C_) - mean * mean;
    float rstd = rsqrtf(var + 1e-5f);
    uint32_t* ohr = oh + (size_t)row * C2;
    uint32_t* olr = ol + (size_t)row * C2;
    #pragma unroll
    for (int j = 0; j < 6; j++) {
        int c = j * 128 + lane * 4;
        float4 g = *(const float4*)(gamma + c);
        float4 bt = *(const float4*)(beta + c);
        float rx = (v[j].x - mean) * rstd * g.x + bt.x;
        float ry = (v[j].y - mean) * rstd * g.y + bt.y;
        float rz = (v[j].z - mean) * rstd * g.z + bt.z;
        float rw = (v[j].w - mean) * rstd * g.w + bt.w;
        int c2 = j * 64 + lane * 2;
        ohr[c2]     = packh2(rx, ry);
        ohr[c2 + 1] = packh2(rz, rw);
        olr[c2]     = packh2(rx - h16(rx), ry - h16(ry));
        olr[c2 + 1] = packh2(rz - h16(rz), rw - h16(rw));
    }
}

// ---------------------------------------------------------------------------
// GEMM NT on pre-packed fp16x2 (hi,lo) operands, x3 mma (~fp32 accurate).
// Block 128x128, stage = 8 k2 (16 k), double-buffered, 256 thr, 8 warps 2x4.
// Stage smem u32 (4224): Ah@0 Al@1056 Bh@2112 Bl@3168, kslot stride 264.
// PACKED_OUT: write fp16x2-hi u32 (no bias) else fp32 + bias.
// ---------------------------------------------------------------------------
template <bool PACKED_OUT>
__global__ void __launch_bounds__(256) gemm_p(
    const uint32_t* __restrict__ Ah, const uint32_t* __restrict__ Al,
    const uint32_t* __restrict__ Bh, const uint32_t* __restrict__ Bl,
    const float* __restrict__ bias, float* __restrict__ Cf,
    uint32_t* __restrict__ Cp, int M, int N, int K2)
{
    __shared__ uint32_t smu[8448];
    int tid  = threadIdx.x;
    int lane = tid & 31, warp = tid >> 5;
    int lr = lane >> 2, lc = lane & 3;
    int wm = (warp & 1) * 64, wn = (warp >> 1) * 32;
    int m0 = blockIdx.y * 128, n0 = blockIdx.x * 128;
    int lrow = tid >> 1, comp = tid & 1;
    int sbase = lrow * 2 + comp;
    const uint32_t* ApH = Ah + (size_t)(m0 + lrow) * K2 + comp * 4;
    const uint32_t* ApL = Al + (size_t)(m0 + lrow) * K2 + comp * 4;
    const uint32_t* BpH = Bh + (size_t)(n0 + lrow) * K2 + comp * 4;
    const uint32_t* BpL = Bl + (size_t)(n0 + lrow) * K2 + comp * 4;

    float acc[4][4][4];
    #pragma unroll
    for (int i = 0; i < 4; i++)
        #pragma unroll
        for (int j = 0; j < 4; j++)
            #pragma unroll
            for (int r = 0; r < 4; r++) acc[i][j][r] = 0.f;

    uint4 vah, val, vbh, vbl;
    #define LDGP(k2o) do { \
        vah = *(const uint4*)(ApH + (k2o)); val = *(const uint4*)(ApL + (k2o)); \
        vbh = *(const uint4*)(BpH + (k2o)); vbl = *(const uint4*)(BpL + (k2o)); \
    } while (0)
    #define STSP(W) do { \
        (W)[0 * 264 + sbase] = vah.x; (W)[1 * 264 + sbase] = vah.y; \
        (W)[2 * 264 + sbase] = vah.z; (W)[3 * 264 + sbase] = vah.w; \
        (W)[1056 + 0 * 264 + sbase] = val.x; (W)[1056 + 1 * 264 + sbase] = val.y; \
        (W)[1056 + 2 * 264 + sbase] = val.z; (W)[1056 + 3 * 264 + sbase] = val.w; \
        (W)[2112 + 0 * 264 + sbase] = vbh.x; (W)[2112 + 1 * 264 + sbase] = vbh.y; \
        (W)[2112 + 2 * 264 + sbase] = vbh.z; (W)[2112 + 3 * 264 + sbase] = vbh.w; \
        (W)[3168 + 0 * 264 + sbase] = vbl.x; (W)[3168 + 1 * 264 + sbase] = vbl.y; \
        (W)[3168 + 2 * 264 + sbase] = vbl.z; (W)[3168 + 3 * 264 + sbase] = vbl.w; \
    } while (0)

    LDGP(0);
    STSP(smu);
    __syncthreads();

    int nk = K2 / 8;
    for (int it = 0; it < nk; it++) {
        if (it + 1 < nk) LDGP((it + 1) * 8);
        const uint32_t* S = smu + (it & 1) * 4224;
        uint32_t ra[4][4], la[4][4], rb[4][2], lb[4][2];
        #pragma unroll
        for (int mi = 0; mi < 4; mi++) {
            int m = wm + 16 * mi;
            uint2 h0 = *(const uint2*)&S[lc * 264 + (m + lr) * 2];
            uint2 h1 = *(const uint2*)&S[lc * 264 + (m + 8 + lr) * 2];
            uint2 l0 = *(const uint2*)&S[1056 + lc * 264 + (m + lr) * 2];
            uint2 l1 = *(const uint2*)&S[1056 + lc * 264 + (m + 8 + lr) * 2];
            ra[mi][0] = h0.x; ra[mi][1] = h1.x; ra[mi][2] = h0.y; ra[mi][3] = h1.y;
            la[mi][0] = l0.x; la[mi][1] = l1.x; la[mi][2] = l0.y; la[mi][3] = l1.y;
        }
        #pragma unroll
        for (int nj = 0; nj < 4; nj++) {
            int n = wn + 8 * nj;
            uint2 hb2 = *(const uint2*)&S[2112 + lc * 264 + (n + lr) * 2];
            uint2 lb2 = *(const uint2*)&S[3168 + lc * 264 + (n + lr) * 2];
            rb[nj][0] = hb2.x; rb[nj][1] = hb2.y;
            lb[nj][0] = lb2.x; lb[nj][1] = lb2.y;
        }
        #pragma unroll
        for (int mi = 0; mi < 4; mi++)
            #pragma unroll
            for (int nj = 0; nj < 4; nj++) {
                mma16(acc[mi][nj], ra[mi], rb[nj]);
                mma16(acc[mi][nj], la[mi], rb[nj]);
                mma16(acc[mi][nj], ra[mi], lb[nj]);
            }
        if (it + 1 < nk) {
            uint32_t* W = smu + ((it + 1) & 1) * 4224;
            STSP(W);
        }
        __syncthreads();
    }

    if (PACKED_OUT) {
        int N2 = N >> 1;
        #pragma unroll
        for (int mi = 0; mi < 4; mi++)
            #pragma unroll
            for (int nj = 0; nj < 4; nj++) {
                int row = m0 + wm + mi * 16 + lr;
                int col2 = ((n0 + wn) >> 1) + 4 * nj + lc;
                Cp[(size_t)row * N2 + col2] = packh2(acc[mi][nj][0], acc[mi][nj][1]);
                Cp[(size_t)(row + 8) * N2 + col2] = packh2(acc[mi][nj][2], acc[mi][nj][3]);
            }
    } else {
        #pragma unroll
        for (int mi = 0; mi < 4; mi++)
            #pragma unroll
            for (int nj = 0; nj < 4; nj++) {
                int row = m0 + wm + mi * 16 + lr;
                int col = n0 + wn + nj * 8 + 2 * lc;
                float bb0 = bias[col], bb1 = bias[col + 1];
                *(float2*)(Cf + (size_t)row * N + col) =
                    make_float2(acc[mi][nj][0] + bb0, acc[mi][nj][1] + bb1);
                *(float2*)(Cf + (size_t)(row + 8) * N + col) =
                    make_float2(acc[mi][nj][2] + bb0, acc[mi][nj][3] + bb1);
            }
    }
}

// ---------------------------------------------------------------------------
// Flash attention on packed fp16 qkv. 256 threads (8 warps), q-tile 128.
// smem u32:  Kq [0,2176):   [((k2>>3)*4+(k2&3))*136 + s*2 + ((k2&7)>>2)]
//            Vq [2176,4352): same, k-dim = s-pairs
//            Pq [4352,10496): per-warp 768 u32, [c2*24 + row]
// qkv packed row layout (u32): q@[h*32+d2], k@[384+..], v@[768+..], stride 1152.
// Softmax scale applied post-mma in fp32 (exp2 domain). Block-causal via
// K-loop bound; reversed qt order shrinks the tail.
// Output: packed (hi,lo) fp16x2 for the out-projection.
// ---------------------------------------------------------------------------
__global__ void __launch_bounds__(256) attn_p(
    const uint32_t* __restrict__ qh,
    uint32_t* __restrict__ oh, uint32_t* __restrict__ ol)
{
    __shared__ uint32_t smu[10496];

    int tid  = threadIdx.x;
    int lane = tid & 31, warp = tid >> 5;
    int lr = lane >> 2, lc = lane & 3;
    int qt = (gridDim.x - 1) - blockIdx.x;
    int bh = blockIdx.y;
    int b = bh / H_, h = bh % H_;
    int r0 = qt * 128;
    int q0w = warp * 16;
    const uint32_t* base = qh + (size_t)b * T_ * QKV32 + h * 32;
    const float QSC = 0.125f * 1.4426950408889634f;

    // Q fragments: direct u32 loads (d-pair packed)
    uint32_t qf[4][4];
    {
        const uint32_t* q0 = base + (size_t)(r0 + q0w + lr) * QKV32;
        const uint32_t* q1 = q0 + 8 * QKV32;
        #pragma unroll
        for (int ks = 0; ks < 4; ks++) {
            qf[ks][0] = q0[8 * ks + lc];
            qf[ks][1] = q1[8 * ks + lc];
            qf[ks][2] = q0[8 * ks + 4 + lc];
            qf[ks][3] = q1[8 * ks + 4 + lc];
        }
    }

    float o[8][4];
    #pragma unroll
    for (int nj = 0; nj < 8; nj++)
        #pragma unroll
        for (int r = 0; r < 4; r++) o[nj][r] = 0.f;
    float m0r = -INFINITY, m1r = -INFINITY, l0 = 0.f, l1 = 0.f;
    int Pbase = 4352 + warp * 768;

    int nkt = ((qt >> 1) + 1) << 2;   // (frame+1)*4 key tiles of 64

    for (int kt = 0; kt < nkt; kt++) {
        __syncthreads();
        // --- K fill: pure u32 copies (2 LDG.128 + 8 STS)
        {
            int ss = tid >> 2;
            int d2b = (tid & 3) * 8;
            const uint32_t* kp = base + 384 + (size_t)(kt * 64 + ss) * QKV32 + d2b;
            uint4 k0 = *(const uint4*)kp;
            uint4 k1 = *(const uint4*)(kp + 4);
            uint32_t kv[8] = {k0.x, k0.y, k0.z, k0.w, k1.x, k1.y, k1.z, k1.w};
            #pragma unroll
            for (int j = 0; j < 8; j++) {
                int k2 = d2b + j;
                smu[((k2 >> 3) * 4 + (k2 & 3)) * 136 + ss * 2 + ((k2 & 7) >> 2)] = kv[j];
            }
        }
        // --- V fill: PRMT pair-transpose (2 LDG.128 + 8 PRMT + 8 STS)
        {
            int rp = tid >> 3;           // s-pair 0..31
            int cb2 = (tid & 7) * 4;     // d2 offset, 4 u32
            const uint32_t* vp0 = base + 768 + (size_t)(kt * 64 + 2 * rp) * QKV32 + cb2;
            uint4 v0 = *(const uint4*)vp0;
            uint4 v1 = *(const uint4*)(vp0 + QKV32);
            int slotc = 2176 + ((rp >> 3) * 4 + (rp & 3)) * 136 + ((rp & 7) >> 2);
            uint32_t a0[4] = {v0.x, v0.y, v0.z, v0.w};
            uint32_t a1[4] = {v1.x, v1.y, v1.z, v1.w};
            #pragma unroll
            for (int i = 0; i < 4; i++) {
                int d0 = 2 * (cb2 + i);
                smu[slotc + d0 * 2]       = prmt(a0[i], a1[i], 0x5410u);
                smu[slotc + (d0 + 1) * 2] = prmt(a0[i], a1[i], 0x7632u);
            }
        }
        __syncthreads();

        // --- S = Q K^T (warp: 16x64), 32 mma
        float s[8][4];
        #pragma unroll
        for (int nj = 0; nj < 8; nj++)
            #pragma unroll
            for (int r = 0; r < 4; r++) s[nj][r] = 0.f;
        #pragma unroll
        for (int ks = 0; ks < 4; ks++)
            #pragma unroll
            for (int nj = 0; nj < 8; nj++) {
                uint2 kb = *(const uint2*)&smu[(ks * 4 + lc) * 136 + (8 * nj + lr) * 2];
                uint32_t bb[2] = {kb.x, kb.y};
                mma16(s[nj], qf[ks], bb);
            }
        #pragma unroll
        for (int nj = 0; nj < 8; nj++) {
            s[nj][0] *= QSC; s[nj][1] *= QSC; s[nj][2] *= QSC; s[nj][3] *= QSC;
        }

        // --- online softmax (exp2 domain)
        float mx0 = -INFINITY, mx1 = -INFINITY;
        #pragma unroll
        for (int nj = 0; nj < 8; nj++) {
            mx0 = fmaxf(mx0, fmaxf(s[nj][0], s[nj][1]));
            mx1 = fmaxf(mx1, fmaxf(s[nj][2], s[nj][3]));
        }
        mx0 = fmaxf(mx0, __shfl_xor_sync(0xffffffffu, mx0, 1));
        mx0 = fmaxf(mx0, __shfl_xor_sync(0xffffffffu, mx0, 2));
        mx1 = fmaxf(mx1, __shfl_xor_sync(0xffffffffu, mx1, 1));
        mx1 = fmaxf(mx1, __shfl_xor_sync(0xffffffffu, mx1, 2));
        float nm0 = fmaxf(m0r, mx0), nm1 = fmaxf(m1r, mx1);
        float al0 = ex2(m0r - nm0), al1 = ex2(m1r - nm1);
        m0r = nm0; m1r = nm1;
        float sum0 = 0.f, sum1 = 0.f;
        #pragma unroll
        for (int nj = 0; nj < 8; nj++) {
            float p0 = ex2(s[nj][0] - nm0);
            float p1 = ex2(s[nj][1] - nm0);
            float p2 = ex2(s[nj][2] - nm1);
            float p3 = ex2(s[nj][3] - nm1);
            sum0 += p0 + p1; sum1 += p2 + p3;
            int c2 = nj * 4 + lc;
            smu[Pbase + c2 * 24 + lr]     = packh2(p0, p1);
            smu[Pbase + c2 * 24 + 8 + lr] = packh2(p2, p3);
        }
        sum0 += __shfl_xor_sync(0xffffffffu, sum0, 1);
        sum0 += __shfl_xor_sync(0xffffffffu, sum0, 2);
        sum1 += __shfl_xor_sync(0xffffffffu, sum1, 1);
        sum1 += __shfl_xor_sync(0xffffffffu, sum1, 2);
        l0 = l0 * al0 + sum0;
        l1 = l1 * al1 + sum1;
        #pragma unroll
        for (int nj = 0; nj < 8; nj++) {
            o[nj][0] *= al0; o[nj][1] *= al0;
            o[nj][2] *= al1; o[nj][3] *= al1;
        }
        __syncwarp();

        // --- O += P V (warp: 16x64), 32 mma
        #pragma unroll
        for (int ks = 0; ks < 4; ks++) {
            uint32_t pa[4];
            pa[0] = smu[Pbase + (8 * ks + lc) * 24 + lr];
            pa[1] = smu[Pbase + (8 * ks + lc) * 24 + 8 + lr];
            pa[2] = smu[Pbase + (8 * ks + 4 + lc) * 24 + lr];
            pa[3] = smu[Pbase + (8 * ks + 4 + lc) * 24 + 8 + lr];
            #pragma unroll
            for (int nj = 0; nj < 8; nj++) {
                uint2 vb = *(const uint2*)&smu[2176 + (ks * 4 + lc) * 136 + (8 * nj + lr) * 2];
                uint32_t bb[2] = {vb.x, vb.y};
                mma16(o[nj], pa, bb);
            }
        }
    }

    // --- normalize + write packed (hi, lo)
    float inv0 = 1.0f / l0, inv1 = 1.0f / l1;
    int row = r0 + q0w + lr;
    size_t off0 = ((size_t)(b * T_ + row)) * C2 + h * 32;
    size_t off1 = off0 + 8 * C2;
    #pragma unroll
    for (int nj = 0; nj < 8; nj++) {
        int d2 = 4 * nj + lc;
        float v00 = o[nj][0] * inv0, v01 = o[nj][1] * inv0;
        float v10 = o[nj][2] * inv1, v11 = o[nj][3] * inv1;
        oh[off0 + d2] = packh2(v00, v01);
        ol[off0 + d2] = packh2(v00 - h16(v00), v01 - h16(v01));
        oh[off1 + d2] = packh2(v10, v11);
        ol[off1 + d2] = packh2(v10 - h16(v10), v11 - h16(v11));
    }
}

// ---------------------------------------------------------------------------
extern "C" void kernel_launch(void* const* d_in, const int* in_sizes, int n_in,
                              void* d_out, int out_size)
{
    const float* x     = (const float*)d_in[0];
    const float* gamma = (const float*)d_in[1];
    const float* beta  = (const float*)d_in[2];
    const float* w_qkv = (const float*)d_in[3];
    const float* w_out = (const float*)d_in[4];
    const float* b_out = (const float*)d_in[5];
    float* out = (float*)d_out;

    uint32_t *xh, *xl, *qh, *ah, *al, *wqh, *wql, *woh, *wol;
    cudaGetSymbolAddress((void**)&xh,  g_xh);
    cudaGetSymbolAddress((void**)&xl,  g_xl);
    cudaGetSymbolAddress((void**)&qh,  g_qh);
    cudaGetSymbolAddress((void**)&ah,  g_ah);
    cudaGetSymbolAddress((void**)&al,  g_al);
    cudaGetSymbolAddress((void**)&wqh, g_wqh);
    cudaGetSymbolAddress((void**)&wql, g_wql);
    cudaGetSymbolAddress((void**)&woh, g_woh);
    cudaGetSymbolAddress((void**)&wol, g_wol);

    // 0) weight pre-split (packed fp16x2 hi/lo)
    wsplit_kernel<<<(QKV3 * C2 + 255) / 256, 256>>>(w_qkv, wqh, wql, QKV3 * C2);
    wsplit_kernel<<<(C_ * C2 + 255) / 256, 256>>>(w_out, woh, wol, C_ * C2);

    // 1) LayerNorm -> packed (hi, lo)
    ln_kernel<<<NTOK / 8, 256>>>(x, gamma, beta, xh, xl);

    // 2) QKV projection -> packed fp16 (hi only)
    gemm_p<true><<<dim3(QKV3 / 128, NTOK / 128), 256>>>(
        xh, xl, wqh, wql, nullptr, nullptr, qh, NTOK, QKV3, C2);

    // 3) Flash attention -> packed (hi, lo)
    attn_p<<<dim3(T_ / 128, B_ * H_), 256>>>(qh, ah, al);

    // 4) Output projection + bias -> fp32
    gemm_p<false><<<dim3(C_ / 128, NTOK / 128), 256>>>(
        ah, al, woh, wol, b_out, out, nullptr, NTOK, C_, C2);
}

// round 7
// speedup vs baseline: 2.9141x; 1.0797x over previous
#include <cuda_runtime.h>
#include <cuda_fp16.h>
#include <math.h>
#include <stdint.h>

#define B_    2
#define T_    4096
#define C_    768
#define H_    12
#define D_    64
#define QKV3  2304
#define NTOK  (B_ * T_)
#define C2    384      // C_/2  (u32-packed pairs)
#define QKV32 1152     // QKV3/2

// Packed fp16x2 scratch (allocation-free __device__ globals)
__device__ uint32_t g_xh[(size_t)NTOK * C2];
__device__ uint32_t g_xl[(size_t)NTOK * C2];
__device__ uint32_t g_qh[(size_t)NTOK * QKV32];   // qkv, fp16 hi only
__device__ uint32_t g_ah[(size_t)NTOK * C2];
__device__ uint32_t g_al[(size_t)NTOK * C2];
__device__ uint32_t g_wqh[(size_t)QKV3 * C2];
__device__ uint32_t g_wql[(size_t)QKV3 * C2];
__device__ uint32_t g_woh[(size_t)C_ * C2];
__device__ uint32_t g_wol[(size_t)C_ * C2];

__device__ __forceinline__ uint32_t packh2(float lo, float hi) {
    uint32_t r;
    asm("cvt.rn.f16x2.f32 %0, %1, %2;" : "=r"(r) : "f"(hi), "f"(lo));
    return r;
}
__device__ __forceinline__ float h16(float v) {
    return __half2float(__float2half_rn(v));
}
__device__ __forceinline__ float ex2(float x) {
    float y;
    asm("ex2.approx.f32 %0, %1;" : "=f"(y) : "f"(x));
    return y;
}
__device__ __forceinline__ uint32_t prmt(uint32_t a, uint32_t b, uint32_t sel) {
    uint32_t r;
    asm("prmt.b32 %0, %1, %2, %3;" : "=r"(r) : "r"(a), "r"(b), "r"(sel));
    return r;
}
__device__ __forceinline__ void mma16(float* d, const uint32_t* a, const uint32_t* b) {
    asm volatile(
        "mma.sync.aligned.m16n8k16.row.col.f32.f16.f16.f32 "
        "{%0,%1,%2,%3}, {%4,%5,%6,%7}, {%8,%9}, {%0,%1,%2,%3};\n"
        : "+f"(d[0]), "+f"(d[1]), "+f"(d[2]), "+f"(d[3])
        : "r"(a[0]), "r"(a[1]), "r"(a[2]), "r"(a[3]), "r"(b[0]), "r"(b[1]));
}

// ---------------------------------------------------------------------------
// Weight split: fp32 [O][768] -> packed (hi, lo) fp16x2 u32 [O][384]
// ---------------------------------------------------------------------------
__global__ void wsplit_kernel(const float* __restrict__ w,
                              uint32_t* __restrict__ wh, uint32_t* __restrict__ wl,
                              int n2)
{
    int i = blockIdx.x * 256 + threadIdx.x;
    if (i < n2) {
        float2 v = *(const float2*)(w + 2 * i);
        float hx = h16(v.x), hy = h16(v.y);
        wh[i] = packh2(v.x, v.y);
        wl[i] = packh2(v.x - hx, v.y - hy);
    }
}

// ---------------------------------------------------------------------------
// LayerNorm, warp-per-row -> packed (hi, lo) output
// ---------------------------------------------------------------------------
__global__ void __launch_bounds__(256) ln_kernel(
    const float* __restrict__ x, const float* __restrict__ gamma,
    const float* __restrict__ beta,
    uint32_t* __restrict__ oh, uint32_t* __restrict__ ol)
{
    int row  = blockIdx.x * 8 + (threadIdx.x >> 5);
    int lane = threadIdx.x & 31;
    const float* xr = x + (size_t)row * C_;
    float4 v[6];
    float s = 0.f, ss = 0.f;
    #pragma unroll
    for (int j = 0; j < 6; j++) {
        v[j] = *(const float4*)(xr + j * 128 + lane * 4);
        s  += v[j].x + v[j].y + v[j].z + v[j].w;
        ss += v[j].x * v[j].x + v[j].y * v[j].y + v[j].z * v[j].z + v[j].w * v[j].w;
    }
    #pragma unroll
    for (int o = 16; o > 0; o >>= 1) {
        s  += __shfl_xor_sync(0xffffffffu, s,  o);
        ss += __shfl_xor_sync(0xffffffffu, ss, o);
    }
    float mean = s * (1.0f / C_);
    float var  = ss * (1.0f / C_) - mean * mean;
    float rstd = rsqrtf(var + 1e-5f);
    uint32_t* ohr = oh + (size_t)row * C2;
    uint32_t* olr = ol + (size_t)row * C2;
    #pragma unroll
    for (int j = 0; j < 6; j++) {
        int c = j * 128 + lane * 4;
        float4 g = *(const float4*)(gamma + c);
        float4 bt = *(const float4*)(beta + c);
        float rx = (v[j].x - mean) * rstd * g.x + bt.x;
        float ry = (v[j].y - mean) * rstd * g.y + bt.y;
        float rz = (v[j].z - mean) * rstd * g.z + bt.z;
        float rw = (v[j].w - mean) * rstd * g.w + bt.w;
        int c2 = j * 64 + lane * 2;
        ohr[c2]     = packh2(rx, ry);
        ohr[c2 + 1] = packh2(rz, rw);
        olr[c2]     = packh2(rx - h16(rx), ry - h16(ry));
        olr[c2 + 1] = packh2(rz - h16(rz), rw - h16(rw));
    }
}

// ---------------------------------------------------------------------------
// GEMM NT on pre-packed fp16x2 (hi,lo) operands, x3 mma (~fp32 accurate).
// Block 128x128, stage = 8 k2 (16 k), double-buffered, 256 thr, 8 warps 2x4.
// Stage smem u32 (4224): Ah@0 Al@1056 Bh@2112 Bl@3168, kslot stride 264.
// __launch_bounds__(256,2): 2 blocks/SM is load-bearing (R6 lost it at 138 regs).
// ---------------------------------------------------------------------------
template <bool PACKED_OUT>
__global__ void __launch_bounds__(256, 2) gemm_p(
    const uint32_t* __restrict__ Ah, const uint32_t* __restrict__ Al,
    const uint32_t* __restrict__ Bh, const uint32_t* __restrict__ Bl,
    const float* __restrict__ bias, float* __restrict__ Cf,
    uint32_t* __restrict__ Cp, int M, int N, int K2)
{
    __shared__ uint32_t smu[8448];
    int tid  = threadIdx.x;
    int lane = tid & 31, warp = tid >> 5;
    int lr = lane >> 2, lc = lane & 3;
    int wm = (warp & 1) * 64, wn = (warp >> 1) * 32;
    int m0 = blockIdx.y * 128, n0 = blockIdx.x * 128;
    int lrow = tid >> 1, comp = tid & 1;
    int sbase = lrow * 2 + comp;
    const uint32_t* ApH = Ah + (size_t)(m0 + lrow) * K2 + comp * 4;
    const uint32_t* ApL = Al + (size_t)(m0 + lrow) * K2 + comp * 4;
    const uint32_t* BpH = Bh + (size_t)(n0 + lrow) * K2 + comp * 4;
    const uint32_t* BpL = Bl + (size_t)(n0 + lrow) * K2 + comp * 4;

    float acc[4][4][4];
    #pragma unroll
    for (int i = 0; i < 4; i++)
        #pragma unroll
        for (int j = 0; j < 4; j++)
            #pragma unroll
            for (int r = 0; r < 4; r++) acc[i][j][r] = 0.f;

    uint4 vah, val, vbh, vbl;
    #define LDGP(k2o) do { \
        vah = *(const uint4*)(ApH + (k2o)); val = *(const uint4*)(ApL + (k2o)); \
        vbh = *(const uint4*)(BpH + (k2o)); vbl = *(const uint4*)(BpL + (k2o)); \
    } while (0)
    #define STSP(W) do { \
        (W)[0 * 264 + sbase] = vah.x; (W)[1 * 264 + sbase] = vah.y; \
        (W)[2 * 264 + sbase] = vah.z; (W)[3 * 264 + sbase] = vah.w; \
        (W)[1056 + 0 * 264 + sbase] = val.x; (W)[1056 + 1 * 264 + sbase] = val.y; \
        (W)[1056 + 2 * 264 + sbase] = val.z; (W)[1056 + 3 * 264 + sbase] = val.w; \
        (W)[2112 + 0 * 264 + sbase] = vbh.x; (W)[2112 + 1 * 264 + sbase] = vbh.y; \
        (W)[2112 + 2 * 264 + sbase] = vbh.z; (W)[2112 + 3 * 264 + sbase] = vbh.w; \
        (W)[3168 + 0 * 264 + sbase] = vbl.x; (W)[3168 + 1 * 264 + sbase] = vbl.y; \
        (W)[3168 + 2 * 264 + sbase] = vbl.z; (W)[3168 + 3 * 264 + sbase] = vbl.w; \
    } while (0)

    LDGP(0);
    STSP(smu);
    __syncthreads();

    int nk = K2 / 8;
    for (int it = 0; it < nk; it++) {
        if (it + 1 < nk) LDGP((it + 1) * 8);
        const uint32_t* S = smu + (it & 1) * 4224;
        uint32_t ra[4][4], la[4][4], rb[4][2], lb[4][2];
        #pragma unroll
        for (int mi = 0; mi < 4; mi++) {
            int m = wm + 16 * mi;
            uint2 h0 = *(const uint2*)&S[lc * 264 + (m + lr) * 2];
            uint2 h1 = *(const uint2*)&S[lc * 264 + (m + 8 + lr) * 2];
            uint2 l0 = *(const uint2*)&S[1056 + lc * 264 + (m + lr) * 2];
            uint2 l1 = *(const uint2*)&S[1056 + lc * 264 + (m + 8 + lr) * 2];
            ra[mi][0] = h0.x; ra[mi][1] = h1.x; ra[mi][2] = h0.y; ra[mi][3] = h1.y;
            la[mi][0] = l0.x; la[mi][1] = l1.x; la[mi][2] = l0.y; la[mi][3] = l1.y;
        }
        #pragma unroll
        for (int nj = 0; nj < 4; nj++) {
            int n = wn + 8 * nj;
            uint2 hb2 = *(const uint2*)&S[2112 + lc * 264 + (n + lr) * 2];
            uint2 lb2 = *(const uint2*)&S[3168 + lc * 264 + (n + lr) * 2];
            rb[nj][0] = hb2.x; rb[nj][1] = hb2.y;
            lb[nj][0] = lb2.x; lb[nj][1] = lb2.y;
        }
        #pragma unroll
        for (int mi = 0; mi < 4; mi++)
            #pragma unroll
            for (int nj = 0; nj < 4; nj++) {
                mma16(acc[mi][nj], ra[mi], rb[nj]);
                mma16(acc[mi][nj], la[mi], rb[nj]);
                mma16(acc[mi][nj], ra[mi], lb[nj]);
            }
        if (it + 1 < nk) {
            uint32_t* W = smu + ((it + 1) & 1) * 4224;
            STSP(W);
        }
        __syncthreads();
    }

    if (PACKED_OUT) {
        int N2 = N >> 1;
        #pragma unroll
        for (int mi = 0; mi < 4; mi++)
            #pragma unroll
            for (int nj = 0; nj < 4; nj++) {
                int row = m0 + wm + mi * 16 + lr;
                int col2 = ((n0 + wn) >> 1) + 4 * nj + lc;
                Cp[(size_t)row * N2 + col2] = packh2(acc[mi][nj][0], acc[mi][nj][1]);
                Cp[(size_t)(row + 8) * N2 + col2] = packh2(acc[mi][nj][2], acc[mi][nj][3]);
            }
    } else {
        #pragma unroll
        for (int mi = 0; mi < 4; mi++)
            #pragma unroll
            for (int nj = 0; nj < 4; nj++) {
                int row = m0 + wm + mi * 16 + lr;
                int col = n0 + wn + nj * 8 + 2 * lc;
                float bb0 = bias[col], bb1 = bias[col + 1];
                *(float2*)(Cf + (size_t)row * N + col) =
                    make_float2(acc[mi][nj][0] + bb0, acc[mi][nj][1] + bb1);
                *(float2*)(Cf + (size_t)(row + 8) * N + col) =
                    make_float2(acc[mi][nj][2] + bb0, acc[mi][nj][3] + bb1);
            }
    }
}

// ---------------------------------------------------------------------------
// Flash attention on packed fp16 qkv. 256 threads (8 warps), q-tile 128.
// Double-buffered K/V smem (stage = 4352 u32): per stage
//   Kq [0,2176):    [((k2>>3)*4+(k2&3))*136 + s*2 + ((k2&7)>>2)]
//   Vq [2176,4352): same with k-dim = s-pairs
// P never touches smem: the S-output fragment of m16n8k16 IS the A-fragment
// of the PV mma (cols 16ks+{2lc,2lc+1,8+2lc,8+2lc+1} = nj in {2ks,2ks+1}).
// One __syncthreads per kt. Softmax exp2-domain, scale post-mma.
// ---------------------------------------------------------------------------
__global__ void __launch_bounds__(256, 2) attn_p(
    const uint32_t* __restrict__ qh,
    uint32_t* __restrict__ oh, uint32_t* __restrict__ ol)
{
    __shared__ uint32_t smu[8704];   // 2 stages x 4352

    int tid  = threadIdx.x;
    int lane = tid & 31, warp = tid >> 5;
    int lr = lane >> 2, lc = lane & 3;
    int qt = (gridDim.x - 1) - blockIdx.x;
    int bh = blockIdx.y;
    int b = bh / H_, h = bh % H_;
    int r0 = qt * 128;
    int q0w = warp * 16;
    const uint32_t* base = qh + (size_t)b * T_ * QKV32 + h * 32;
    const float QSC = 0.125f * 1.4426950408889634f;

    // fill indices (fixed per thread)
    int kss = tid >> 2, kd2b = (tid & 3) * 8;
    int kidx[8];
    #pragma unroll
    for (int j = 0; j < 8; j++) {
        int k2 = kd2b + j;
        kidx[j] = ((k2 >> 3) * 4 + (k2 & 3)) * 136 + kss * 2 + ((k2 & 7) >> 2);
    }
    int vrp = tid >> 3, vcb2 = (tid & 7) * 4;
    int vslot = 2176 + ((vrp >> 3) * 4 + (vrp & 3)) * 136 + ((vrp & 7) >> 2);

    // Q fragments: direct u32 loads
    uint32_t qf[4][4];
    {
        const uint32_t* q0 = base + (size_t)(r0 + q0w + lr) * QKV32;
        const uint32_t* q1 = q0 + 8 * QKV32;
        #pragma unroll
        for (int ks = 0; ks < 4; ks++) {
            qf[ks][0] = q0[8 * ks + lc];
            qf[ks][1] = q1[8 * ks + lc];
            qf[ks][2] = q0[8 * ks + 4 + lc];
            qf[ks][3] = q1[8 * ks + 4 + lc];
        }
    }

    float o[8][4];
    #pragma unroll
    for (int nj = 0; nj < 8; nj++)
        #pragma unroll
        for (int r = 0; r < 4; r++) o[nj][r] = 0.f;
    float m0r = -INFINITY, m1r = -INFINITY, l0 = 0.f, l1 = 0.f;

    int nkt = ((qt >> 1) + 1) << 2;   // (frame+1)*4 key tiles of 64

    // prefill stage 0
    {
        const uint32_t* kp = base + 384 + (size_t)kss * QKV32 + kd2b;
        uint4 k0 = *(const uint4*)kp;
        uint4 k1 = *(const uint4*)(kp + 4);
        uint32_t kv[8] = {k0.x, k0.y, k0.z, k0.w, k1.x, k1.y, k1.z, k1.w};
        #pragma unroll
        for (int j = 0; j < 8; j++) smu[kidx[j]] = kv[j];
        const uint32_t* vp = base + 768 + (size_t)(2 * vrp) * QKV32 + vcb2;
        uint4 v0 = *(const uint4*)vp;
        uint4 v1 = *(const uint4*)(vp + QKV32);
        uint32_t a0[4] = {v0.x, v0.y, v0.z, v0.w};
        uint32_t a1[4] = {v1.x, v1.y, v1.z, v1.w};
        #pragma unroll
        for (int i = 0; i < 4; i++) {
            int d0 = 2 * (vcb2 + i);
            smu[vslot + d0 * 2]       = prmt(a0[i], a1[i], 0x5410u);
            smu[vslot + (d0 + 1) * 2] = prmt(a0[i], a1[i], 0x7632u);
        }
    }
    __syncthreads();

    for (int kt = 0; kt < nkt; kt++) {
        const uint32_t* cur = smu + (kt & 1) * 4352;
        uint32_t* nxt = smu + ((kt + 1) & 1) * 4352;
        bool more = (kt + 1 < nkt);

        // issue next-stage LDGs early (latency hidden under mma)
        uint4 nk0, nk1, nv0, nv1;
        if (more) {
            const uint32_t* kp = base + 384 + (size_t)((kt + 1) * 64 + kss) * QKV32 + kd2b;
            nk0 = *(const uint4*)kp;
            nk1 = *(const uint4*)(kp + 4);
            const uint32_t* vp = base + 768 + (size_t)((kt + 1) * 64 + 2 * vrp) * QKV32 + vcb2;
            nv0 = *(const uint4*)vp;
            nv1 = *(const uint4*)(vp + QKV32);
        }

        // --- S = Q K^T (warp: 16x64), 32 mma
        float s[8][4];
        #pragma unroll
        for (int nj = 0; nj < 8; nj++)
            #pragma unroll
            for (int r = 0; r < 4; r++) s[nj][r] = 0.f;
        #pragma unroll
        for (int ks = 0; ks < 4; ks++)
            #pragma unroll
            for (int nj = 0; nj < 8; nj++) {
                uint2 kb = *(const uint2*)&cur[(ks * 4 + lc) * 136 + (8 * nj + lr) * 2];
                uint32_t bb[2] = {kb.x, kb.y};
                mma16(s[nj], qf[ks], bb);
            }

        // --- online softmax (exp2 domain); P packed straight into A-fragments
        float mx0 = -INFINITY, mx1 = -INFINITY;
        #pragma unroll
        for (int nj = 0; nj < 8; nj++) {
            s[nj][0] *= QSC; s[nj][1] *= QSC; s[nj][2] *= QSC; s[nj][3] *= QSC;
            mx0 = fmaxf(mx0, fmaxf(s[nj][0], s[nj][1]));
            mx1 = fmaxf(mx1, fmaxf(s[nj][2], s[nj][3]));
        }
        mx0 = fmaxf(mx0, __shfl_xor_sync(0xffffffffu, mx0, 1));
        mx0 = fmaxf(mx0, __shfl_xor_sync(0xffffffffu, mx0, 2));
        mx1 = fmaxf(mx1, __shfl_xor_sync(0xffffffffu, mx1, 1));
        mx1 = fmaxf(mx1, __shfl_xor_sync(0xffffffffu, mx1, 2));
        float nm0 = fmaxf(m0r, mx0), nm1 = fmaxf(m1r, mx1);
        float al0 = ex2(m0r - nm0), al1 = ex2(m1r - nm1);
        m0r = nm0; m1r = nm1;
        float sum0 = 0.f, sum1 = 0.f;
        uint32_t pa[4][4];
        #pragma unroll
        for (int ks = 0; ks < 4; ks++) {
            #pragma unroll
            for (int half = 0; half < 2; half++) {
                int nj = 2 * ks + half;
                float p0 = ex2(s[nj][0] - nm0);
                float p1 = ex2(s[nj][1] - nm0);
                float p2 = ex2(s[nj][2] - nm1);
                float p3 = ex2(s[nj][3] - nm1);
                sum0 += p0 + p1; sum1 += p2 + p3;
                pa[ks][2 * half]     = packh2(p0, p1);
                pa[ks][2 * half + 1] = packh2(p2, p3);
            }
        }
        sum0 += __shfl_xor_sync(0xffffffffu, sum0, 1);
        sum0 += __shfl_xor_sync(0xffffffffu, sum0, 2);
        sum1 += __shfl_xor_sync(0xffffffffu, sum1, 1);
        sum1 += __shfl_xor_sync(0xffffffffu, sum1, 2);
        l0 = l0 * al0 + sum0;
        l1 = l1 * al1 + sum1;
        #pragma unroll
        for (int nj = 0; nj < 8; nj++) {
            o[nj][0] *= al0; o[nj][1] *= al0;
            o[nj][2] *= al1; o[nj][3] *= al1;
        }

        // --- O += P V (warp: 16x64), 32 mma — P from registers
        #pragma unroll
        for (int ks = 0; ks < 4; ks++)
            #pragma unroll
            for (int nj = 0; nj < 8; nj++) {
                uint2 vb = *(const uint2*)&cur[2176 + (ks * 4 + lc) * 136 + (8 * nj + lr) * 2];
                uint32_t bb[2] = {vb.x, vb.y};
                mma16(o[nj], pa[ks], bb);
            }

        // --- store next stage, single barrier
        if (more) {
            uint32_t kv[8] = {nk0.x, nk0.y, nk0.z, nk0.w, nk1.x, nk1.y, nk1.z, nk1.w};
            #pragma unroll
            for (int j = 0; j < 8; j++) nxt[kidx[j]] = kv[j];
            uint32_t a0[4] = {nv0.x, nv0.y, nv0.z, nv0.w};
            uint32_t a1[4] = {nv1.x, nv1.y, nv1.z, nv1.w};
            #pragma unroll
            for (int i = 0; i < 4; i++) {
                int d0 = 2 * (vcb2 + i);
                nxt[vslot + d0 * 2]       = prmt(a0[i], a1[i], 0x5410u);
                nxt[vslot + (d0 + 1) * 2] = prmt(a0[i], a1[i], 0x7632u);
            }
            __syncthreads();
        }
    }

    // --- normalize + write packed (hi, lo)
    float inv0 = 1.0f / l0, inv1 = 1.0f / l1;
    int row = r0 + q0w + lr;
    size_t off0 = ((size_t)(b * T_ + row)) * C2 + h * 32;
    size_t off1 = off0 + 8 * C2;
    #pragma unroll
    for (int nj = 0; nj < 8; nj++) {
        int d2 = 4 * nj + lc;
        float v00 = o[nj][0] * inv0, v01 = o[nj][1] * inv0;
        float v10 = o[nj][2] * inv1, v11 = o[nj][3] * inv1;
        oh[off0 + d2] = packh2(v00, v01);
        ol[off0 + d2] = packh2(v00 - h16(v00), v01 - h16(v01));
        oh[off1 + d2] = packh2(v10, v11);
        ol[off1 + d2] = packh2(v10 - h16(v10), v11 - h16(v11));
    }
}

// ---------------------------------------------------------------------------
extern "C" void kernel_launch(void* const* d_in, const int* in_sizes, int n_in,
                              void* d_out, int out_size)
{
    const float* x     = (const float*)d_in[0];
    const float* gamma = (const float*)d_in[1];
    const float* beta  = (const float*)d_in[2];
    const float* w_qkv = (const float*)d_in[3];
    const float* w_out = (const float*)d_in[4];
    const float* b_out = (const float*)d_in[5];
    float* out = (float*)d_out;

    uint32_t *xh, *xl, *qh, *ah, *al, *wqh, *wql, *woh, *wol;
    cudaGetSymbolAddress((void**)&xh,  g_xh);
    cudaGetSymbolAddress((void**)&xl,  g_xl);
    cudaGetSymbolAddress((void**)&qh,  g_qh);
    cudaGetSymbolAddress((void**)&ah,  g_ah);
    cudaGetSymbolAddress((void**)&al,  g_al);
    cudaGetSymbolAddress((void**)&wqh, g_wqh);
    cudaGetSymbolAddress((void**)&wql, g_wql);
    cudaGetSymbolAddress((void**)&woh, g_woh);
    cudaGetSymbolAddress((void**)&wol, g_wol);

    // 0) weight pre-split (packed fp16x2 hi/lo)
    wsplit_kernel<<<(QKV3 * C2 + 255) / 256, 256>>>(w_qkv, wqh, wql, QKV3 * C2);
    wsplit_kernel<<<(C_ * C2 + 255) / 256, 256>>>(w_out, woh, wol, C_ * C2);

    // 1) LayerNorm -> packed (hi, lo)
    ln_kernel<<<NTOK / 8, 256>>>(x, gamma, beta, xh, xl);

    // 2) QKV projection -> packed fp16 (hi only)
    gemm_p<true><<<dim3(QKV3 / 128, NTOK / 128), 256>>>(
        xh, xl, wqh, wql, nullptr, nullptr, qh, NTOK, QKV3, C2);

    // 3) Flash attention -> packed (hi, lo)
    attn_p<<<dim3(T_ / 128, B_ * H_), 256>>>(qh, ah, al);

    // 4) Output projection + bias -> fp32
    gemm_p<false><<<dim3(C_ / 128, NTOK / 128), 256>>>(
        ah, al, woh, wol, b_out, out, nullptr, NTOK, C_, C2);
}

// round 8
// speedup vs baseline: 3.2764x; 1.1243x over previous
#include <cuda_runtime.h>
#include <cuda_fp16.h>
#include <math.h>
#include <stdint.h>

#define B_    2
#define T_    4096
#define C_    768
#define H_    12
#define D_    64
#define QKV3  2304
#define NTOK  (B_ * T_)
#define C2    384      // C_/2  (u32-packed pairs)
#define QKV32 1152     // QKV3/2

// Packed fp16x2 scratch (allocation-free __device__ globals)
__device__ uint32_t g_xh[(size_t)NTOK * C2];
__device__ uint32_t g_xl[(size_t)NTOK * C2];
__device__ uint32_t g_qh[(size_t)NTOK * QKV32];   // qkv, fp16 hi only
__device__ uint32_t g_ah[(size_t)NTOK * C2];
__device__ uint32_t g_al[(size_t)NTOK * C2];
__device__ uint32_t g_wqh[(size_t)QKV3 * C2];
__device__ uint32_t g_wql[(size_t)QKV3 * C2];
__device__ uint32_t g_woh[(size_t)C_ * C2];
__device__ uint32_t g_wol[(size_t)C_ * C2];

__device__ __forceinline__ uint32_t packh2(float lo, float hi) {
    uint32_t r;
    asm("cvt.rn.f16x2.f32 %0, %1, %2;" : "=r"(r) : "f"(hi), "f"(lo));
    return r;
}
__device__ __forceinline__ float h16(float v) {
    return __half2float(__float2half_rn(v));
}
__device__ __forceinline__ float ex2(float x) {
    float y;
    asm("ex2.approx.f32 %0, %1;" : "=f"(y) : "f"(x));
    return y;
}
__device__ __forceinline__ uint32_t prmt(uint32_t a, uint32_t b, uint32_t sel) {
    uint32_t r;
    asm("prmt.b32 %0, %1, %2, %3;" : "=r"(r) : "r"(a), "r"(b), "r"(sel));
    return r;
}
__device__ __forceinline__ void mma16(float* d, const uint32_t* a, const uint32_t* b) {
    asm volatile(
        "mma.sync.aligned.m16n8k16.row.col.f32.f16.f16.f32 "
        "{%0,%1,%2,%3}, {%4,%5,%6,%7}, {%8,%9}, {%0,%1,%2,%3};\n"
        : "+f"(d[0]), "+f"(d[1]), "+f"(d[2]), "+f"(d[3])
        : "r"(a[0]), "r"(a[1]), "r"(a[2]), "r"(a[3]), "r"(b[0]), "r"(b[1]));
}

// ---------------------------------------------------------------------------
// Weight split: fp32 [O][768] -> packed (hi, lo) fp16x2 u32 [O][384]
// ---------------------------------------------------------------------------
__global__ void wsplit_kernel(const float* __restrict__ w,
                              uint32_t* __restrict__ wh, uint32_t* __restrict__ wl,
                              int n2)
{
    int i = blockIdx.x * 256 + threadIdx.x;
    if (i < n2) {
        float2 v = *(const float2*)(w + 2 * i);
        float hx = h16(v.x), hy = h16(v.y);
        wh[i] = packh2(v.x, v.y);
        wl[i] = packh2(v.x - hx, v.y - hy);
    }
}

// ---------------------------------------------------------------------------
// LayerNorm, warp-per-row -> packed (hi, lo) output
// ---------------------------------------------------------------------------
__global__ void __launch_bounds__(256) ln_kernel(
    const float* __restrict__ x, const float* __restrict__ gamma,
    const float* __restrict__ beta,
    uint32_t* __restrict__ oh, uint32_t* __restrict__ ol)
{
    int row  = blockIdx.x * 8 + (threadIdx.x >> 5);
    int lane = threadIdx.x & 31;
    const float* xr = x + (size_t)row * C_;
    float4 v[6];
    float s = 0.f, ss = 0.f;
    #pragma unroll
    for (int j = 0; j < 6; j++) {
        v[j] = *(const float4*)(xr + j * 128 + lane * 4);
        s  += v[j].x + v[j].y + v[j].z + v[j].w;
        ss += v[j].x * v[j].x + v[j].y * v[j].y + v[j].z * v[j].z + v[j].w * v[j].w;
    }
    #pragma unroll
    for (int o = 16; o > 0; o >>= 1) {
        s  += __shfl_xor_sync(0xffffffffu, s,  o);
        ss += __shfl_xor_sync(0xffffffffu, ss, o);
    }
    float mean = s * (1.0f / C_);
    float var  = ss * (1.0f / C_) - mean * mean;
    float rstd = rsqrtf(var + 1e-5f);
    uint32_t* ohr = oh + (size_t)row * C2;
    uint32_t* olr = ol + (size_t)row * C2;
    #pragma unroll
    for (int j = 0; j < 6; j++) {
        int c = j * 128 + lane * 4;
        float4 g = *(const float4*)(gamma + c);
        float4 bt = *(const float4*)(beta + c);
        float rx = (v[j].x - mean) * rstd * g.x + bt.x;
        float ry = (v[j].y - mean) * rstd * g.y + bt.y;
        float rz = (v[j].z - mean) * rstd * g.z + bt.z;
        float rw = (v[j].w - mean) * rstd * g.w + bt.w;
        int c2 = j * 64 + lane * 2;
        ohr[c2]     = packh2(rx, ry);
        ohr[c2 + 1] = packh2(rz, rw);
        olr[c2]     = packh2(rx - h16(rx), ry - h16(ry));
        olr[c2 + 1] = packh2(rz - h16(rz), rw - h16(rw));
    }
}

// ---------------------------------------------------------------------------
// GEMM NT on pre-packed fp16x2 operands. X3: hh+lh+hl (~fp32 accurate).
// !X3: hh+lh only (= exact-A x fp16-B; used for QKV whose output is fp16
// anyway — skips Bl traffic and 1/3 of the mma).
// Block 128x128, stage = 8 k2 (16 k), double-buffered, 256 thr, 8 warps 2x4.
// Stage smem u32 (4224): Ah@0 Al@1056 Bh@2112 Bl@3168, kslot stride 264.
// __launch_bounds__(256,2): 2 blocks/SM is load-bearing.
// ---------------------------------------------------------------------------
template <bool PACKED_OUT, bool X3>
__global__ void __launch_bounds__(256, 2) gemm_p(
    const uint32_t* __restrict__ Ah, const uint32_t* __restrict__ Al,
    const uint32_t* __restrict__ Bh, const uint32_t* __restrict__ Bl,
    const float* __restrict__ bias, float* __restrict__ Cf,
    uint32_t* __restrict__ Cp, int M, int N, int K2)
{
    __shared__ uint32_t smu[8448];
    int tid  = threadIdx.x;
    int lane = tid & 31, warp = tid >> 5;
    int lr = lane >> 2, lc = lane & 3;
    int wm = (warp & 1) * 64, wn = (warp >> 1) * 32;
    int m0 = blockIdx.y * 128, n0 = blockIdx.x * 128;
    int lrow = tid >> 1, comp = tid & 1;
    int sbase = lrow * 2 + comp;
    const uint32_t* ApH = Ah + (size_t)(m0 + lrow) * K2 + comp * 4;
    const uint32_t* ApL = Al + (size_t)(m0 + lrow) * K2 + comp * 4;
    const uint32_t* BpH = Bh + (size_t)(n0 + lrow) * K2 + comp * 4;
    const uint32_t* BpL = Bl + (size_t)(n0 + lrow) * K2 + comp * 4;

    float acc[4][4][4];
    #pragma unroll
    for (int i = 0; i < 4; i++)
        #pragma unroll
        for (int j = 0; j < 4; j++)
            #pragma unroll
            for (int r = 0; r < 4; r++) acc[i][j][r] = 0.f;

    uint4 vah, val, vbh, vbl;
    #define LDGP(k2o) do { \
        vah = *(const uint4*)(ApH + (k2o)); val = *(const uint4*)(ApL + (k2o)); \
        vbh = *(const uint4*)(BpH + (k2o)); \
        if (X3) vbl = *(const uint4*)(BpL + (k2o)); \
    } while (0)
    #define STSP(W) do { \
        (W)[0 * 264 + sbase] = vah.x; (W)[1 * 264 + sbase] = vah.y; \
        (W)[2 * 264 + sbase] = vah.z; (W)[3 * 264 + sbase] = vah.w; \
        (W)[1056 + 0 * 264 + sbase] = val.x; (W)[1056 + 1 * 264 + sbase] = val.y; \
        (W)[1056 + 2 * 264 + sbase] = val.z; (W)[1056 + 3 * 264 + sbase] = val.w; \
        (W)[2112 + 0 * 264 + sbase] = vbh.x; (W)[2112 + 1 * 264 + sbase] = vbh.y; \
        (W)[2112 + 2 * 264 + sbase] = vbh.z; (W)[2112 + 3 * 264 + sbase] = vbh.w; \
        if (X3) { \
            (W)[3168 + 0 * 264 + sbase] = vbl.x; (W)[3168 + 1 * 264 + sbase] = vbl.y; \
            (W)[3168 + 2 * 264 + sbase] = vbl.z; (W)[3168 + 3 * 264 + sbase] = vbl.w; \
        } \
    } while (0)

    LDGP(0);
    STSP(smu);
    __syncthreads();

    int nk = K2 / 8;
    for (int it = 0; it < nk; it++) {
        if (it + 1 < nk) LDGP((it + 1) * 8);
        const uint32_t* S = smu + (it & 1) * 4224;
        uint32_t ra[4][4], la[4][4], rb[4][2], lb[4][2];
        #pragma unroll
        for (int mi = 0; mi < 4; mi++) {
            int m = wm + 16 * mi;
            uint2 h0 = *(const uint2*)&S[lc * 264 + (m + lr) * 2];
            uint2 h1 = *(const uint2*)&S[lc * 264 + (m + 8 + lr) * 2];
            uint2 l0 = *(const uint2*)&S[1056 + lc * 264 + (m + lr) * 2];
            uint2 l1 = *(const uint2*)&S[1056 + lc * 264 + (m + 8 + lr) * 2];
            ra[mi][0] = h0.x; ra[mi][1] = h1.x; ra[mi][2] = h0.y; ra[mi][3] = h1.y;
            la[mi][0] = l0.x; la[mi][1] = l1.x; la[mi][2] = l0.y; la[mi][3] = l1.y;
        }
        #pragma unroll
        for (int nj = 0; nj < 4; nj++) {
            int n = wn + 8 * nj;
            uint2 hb2 = *(const uint2*)&S[2112 + lc * 264 + (n + lr) * 2];
            rb[nj][0] = hb2.x; rb[nj][1] = hb2.y;
            if (X3) {
                uint2 lb2 = *(const uint2*)&S[3168 + lc * 264 + (n + lr) * 2];
                lb[nj][0] = lb2.x; lb[nj][1] = lb2.y;
            }
        }
        #pragma unroll
        for (int mi = 0; mi < 4; mi++)
            #pragma unroll
            for (int nj = 0; nj < 4; nj++) {
                mma16(acc[mi][nj], ra[mi], rb[nj]);
                mma16(acc[mi][nj], la[mi], rb[nj]);
                if (X3) mma16(acc[mi][nj], ra[mi], lb[nj]);
            }
        if (it + 1 < nk) {
            uint32_t* W = smu + ((it + 1) & 1) * 4224;
            STSP(W);
        }
        __syncthreads();
    }

    if (PACKED_OUT) {
        int N2 = N >> 1;
        #pragma unroll
        for (int mi = 0; mi < 4; mi++)
            #pragma unroll
            for (int nj = 0; nj < 4; nj++) {
                int row = m0 + wm + mi * 16 + lr;
                int col2 = ((n0 + wn) >> 1) + 4 * nj + lc;
                Cp[(size_t)row * N2 + col2] = packh2(acc[mi][nj][0], acc[mi][nj][1]);
                Cp[(size_t)(row + 8) * N2 + col2] = packh2(acc[mi][nj][2], acc[mi][nj][3]);
            }
    } else {
        #pragma unroll
        for (int mi = 0; mi < 4; mi++)
            #pragma unroll
            for (int nj = 0; nj < 4; nj++) {
                int row = m0 + wm + mi * 16 + lr;
                int col = n0 + wn + nj * 8 + 2 * lc;
                float bb0 = bias[col], bb1 = bias[col + 1];
                *(float2*)(Cf + (size_t)row * N + col) =
                    make_float2(acc[mi][nj][0] + bb0, acc[mi][nj][1] + bb1);
                *(float2*)(Cf + (size_t)(row + 8) * N + col) =
                    make_float2(acc[mi][nj][2] + bb0, acc[mi][nj][3] + bb1);
            }
    }
}

// ---------------------------------------------------------------------------
// Flash attention on packed fp16 qkv. 256 threads (8 warps), q-tile 128.
// Double-buffered K/V smem (stage = 4352 u32): per stage
//   Kq [0,2176):    [((k2>>3)*4+(k2&3))*136 + s*2 + ((k2&7)>>2)]
//   Vq [2176,4352): same with k-dim = s-pairs
// P never touches smem: S-output fragment of m16n8k16 IS the PV A-fragment.
// One __syncthreads per kt. Softmax exp2-domain, scale post-mma.
// ---------------------------------------------------------------------------
__global__ void __launch_bounds__(256, 2) attn_p(
    const uint32_t* __restrict__ qh,
    uint32_t* __restrict__ oh, uint32_t* __restrict__ ol)
{
    __shared__ uint32_t smu[8704];   // 2 stages x 4352

    int tid  = threadIdx.x;
    int lane = tid & 31, warp = tid >> 5;
    int lr = lane >> 2, lc = lane & 3;
    int qt = (gridDim.x - 1) - blockIdx.x;
    int bh = blockIdx.y;
    int b = bh / H_, h = bh % H_;
    int r0 = qt * 128;
    int q0w = warp * 16;
    const uint32_t* base = qh + (size_t)b * T_ * QKV32 + h * 32;
    const float QSC = 0.125f * 1.4426950408889634f;

    // fill indices (fixed per thread)
    int kss = tid >> 2, kd2b = (tid & 3) * 8;
    int kidx[8];
    #pragma unroll
    for (int j = 0; j < 8; j++) {
        int k2 = kd2b + j;
        kidx[j] = ((k2 >> 3) * 4 + (k2 & 3)) * 136 + kss * 2 + ((k2 & 7) >> 2);
    }
    int vrp = tid >> 3, vcb2 = (tid & 7) * 4;
    int vslot = 2176 + ((vrp >> 3) * 4 + (vrp & 3)) * 136 + ((vrp & 7) >> 2);

    // Q fragments: direct u32 loads
    uint32_t qf[4][4];
    {
        const uint32_t* q0 = base + (size_t)(r0 + q0w + lr) * QKV32;
        const uint32_t* q1 = q0 + 8 * QKV32;
        #pragma unroll
        for (int ks = 0; ks < 4; ks++) {
            qf[ks][0] = q0[8 * ks + lc];
            qf[ks][1] = q1[8 * ks + lc];
            qf[ks][2] = q0[8 * ks + 4 + lc];
            qf[ks][3] = q1[8 * ks + 4 + lc];
        }
    }

    float o[8][4];
    #pragma unroll
    for (int nj = 0; nj < 8; nj++)
        #pragma unroll
        for (int r = 0; r < 4; r++) o[nj][r] = 0.f;
    float m0r = -INFINITY, m1r = -INFINITY, l0 = 0.f, l1 = 0.f;

    int nkt = ((qt >> 1) + 1) << 2;   // (frame+1)*4 key tiles of 64

    // prefill stage 0
    {
        const uint32_t* kp = base + 384 + (size_t)kss * QKV32 + kd2b;
        uint4 k0 = *(const uint4*)kp;
        uint4 k1 = *(const uint4*)(kp + 4);
        uint32_t kv[8] = {k0.x, k0.y, k0.z, k0.w, k1.x, k1.y, k1.z, k1.w};
        #pragma unroll
        for (int j = 0; j < 8; j++) smu[kidx[j]] = kv[j];
        const uint32_t* vp = base + 768 + (size_t)(2 * vrp) * QKV32 + vcb2;
        uint4 v0 = *(const uint4*)vp;
        uint4 v1 = *(const uint4*)(vp + QKV32);
        uint32_t a0[4] = {v0.x, v0.y, v0.z, v0.w};
        uint32_t a1[4] = {v1.x, v1.y, v1.z, v1.w};
        #pragma unroll
        for (int i = 0; i < 4; i++) {
            int d0 = 2 * (vcb2 + i);
            smu[vslot + d0 * 2]       = prmt(a0[i], a1[i], 0x5410u);
            smu[vslot + (d0 + 1) * 2] = prmt(a0[i], a1[i], 0x7632u);
        }
    }
    __syncthreads();

    for (int kt = 0; kt < nkt; kt++) {
        const uint32_t* cur = smu + (kt & 1) * 4352;
        uint32_t* nxt = smu + ((kt + 1) & 1) * 4352;
        bool more = (kt + 1 < nkt);

        // issue next-stage LDGs early (latency hidden under mma)
        uint4 nk0, nk1, nv0, nv1;
        if (more) {
            const uint32_t* kp = base + 384 + (size_t)((kt + 1) * 64 + kss) * QKV32 + kd2b;
            nk0 = *(const uint4*)kp;
            nk1 = *(const uint4*)(kp + 4);
            const uint32_t* vp = base + 768 + (size_t)((kt + 1) * 64 + 2 * vrp) * QKV32 + vcb2;
            nv0 = *(const uint4*)vp;
            nv1 = *(const uint4*)(vp + QKV32);
        }

        // --- S = Q K^T (warp: 16x64), 32 mma
        float s[8][4];
        #pragma unroll
        for (int nj = 0; nj < 8; nj++)
            #pragma unroll
            for (int r = 0; r < 4; r++) s[nj][r] = 0.f;
        #pragma unroll
        for (int ks = 0; ks < 4; ks++)
            #pragma unroll
            for (int nj = 0; nj < 8; nj++) {
                uint2 kb = *(const uint2*)&cur[(ks * 4 + lc) * 136 + (8 * nj + lr) * 2];
                uint32_t bb[2] = {kb.x, kb.y};
                mma16(s[nj], qf[ks], bb);
            }

        // --- online softmax (exp2 domain); P packed straight into A-fragments
        float mx0 = -INFINITY, mx1 = -INFINITY;
        #pragma unroll
        for (int nj = 0; nj < 8; nj++) {
            s[nj][0] *= QSC; s[nj][1] *= QSC; s[nj][2] *= QSC; s[nj][3] *= QSC;
            mx0 = fmaxf(mx0, fmaxf(s[nj][0], s[nj][1]));
            mx1 = fmaxf(mx1, fmaxf(s[nj][2], s[nj][3]));
        }
        mx0 = fmaxf(mx0, __shfl_xor_sync(0xffffffffu, mx0, 1));
        mx0 = fmaxf(mx0, __shfl_xor_sync(0xffffffffu, mx0, 2));
        mx1 = fmaxf(mx1, __shfl_xor_sync(0xffffffffu, mx1, 1));
        mx1 = fmaxf(mx1, __shfl_xor_sync(0xffffffffu, mx1, 2));
        float nm0 = fmaxf(m0r, mx0), nm1 = fmaxf(m1r, mx1);
        float al0 = ex2(m0r - nm0), al1 = ex2(m1r - nm1);
        m0r = nm0; m1r = nm1;
        float sum0 = 0.f, sum1 = 0.f;
        uint32_t pa[4][4];
        #pragma unroll
        for (int ks = 0; ks < 4; ks++) {
            #pragma unroll
            for (int half = 0; half < 2; half++) {
                int nj = 2 * ks + half;
                float p0 = ex2(s[nj][0] - nm0);
                float p1 = ex2(s[nj][1] - nm0);
                float p2 = ex2(s[nj][2] - nm1);
                float p3 = ex2(s[nj][3] - nm1);
                sum0 += p0 + p1; sum1 += p2 + p3;
                pa[ks][2 * half]     = packh2(p0, p1);
                pa[ks][2 * half + 1] = packh2(p2, p3);
            }
        }
        sum0 += __shfl_xor_sync(0xffffffffu, sum0, 1);
        sum0 += __shfl_xor_sync(0xffffffffu, sum0, 2);
        sum1 += __shfl_xor_sync(0xffffffffu, sum1, 1);
        sum1 += __shfl_xor_sync(0xffffffffu, sum1, 2);
        l0 = l0 * al0 + sum0;
        l1 = l1 * al1 + sum1;
        #pragma unroll
        for (int nj = 0; nj < 8; nj++) {
            o[nj][0] *= al0; o[nj][1] *= al0;
            o[nj][2] *= al1; o[nj][3] *= al1;
        }

        // --- O += P V (warp: 16x64), 32 mma — P from registers
        #pragma unroll
        for (int ks = 0; ks < 4; ks++)
            #pragma unroll
            for (int nj = 0; nj < 8; nj++) {
                uint2 vb = *(const uint2*)&cur[2176 + (ks * 4 + lc) * 136 + (8 * nj + lr) * 2];
                uint32_t bb[2] = {vb.x, vb.y};
                mma16(o[nj], pa[ks], bb);
            }

        // --- store next stage, single barrier
        if (more) {
            uint32_t kv[8] = {nk0.x, nk0.y, nk0.z, nk0.w, nk1.x, nk1.y, nk1.z, nk1.w};
            #pragma unroll
            for (int j = 0; j < 8; j++) nxt[kidx[j]] = kv[j];
            uint32_t a0[4] = {nv0.x, nv0.y, nv0.z, nv0.w};
            uint32_t a1[4] = {nv1.x, nv1.y, nv1.z, nv1.w};
            #pragma unroll
            for (int i = 0; i < 4; i++) {
                int d0 = 2 * (vcb2 + i);
                nxt[vslot + d0 * 2]       = prmt(a0[i], a1[i], 0x5410u);
                nxt[vslot + (d0 + 1) * 2] = prmt(a0[i], a1[i], 0x7632u);
            }
            __syncthreads();
        }
    }

    // --- normalize + write packed (hi, lo)
    float inv0 = 1.0f / l0, inv1 = 1.0f / l1;
    int row = r0 + q0w + lr;
    size_t off0 = ((size_t)(b * T_ + row)) * C2 + h * 32;
    size_t off1 = off0 + 8 * C2;
    #pragma unroll
    for (int nj = 0; nj < 8; nj++) {
        int d2 = 4 * nj + lc;
        float v00 = o[nj][0] * inv0, v01 = o[nj][1] * inv0;
        float v10 = o[nj][2] * inv1, v11 = o[nj][3] * inv1;
        oh[off0 + d2] = packh2(v00, v01);
        ol[off0 + d2] = packh2(v00 - h16(v00), v01 - h16(v01));
        oh[off1 + d2] = packh2(v10, v11);
        ol[off1 + d2] = packh2(v10 - h16(v10), v11 - h16(v11));
    }
}

// ---------------------------------------------------------------------------
extern "C" void kernel_launch(void* const* d_in, const int* in_sizes, int n_in,
                              void* d_out, int out_size)
{
    const float* x     = (const float*)d_in[0];
    const float* gamma = (const float*)d_in[1];
    const float* beta  = (const float*)d_in[2];
    const float* w_qkv = (const float*)d_in[3];
    const float* w_out = (const float*)d_in[4];
    const float* b_out = (const float*)d_in[5];
    float* out = (float*)d_out;

    uint32_t *xh, *xl, *qh, *ah, *al, *wqh, *wql, *woh, *wol;
    cudaGetSymbolAddress((void**)&xh,  g_xh);
    cudaGetSymbolAddress((void**)&xl,  g_xl);
    cudaGetSymbolAddress((void**)&qh,  g_qh);
    cudaGetSymbolAddress((void**)&ah,  g_ah);
    cudaGetSymbolAddress((void**)&al,  g_al);
    cudaGetSymbolAddress((void**)&wqh, g_wqh);
    cudaGetSymbolAddress((void**)&wql, g_wql);
    cudaGetSymbolAddress((void**)&woh, g_woh);
    cudaGetSymbolAddress((void**)&wol, g_wol);

    // 0) weight pre-split (packed fp16x2 hi/lo)
    wsplit_kernel<<<(QKV3 * C2 + 255) / 256, 256>>>(w_qkv, wqh, wql, QKV3 * C2);
    wsplit_kernel<<<(C_ * C2 + 255) / 256, 256>>>(w_out, woh, wol, C_ * C2);

    // 1) LayerNorm -> packed (hi, lo)
    ln_kernel<<<NTOK / 8, 256>>>(x, gamma, beta, xh, xl);

    // 2) QKV projection -> packed fp16 (hi only); x2 split (output is fp16 anyway)
    gemm_p<true, false><<<dim3(QKV3 / 128, NTOK / 128), 256>>>(
        xh, xl, wqh, wql, nullptr, nullptr, qh, NTOK, QKV3, C2);

    // 3) Flash attention -> packed (hi, lo)
    attn_p<<<dim3(T_ / 128, B_ * H_), 256>>>(qh, ah, al);

    // 4) Output projection + bias -> fp32; full x3 (output compared in fp32)
    gemm_p<false, true><<<dim3(C_ / 128, NTOK / 128), 256>>>(
        ah, al, woh, wol, b_out, out, nullptr, NTOK, C_, C2);
}

// round 9
// speedup vs baseline: 3.6603x; 1.1171x over previous
#include <cuda_runtime.h>
#include <cuda_fp16.h>
#include <math.h>
#include <stdint.h>

#define B_    2
#define T_    4096
#define C_    768
#define H_    12
#define D_    64
#define QKV3  2304
#define NTOK  (B_ * T_)
#define C2    384      // C_/2  (u32-packed pairs)
#define QKV32 1152     // QKV3/2

// Packed fp16x2 scratch (allocation-free __device__ globals)
__device__ uint32_t g_xh[(size_t)NTOK * C2];
__device__ uint32_t g_xl[(size_t)NTOK * C2];
__device__ uint32_t g_qh[(size_t)NTOK * QKV32];   // qkv, fp16 hi only
__device__ uint32_t g_ah[(size_t)NTOK * C2];
__device__ uint32_t g_al[(size_t)NTOK * C2];
__device__ uint32_t g_wqh[(size_t)QKV3 * C2];
__device__ uint32_t g_wql[(size_t)QKV3 * C2];
__device__ uint32_t g_woh[(size_t)C_ * C2];
__device__ uint32_t g_wol[(size_t)C_ * C2];

__device__ __forceinline__ uint32_t packh2(float lo, float hi) {
    uint32_t r;
    asm("cvt.rn.f16x2.f32 %0, %1, %2;" : "=r"(r) : "f"(hi), "f"(lo));
    return r;
}
__device__ __forceinline__ float h16(float v) {
    return __half2float(__float2half_rn(v));
}
__device__ __forceinline__ float ex2(float x) {
    float y;
    asm("ex2.approx.f32 %0, %1;" : "=f"(y) : "f"(x));
    return y;
}
__device__ __forceinline__ uint32_t prmt(uint32_t a, uint32_t b, uint32_t sel) {
    uint32_t r;
    asm("prmt.b32 %0, %1, %2, %3;" : "=r"(r) : "r"(a), "r"(b), "r"(sel));
    return r;
}
__device__ __forceinline__ void mma16(float* d, const uint32_t* a, const uint32_t* b) {
    asm volatile(
        "mma.sync.aligned.m16n8k16.row.col.f32.f16.f16.f32 "
        "{%0,%1,%2,%3}, {%4,%5,%6,%7}, {%8,%9}, {%0,%1,%2,%3};\n"
        : "+f"(d[0]), "+f"(d[1]), "+f"(d[2]), "+f"(d[3])
        : "r"(a[0]), "r"(a[1]), "r"(a[2]), "r"(a[3]), "r"(b[0]), "r"(b[1]));
}

// ---------------------------------------------------------------------------
// Weight split: fp32 [O][768] -> packed (hi, lo) fp16x2 u32 [O][384]
// ---------------------------------------------------------------------------
__global__ void wsplit_kernel(const float* __restrict__ w,
                              uint32_t* __restrict__ wh, uint32_t* __restrict__ wl,
                              int n2)
{
    int i = blockIdx.x * 256 + threadIdx.x;
    if (i < n2) {
        float2 v = *(const float2*)(w + 2 * i);
        float hx = h16(v.x), hy = h16(v.y);
        wh[i] = packh2(v.x, v.y);
        wl[i] = packh2(v.x - hx, v.y - hy);
    }
}

// ---------------------------------------------------------------------------
// LayerNorm, warp-per-row -> packed (hi, lo) output
// ---------------------------------------------------------------------------
__global__ void __launch_bounds__(256) ln_kernel(
    const float* __restrict__ x, const float* __restrict__ gamma,
    const float* __restrict__ beta,
    uint32_t* __restrict__ oh, uint32_t* __restrict__ ol)
{
    int row  = blockIdx.x * 8 + (threadIdx.x >> 5);
    int lane = threadIdx.x & 31;
    const float* xr = x + (size_t)row * C_;
    float4 v[6];
    float s = 0.f, ss = 0.f;
    #pragma unroll
    for (int j = 0; j < 6; j++) {
        v[j] = *(const float4*)(xr + j * 128 + lane * 4);
        s  += v[j].x + v[j].y + v[j].z + v[j].w;
        ss += v[j].x * v[j].x + v[j].y * v[j].y + v[j].z * v[j].z + v[j].w * v[j].w;
    }
    #pragma unroll
    for (int o = 16; o > 0; o >>= 1) {
        s  += __shfl_xor_sync(0xffffffffu, s,  o);
        ss += __shfl_xor_sync(0xffffffffu, ss, o);
    }
    float mean = s * (1.0f / C_);
    float var  = ss * (1.0f / C_) - mean * mean;
    float rstd = rsqrtf(var + 1e-5f);
    uint32_t* ohr = oh + (size_t)row * C2;
    uint32_t* olr = ol + (size_t)row * C2;
    #pragma unroll
    for (int j = 0; j < 6; j++) {
        int c = j * 128 + lane * 4;
        float4 g = *(const float4*)(gamma + c);
        float4 bt = *(const float4*)(beta + c);
        float rx = (v[j].x - mean) * rstd * g.x + bt.x;
        float ry = (v[j].y - mean) * rstd * g.y + bt.y;
        float rz = (v[j].z - mean) * rstd * g.z + bt.z;
        float rw = (v[j].w - mean) * rstd * g.w + bt.w;
        int c2 = j * 64 + lane * 2;
        ohr[c2]     = packh2(rx, ry);
        ohr[c2 + 1] = packh2(rz, rw);
        olr[c2]     = packh2(rx - h16(rx), ry - h16(ry));
        olr[c2 + 1] = packh2(rz - h16(rz), rw - h16(rw));
    }
}

// ---------------------------------------------------------------------------
// GEMM NT on pre-packed fp16x2 operands, x2 split (hh+lh = exact-A x fp16-B).
// Block 128x128, stage = 8 k2 (16 k), double-buffered, 256 thr.
// Warp shape 4(m) x 2(n): warp tile 32x64 — balances A/B smem traffic
// (4KB/warp-iter vs 5KB for 64x32), cutting the binding L1 wavefront load.
// Stage smem u32 (4224): Ah@0 Al@1056 Bh@2112 (Bl slot unused), stride 264.
// __launch_bounds__(256,2): 2 blocks/SM is load-bearing.
// ---------------------------------------------------------------------------
template <bool PACKED_OUT>
__global__ void __launch_bounds__(256, 2) gemm_p(
    const uint32_t* __restrict__ Ah, const uint32_t* __restrict__ Al,
    const uint32_t* __restrict__ Bh,
    const float* __restrict__ bias, float* __restrict__ Cf,
    uint32_t* __restrict__ Cp, int M, int N, int K2)
{
    __shared__ uint32_t smu[6336];   // 2 stages x 3168 (Ah,Al,Bh)
    int tid  = threadIdx.x;
    int lane = tid & 31, warp = tid >> 5;
    int lr = lane >> 2, lc = lane & 3;
    int wm = (warp & 3) * 32, wn = (warp >> 2) * 64;
    int m0 = blockIdx.y * 128, n0 = blockIdx.x * 128;
    int lrow = tid >> 1, comp = tid & 1;
    int sbase = lrow * 2 + comp;
    const uint32_t* ApH = Ah + (size_t)(m0 + lrow) * K2 + comp * 4;
    const uint32_t* ApL = Al + (size_t)(m0 + lrow) * K2 + comp * 4;
    const uint32_t* BpH = Bh + (size_t)(n0 + lrow) * K2 + comp * 4;

    float acc[2][8][4];
    #pragma unroll
    for (int i = 0; i < 2; i++)
        #pragma unroll
        for (int j = 0; j < 8; j++)
            #pragma unroll
            for (int r = 0; r < 4; r++) acc[i][j][r] = 0.f;

    uint4 vah, val, vbh;
    #define LDGP(k2o) do { \
        vah = *(const uint4*)(ApH + (k2o)); val = *(const uint4*)(ApL + (k2o)); \
        vbh = *(const uint4*)(BpH + (k2o)); \
    } while (0)
    #define STSP(W) do { \
        (W)[0 * 264 + sbase] = vah.x; (W)[1 * 264 + sbase] = vah.y; \
        (W)[2 * 264 + sbase] = vah.z; (W)[3 * 264 + sbase] = vah.w; \
        (W)[1056 + 0 * 264 + sbase] = val.x; (W)[1056 + 1 * 264 + sbase] = val.y; \
        (W)[1056 + 2 * 264 + sbase] = val.z; (W)[1056 + 3 * 264 + sbase] = val.w; \
        (W)[2112 + 0 * 264 + sbase] = vbh.x; (W)[2112 + 1 * 264 + sbase] = vbh.y; \
        (W)[2112 + 2 * 264 + sbase] = vbh.z; (W)[2112 + 3 * 264 + sbase] = vbh.w; \
    } while (0)

    LDGP(0);
    STSP(smu);
    __syncthreads();

    int nk = K2 / 8;
    for (int it = 0; it < nk; it++) {
        if (it + 1 < nk) LDGP((it + 1) * 8);
        const uint32_t* S = smu + (it & 1) * 3168;
        uint32_t ra[2][4], la[2][4], rb[8][2];
        #pragma unroll
        for (int mi = 0; mi < 2; mi++) {
            int m = wm + 16 * mi;
            uint2 h0 = *(const uint2*)&S[lc * 264 + (m + lr) * 2];
            uint2 h1 = *(const uint2*)&S[lc * 264 + (m + 8 + lr) * 2];
            uint2 l0 = *(const uint2*)&S[1056 + lc * 264 + (m + lr) * 2];
            uint2 l1 = *(const uint2*)&S[1056 + lc * 264 + (m + 8 + lr) * 2];
            ra[mi][0] = h0.x; ra[mi][1] = h1.x; ra[mi][2] = h0.y; ra[mi][3] = h1.y;
            la[mi][0] = l0.x; la[mi][1] = l1.x; la[mi][2] = l0.y; la[mi][3] = l1.y;
        }
        #pragma unroll
        for (int nj = 0; nj < 8; nj++) {
            int n = wn + 8 * nj;
            uint2 hb2 = *(const uint2*)&S[2112 + lc * 264 + (n + lr) * 2];
            rb[nj][0] = hb2.x; rb[nj][1] = hb2.y;
        }
        #pragma unroll
        for (int mi = 0; mi < 2; mi++)
            #pragma unroll
            for (int nj = 0; nj < 8; nj++) {
                mma16(acc[mi][nj], ra[mi], rb[nj]);
                mma16(acc[mi][nj], la[mi], rb[nj]);
            }
        if (it + 1 < nk) {
            uint32_t* W = smu + ((it + 1) & 1) * 3168;
            STSP(W);
        }
        __syncthreads();
    }

    if (PACKED_OUT) {
        int N2 = N >> 1;
        #pragma unroll
        for (int mi = 0; mi < 2; mi++)
            #pragma unroll
            for (int nj = 0; nj < 8; nj++) {
                int row = m0 + wm + mi * 16 + lr;
                int col2 = ((n0 + wn) >> 1) + 4 * nj + lc;
                Cp[(size_t)row * N2 + col2] = packh2(acc[mi][nj][0], acc[mi][nj][1]);
                Cp[(size_t)(row + 8) * N2 + col2] = packh2(acc[mi][nj][2], acc[mi][nj][3]);
            }
    } else {
        #pragma unroll
        for (int mi = 0; mi < 2; mi++)
            #pragma unroll
            for (int nj = 0; nj < 8; nj++) {
                int row = m0 + wm + mi * 16 + lr;
                int col = n0 + wn + nj * 8 + 2 * lc;
                float bb0 = bias[col], bb1 = bias[col + 1];
                *(float2*)(Cf + (size_t)row * N + col) =
                    make_float2(acc[mi][nj][0] + bb0, acc[mi][nj][1] + bb1);
                *(float2*)(Cf + (size_t)(row + 8) * N + col) =
                    make_float2(acc[mi][nj][2] + bb0, acc[mi][nj][3] + bb1);
            }
    }
}

// ---------------------------------------------------------------------------
// Flash attention on packed fp16 qkv. 256 threads (8 warps), q-tile 128.
// Double-buffered K/V smem (stage = 4352 u32). P register-resident
// (S-output fragment of m16n8k16 IS the PV A-fragment). One barrier per kt.
// Softmax: raw-S max, ex2(fma(s,QSC,-nm)), O-rescale skipped via warp vote.
// ---------------------------------------------------------------------------
__global__ void __launch_bounds__(256, 2) attn_p(
    const uint32_t* __restrict__ qh,
    uint32_t* __restrict__ oh, uint32_t* __restrict__ ol)
{
    __shared__ uint32_t smu[8704];   // 2 stages x 4352

    int tid  = threadIdx.x;
    int lane = tid & 31, warp = tid >> 5;
    int lr = lane >> 2, lc = lane & 3;
    int qt = (gridDim.x - 1) - blockIdx.x;
    int bh = blockIdx.y;
    int b = bh / H_, h = bh % H_;
    int r0 = qt * 128;
    int q0w = warp * 16;
    const uint32_t* base = qh + (size_t)b * T_ * QKV32 + h * 32;
    const float QSC = 0.125f * 1.4426950408889634f;

    // fill indices (fixed per thread)
    int kss = tid >> 2, kd2b = (tid & 3) * 8;
    int kidx[8];
    #pragma unroll
    for (int j = 0; j < 8; j++) {
        int k2 = kd2b + j;
        kidx[j] = ((k2 >> 3) * 4 + (k2 & 3)) * 136 + kss * 2 + ((k2 & 7) >> 2);
    }
    int vrp = tid >> 3, vcb2 = (tid & 7) * 4;
    int vslot = 2176 + ((vrp >> 3) * 4 + (vrp & 3)) * 136 + ((vrp & 7) >> 2);

    // Q fragments: direct u32 loads
    uint32_t qf[4][4];
    {
        const uint32_t* q0 = base + (size_t)(r0 + q0w + lr) * QKV32;
        const uint32_t* q1 = q0 + 8 * QKV32;
        #pragma unroll
        for (int ks = 0; ks < 4; ks++) {
            qf[ks][0] = q0[8 * ks + lc];
            qf[ks][1] = q1[8 * ks + lc];
            qf[ks][2] = q0[8 * ks + 4 + lc];
            qf[ks][3] = q1[8 * ks + 4 + lc];
        }
    }

    float o[8][4];
    #pragma unroll
    for (int nj = 0; nj < 8; nj++)
        #pragma unroll
        for (int r = 0; r < 4; r++) o[nj][r] = 0.f;
    float m0r = -INFINITY, m1r = -INFINITY, l0 = 0.f, l1 = 0.f;

    int nkt = ((qt >> 1) + 1) << 2;   // (frame+1)*4 key tiles of 64

    // prefill stage 0
    {
        const uint32_t* kp = base + 384 + (size_t)kss * QKV32 + kd2b;
        uint4 k0 = *(const uint4*)kp;
        uint4 k1 = *(const uint4*)(kp + 4);
        uint32_t kv[8] = {k0.x, k0.y, k0.z, k0.w, k1.x, k1.y, k1.z, k1.w};
        #pragma unroll
        for (int j = 0; j < 8; j++) smu[kidx[j]] = kv[j];
        const uint32_t* vp = base + 768 + (size_t)(2 * vrp) * QKV32 + vcb2;
        uint4 v0 = *(const uint4*)vp;
        uint4 v1 = *(const uint4*)(vp + QKV32);
        uint32_t a0[4] = {v0.x, v0.y, v0.z, v0.w};
        uint32_t a1[4] = {v1.x, v1.y, v1.z, v1.w};
        #pragma unroll
        for (int i = 0; i < 4; i++) {
            int d0 = 2 * (vcb2 + i);
            smu[vslot + d0 * 2]       = prmt(a0[i], a1[i], 0x5410u);
            smu[vslot + (d0 + 1) * 2] = prmt(a0[i], a1[i], 0x7632u);
        }
    }
    __syncthreads();

    for (int kt = 0; kt < nkt; kt++) {
        const uint32_t* cur = smu + (kt & 1) * 4352;
        uint32_t* nxt = smu + ((kt + 1) & 1) * 4352;
        bool more = (kt + 1 < nkt);

        // issue next-stage LDGs early (latency hidden under mma)
        uint4 nk0, nk1, nv0, nv1;
        if (more) {
            const uint32_t* kp = base + 384 + (size_t)((kt + 1) * 64 + kss) * QKV32 + kd2b;
            nk0 = *(const uint4*)kp;
            nk1 = *(const uint4*)(kp + 4);
            const uint32_t* vp = base + 768 + (size_t)((kt + 1) * 64 + 2 * vrp) * QKV32 + vcb2;
            nv0 = *(const uint4*)vp;
            nv1 = *(const uint4*)(vp + QKV32);
        }

        // --- S = Q K^T (warp: 16x64), 32 mma (raw scores)
        float s[8][4];
        #pragma unroll
        for (int nj = 0; nj < 8; nj++)
            #pragma unroll
            for (int r = 0; r < 4; r++) s[nj][r] = 0.f;
        #pragma unroll
        for (int ks = 0; ks < 4; ks++)
            #pragma unroll
            for (int nj = 0; nj < 8; nj++) {
                uint2 kb = *(const uint2*)&cur[(ks * 4 + lc) * 136 + (8 * nj + lr) * 2];
                uint32_t bb[2] = {kb.x, kb.y};
                mma16(s[nj], qf[ks], bb);
            }

        // --- online softmax (exp2 domain; scale folded into ex2 arg)
        float mx0 = -INFINITY, mx1 = -INFINITY;
        #pragma unroll
        for (int nj = 0; nj < 8; nj++) {
            mx0 = fmaxf(mx0, fmaxf(s[nj][0], s[nj][1]));
            mx1 = fmaxf(mx1, fmaxf(s[nj][2], s[nj][3]));
        }
        mx0 = fmaxf(mx0, __shfl_xor_sync(0xffffffffu, mx0, 1));
        mx0 = fmaxf(mx0, __shfl_xor_sync(0xffffffffu, mx0, 2));
        mx1 = fmaxf(mx1, __shfl_xor_sync(0xffffffffu, mx1, 1));
        mx1 = fmaxf(mx1, __shfl_xor_sync(0xffffffffu, mx1, 2));
        float nm0 = fmaxf(m0r, mx0 * QSC), nm1 = fmaxf(m1r, mx1 * QSC);
        float al0 = ex2(m0r - nm0), al1 = ex2(m1r - nm1);
        m0r = nm0; m1r = nm1;
        float sum0 = 0.f, sum1 = 0.f;
        uint32_t pa[4][4];
        #pragma unroll
        for (int ks = 0; ks < 4; ks++) {
            #pragma unroll
            for (int half = 0; half < 2; half++) {
                int nj = 2 * ks + half;
                float p0 = ex2(fmaf(s[nj][0], QSC, -nm0));
                float p1 = ex2(fmaf(s[nj][1], QSC, -nm0));
                float p2 = ex2(fmaf(s[nj][2], QSC, -nm1));
                float p3 = ex2(fmaf(s[nj][3], QSC, -nm1));
                sum0 += p0 + p1; sum1 += p2 + p3;
                pa[ks][2 * half]     = packh2(p0, p1);
                pa[ks][2 * half + 1] = packh2(p2, p3);
            }
        }
        sum0 += __shfl_xor_sync(0xffffffffu, sum0, 1);
        sum0 += __shfl_xor_sync(0xffffffffu, sum0, 2);
        sum1 += __shfl_xor_sync(0xffffffffu, sum1, 1);
        sum1 += __shfl_xor_sync(0xffffffffu, sum1, 2);
        l0 = l0 * al0 + sum0;
        l1 = l1 * al1 + sum1;
        if (__any_sync(0xffffffffu, (al0 != 1.0f) | (al1 != 1.0f))) {
            #pragma unroll
            for (int nj = 0; nj < 8; nj++) {
                o[nj][0] *= al0; o[nj][1] *= al0;
                o[nj][2] *= al1; o[nj][3] *= al1;
            }
        }

        // --- O += P V (warp: 16x64), 32 mma — P from registers
        #pragma unroll
        for (int ks = 0; ks < 4; ks++)
            #pragma unroll
            for (int nj = 0; nj < 8; nj++) {
                uint2 vb = *(const uint2*)&cur[2176 + (ks * 4 + lc) * 136 + (8 * nj + lr) * 2];
                uint32_t bb[2] = {vb.x, vb.y};
                mma16(o[nj], pa[ks], bb);
            }

        // --- store next stage, single barrier
        if (more) {
            uint32_t kv[8] = {nk0.x, nk0.y, nk0.z, nk0.w, nk1.x, nk1.y, nk1.z, nk1.w};
            #pragma unroll
            for (int j = 0; j < 8; j++) nxt[kidx[j]] = kv[j];
            uint32_t a0[4] = {nv0.x, nv0.y, nv0.z, nv0.w};
            uint32_t a1[4] = {nv1.x, nv1.y, nv1.z, nv1.w};
            #pragma unroll
            for (int i = 0; i < 4; i++) {
                int d0 = 2 * (vcb2 + i);
                nxt[vslot + d0 * 2]       = prmt(a0[i], a1[i], 0x5410u);
                nxt[vslot + (d0 + 1) * 2] = prmt(a0[i], a1[i], 0x7632u);
            }
            __syncthreads();
        }
    }

    // --- normalize + write packed (hi, lo)
    float inv0 = 1.0f / l0, inv1 = 1.0f / l1;
    int row = r0 + q0w + lr;
    size_t off0 = ((size_t)(b * T_ + row)) * C2 + h * 32;
    size_t off1 = off0 + 8 * C2;
    #pragma unroll
    for (int nj = 0; nj < 8; nj++) {
        int d2 = 4 * nj + lc;
        float v00 = o[nj][0] * inv0, v01 = o[nj][1] * inv0;
        float v10 = o[nj][2] * inv1, v11 = o[nj][3] * inv1;
        oh[off0 + d2] = packh2(v00, v01);
        ol[off0 + d2] = packh2(v00 - h16(v00), v01 - h16(v01));
        oh[off1 + d2] = packh2(v10, v11);
        ol[off1 + d2] = packh2(v10 - h16(v10), v11 - h16(v11));
    }
}

// ---------------------------------------------------------------------------
extern "C" void kernel_launch(void* const* d_in, const int* in_sizes, int n_in,
                              void* d_out, int out_size)
{
    const float* x     = (const float*)d_in[0];
    const float* gamma = (const float*)d_in[1];
    const float* beta  = (const float*)d_in[2];
    const float* w_qkv = (const float*)d_in[3];
    const float* w_out = (const float*)d_in[4];
    const float* b_out = (const float*)d_in[5];
    float* out = (float*)d_out;

    uint32_t *xh, *xl, *qh, *ah, *al, *wqh, *wql, *woh, *wol;
    cudaGetSymbolAddress((void**)&xh,  g_xh);
    cudaGetSymbolAddress((void**)&xl,  g_xl);
    cudaGetSymbolAddress((void**)&qh,  g_qh);
    cudaGetSymbolAddress((void**)&ah,  g_ah);
    cudaGetSymbolAddress((void**)&al,  g_al);
    cudaGetSymbolAddress((void**)&wqh, g_wqh);
    cudaGetSymbolAddress((void**)&wql, g_wql);
    cudaGetSymbolAddress((void**)&woh, g_woh);
    cudaGetSymbolAddress((void**)&wol, g_wol);

    // 0) weight pre-split (packed fp16x2 hi/lo; lo kept for possible x3 revert)
    wsplit_kernel<<<(QKV3 * C2 + 255) / 256, 256>>>(w_qkv, wqh, wql, QKV3 * C2);
    wsplit_kernel<<<(C_ * C2 + 255) / 256, 256>>>(w_out, woh, wol, C_ * C2);

    // 1) LayerNorm -> packed (hi, lo)
    ln_kernel<<<NTOK / 8, 256>>>(x, gamma, beta, xh, xl);

    // 2) QKV projection -> packed fp16 (hi only); x2 split
    gemm_p<true><<<dim3(QKV3 / 128, NTOK / 128), 256>>>(
        xh, xl, wqh, nullptr, nullptr, qh, NTOK, QKV3, C2);

    // 3) Flash attention -> packed (hi, lo)
    attn_p<<<dim3(T_ / 128, B_ * H_), 256>>>(qh, ah, al);

    // 4) Output projection + bias -> fp32; x2 split
    gemm_p<false><<<dim3(C_ / 128, NTOK / 128), 256>>>(
        ah, al, woh, b_out, out, nullptr, NTOK, C_, C2);
}

// round 11
// speedup vs baseline: 3.9800x; 1.0874x over previous
#include <cuda_runtime.h>
#include <cuda_fp16.h>
#include <math.h>
#include <stdint.h>

#define B_    2
#define T_    4096
#define C_    768
#define H_    12
#define D_    64
#define QKV3  2304
#define NTOK  (B_ * T_)
#define C2    384      // C_/2  (u32-packed pairs)
#define QKV32 1152     // QKV3/2

// Packed fp16x2 scratch (allocation-free __device__ globals)
__device__ uint32_t g_xh[(size_t)NTOK * C2];
__device__ uint32_t g_xl[(size_t)NTOK * C2];
__device__ uint32_t g_qh[(size_t)NTOK * QKV32];   // qkv, fp16 hi only
__device__ uint32_t g_ah[(size_t)NTOK * C2];
__device__ uint32_t g_al[(size_t)NTOK * C2];
__device__ uint32_t g_wqh[(size_t)QKV3 * C2];
__device__ uint32_t g_woh[(size_t)C_ * C2];

__device__ __forceinline__ uint32_t packh2(float lo, float hi) {
    uint32_t r;
    asm("cvt.rn.f16x2.f32 %0, %1, %2;" : "=r"(r) : "f"(hi), "f"(lo));
    return r;
}
__device__ __forceinline__ float h16(float v) {
    return __half2float(__float2half_rn(v));
}
__device__ __forceinline__ float ex2(float x) {
    float y;
    asm("ex2.approx.f32 %0, %1;" : "=f"(y) : "f"(x));
    return y;
}
__device__ __forceinline__ uint32_t prmt(uint32_t a, uint32_t b, uint32_t sel) {
    uint32_t r;
    asm("prmt.b32 %0, %1, %2, %3;" : "=r"(r) : "r"(a), "r"(b), "r"(sel));
    return r;
}
__device__ __forceinline__ void mma16(float* d, const uint32_t* a, const uint32_t* b) {
    asm volatile(
        "mma.sync.aligned.m16n8k16.row.col.f32.f16.f16.f32 "
        "{%0,%1,%2,%3}, {%4,%5,%6,%7}, {%8,%9}, {%0,%1,%2,%3};\n"
        : "+f"(d[0]), "+f"(d[1]), "+f"(d[2]), "+f"(d[3])
        : "r"(a[0]), "r"(a[1]), "r"(a[2]), "r"(a[3]), "r"(b[0]), "r"(b[1]));
}

// ---------------------------------------------------------------------------
// Weight split: fp32 [O][768] -> packed hi fp16x2 u32 [O][384] (lo optional)
// ---------------------------------------------------------------------------
__global__ void wsplit_kernel(const float* __restrict__ w,
                              uint32_t* __restrict__ wh, uint32_t* __restrict__ wl,
                              int n2)
{
    int i = blockIdx.x * 256 + threadIdx.x;
    if (i < n2) {
        float2 v = *(const float2*)(w + 2 * i);
        wh[i] = packh2(v.x, v.y);
        if (wl) {
            float hx = h16(v.x), hy = h16(v.y);
            wl[i] = packh2(v.x - hx, v.y - hy);
        }
    }
}

// ---------------------------------------------------------------------------
// LayerNorm, warp-per-row -> packed (hi, lo) output
// ---------------------------------------------------------------------------
__global__ void __launch_bounds__(256) ln_kernel(
    const float* __restrict__ x, const float* __restrict__ gamma,
    const float* __restrict__ beta,
    uint32_t* __restrict__ oh, uint32_t* __restrict__ ol)
{
    int row  = blockIdx.x * 8 + (threadIdx.x >> 5);
    int lane = threadIdx.x & 31;
    const float* xr = x + (size_t)row * C_;
    float4 v[6];
    float s = 0.f, ss = 0.f;
    #pragma unroll
    for (int j = 0; j < 6; j++) {
        v[j] = *(const float4*)(xr + j * 128 + lane * 4);
        s  += v[j].x + v[j].y + v[j].z + v[j].w;
        ss += v[j].x * v[j].x + v[j].y * v[j].y + v[j].z * v[j].z + v[j].w * v[j].w;
    }
    #pragma unroll
    for (int o = 16; o > 0; o >>= 1) {
        s  += __shfl_xor_sync(0xffffffffu, s,  o);
        ss += __shfl_xor_sync(0xffffffffu, ss, o);
    }
    float mean = s * (1.0f / C_);
    float var  = ss * (1.0f / C_) - mean * mean;
    float rstd = rsqrtf(var + 1e-5f);
    uint32_t* ohr = oh + (size_t)row * C2;
    uint32_t* olr = ol + (size_t)row * C2;
    #pragma unroll
    for (int j = 0; j < 6; j++) {
        int c = j * 128 + lane * 4;
        float4 g = *(const float4*)(gamma + c);
        float4 bt = *(const float4*)(beta + c);
        float rx = (v[j].x - mean) * rstd * g.x + bt.x;
        float ry = (v[j].y - mean) * rstd * g.y + bt.y;
        float rz = (v[j].z - mean) * rstd * g.z + bt.z;
        float rw = (v[j].w - mean) * rstd * g.w + bt.w;
        int c2 = j * 64 + lane * 2;
        ohr[c2]     = packh2(rx, ry);
        ohr[c2 + 1] = packh2(rz, rw);
        olr[c2]     = packh2(rx - h16(rx), ry - h16(ry));
        olr[c2 + 1] = packh2(rz - h16(rz), rw - h16(rw));
    }
}

// ---------------------------------------------------------------------------
// GEMM NT on pre-packed fp16x2 operands, x2 split (hh+lh = exact-A x fp16-B).
// Block 128x128, stage = 8 k2 (16 k), double-buffered, 256 thr.
// Warp shape 4(m) x 2(n): warp tile 32x64 (optimal smem-traffic split).
// Stage smem u32 (3168): Ah@0 Al@1056 Bh@2112, kslot stride 264.
// __launch_bounds__(256,2): 2 blocks/SM is load-bearing.
// ---------------------------------------------------------------------------
template <bool PACKED_OUT>
__global__ void __launch_bounds__(256, 2) gemm_p(
    const uint32_t* __restrict__ Ah, const uint32_t* __restrict__ Al,
    const uint32_t* __restrict__ Bh,
    const float* __restrict__ bias, float* __restrict__ Cf,
    uint32_t* __restrict__ Cp, int M, int N, int K2)
{
    __shared__ uint32_t smu[6336];
    int tid  = threadIdx.x;
    int lane = tid & 31, warp = tid >> 5;
    int lr = lane >> 2, lc = lane & 3;
    int wm = (warp & 3) * 32, wn = (warp >> 2) * 64;
    int m0 = blockIdx.y * 128, n0 = blockIdx.x * 128;
    int lrow = tid >> 1, comp = tid & 1;
    int sbase = lrow * 2 + comp;
    const uint32_t* ApH = Ah + (size_t)(m0 + lrow) * K2 + comp * 4;
    const uint32_t* ApL = Al + (size_t)(m0 + lrow) * K2 + comp * 4;
    const uint32_t* BpH = Bh + (size_t)(n0 + lrow) * K2 + comp * 4;

    float acc[2][8][4];
    #pragma unroll
    for (int i = 0; i < 2; i++)
        #pragma unroll
        for (int j = 0; j < 8; j++)
            #pragma unroll
            for (int r = 0; r < 4; r++) acc[i][j][r] = 0.f;

    uint4 vah, val, vbh;
    #define LDGP(k2o) do { \
        vah = *(const uint4*)(ApH + (k2o)); val = *(const uint4*)(ApL + (k2o)); \
        vbh = *(const uint4*)(BpH + (k2o)); \
    } while (0)
    #define STSP(W) do { \
        (W)[0 * 264 + sbase] = vah.x; (W)[1 * 264 + sbase] = vah.y; \
        (W)[2 * 264 + sbase] = vah.z; (W)[3 * 264 + sbase] = vah.w; \
        (W)[1056 + 0 * 264 + sbase] = val.x; (W)[1056 + 1 * 264 + sbase] = val.y; \
        (W)[1056 + 2 * 264 + sbase] = val.z; (W)[1056 + 3 * 264 + sbase] = val.w; \
        (W)[2112 + 0 * 264 + sbase] = vbh.x; (W)[2112 + 1 * 264 + sbase] = vbh.y; \
        (W)[2112 + 2 * 264 + sbase] = vbh.z; (W)[2112 + 3 * 264 + sbase] = vbh.w; \
    } while (0)

    LDGP(0);
    STSP(smu);
    __syncthreads();

    int nk = K2 / 8;
    for (int it = 0; it < nk; it++) {
        if (it + 1 < nk) LDGP((it + 1) * 8);
        const uint32_t* S = smu + (it & 1) * 3168;
        uint32_t ra[2][4], la[2][4], rb[8][2];
        #pragma unroll
        for (int mi = 0; mi < 2; mi++) {
            int m = wm + 16 * mi;
            uint2 h0 = *(const uint2*)&S[lc * 264 + (m + lr) * 2];
            uint2 h1 = *(const uint2*)&S[lc * 264 + (m + 8 + lr) * 2];
            uint2 l0 = *(const uint2*)&S[1056 + lc * 264 + (m + lr) * 2];
            uint2 l1 = *(const uint2*)&S[1056 + lc * 264 + (m + 8 + lr) * 2];
            ra[mi][0] = h0.x; ra[mi][1] = h1.x; ra[mi][2] = h0.y; ra[mi][3] = h1.y;
            la[mi][0] = l0.x; la[mi][1] = l1.x; la[mi][2] = l0.y; la[mi][3] = l1.y;
        }
        #pragma unroll
        for (int nj = 0; nj < 8; nj++) {
            int n = wn + 8 * nj;
            uint2 hb2 = *(const uint2*)&S[2112 + lc * 264 + (n + lr) * 2];
            rb[nj][0] = hb2.x; rb[nj][1] = hb2.y;
        }
        #pragma unroll
        for (int mi = 0; mi < 2; mi++)
            #pragma unroll
            for (int nj = 0; nj < 8; nj++) {
                mma16(acc[mi][nj], ra[mi], rb[nj]);
                mma16(acc[mi][nj], la[mi], rb[nj]);
            }
        if (it + 1 < nk) {
            uint32_t* W = smu + ((it + 1) & 1) * 3168;
            STSP(W);
        }
        __syncthreads();
    }

    if (PACKED_OUT) {
        int N2 = N >> 1;
        #pragma unroll
        for (int mi = 0; mi < 2; mi++)
            #pragma unroll
            for (int nj = 0; nj < 8; nj++) {
                int row = m0 + wm + mi * 16 + lr;
                int col2 = ((n0 + wn) >> 1) + 4 * nj + lc;
                Cp[(size_t)row * N2 + col2] = packh2(acc[mi][nj][0], acc[mi][nj][1]);
                Cp[(size_t)(row + 8) * N2 + col2] = packh2(acc[mi][nj][2], acc[mi][nj][3]);
            }
    } else {
        #pragma unroll
        for (int mi = 0; mi < 2; mi++)
            #pragma unroll
            for (int nj = 0; nj < 8; nj++) {
                int row = m0 + wm + mi * 16 + lr;
                int col = n0 + wn + nj * 8 + 2 * lc;
                float bb0 = bias[col], bb1 = bias[col + 1];
                *(float2*)(Cf + (size_t)row * N + col) =
                    make_float2(acc[mi][nj][0] + bb0, acc[mi][nj][1] + bb1);
                *(float2*)(Cf + (size_t)(row + 8) * N + col) =
                    make_float2(acc[mi][nj][2] + bb0, acc[mi][nj][3] + bb1);
            }
    }
}

// ---------------------------------------------------------------------------
// Flash attention on packed fp16 qkv. 128 threads (4 warps), q-tile 128:
// each warp owns 32 q-rows as two 16-row m-tiles (mt=0,1), so every K/V
// fragment load from smem feeds TWO mmas — halves smem fragment traffic
// vs the 8-warp/16-row version. Double-buffered K/V (stage = 4352 u32):
//   Kq [0,2176):    [((k2>>3)*4+(k2&3))*136 + s*2 + ((k2&7)>>2)]
//   Vq [2176,4352): same with k-dim = s-pairs
// P register-resident (S fragment IS the PV A-fragment). One barrier per kt.
// Softmax: raw-S max, ex2(fma(s,QSC,-nm)), rescale skipped via warp vote.
// ---------------------------------------------------------------------------
__global__ void __launch_bounds__(128, 2) attn_p(
    const uint32_t* __restrict__ qh,
    uint32_t* __restrict__ oh, uint32_t* __restrict__ ol)
{
    __shared__ uint32_t smu[8704];   // 2 stages x 4352

    int tid  = threadIdx.x;
    int lane = tid & 31, warp = tid >> 5;
    int lr = lane >> 2, lc = lane & 3;
    int qt = (gridDim.x - 1) - blockIdx.x;
    int bh = blockIdx.y;
    int b = bh / H_, h = bh % H_;
    int r0 = qt * 128;
    int q0w = warp * 32;
    const uint32_t* base = qh + (size_t)b * T_ * QKV32 + h * 32;
    const float QSC = 0.125f * 1.4426950408889634f;

    // fill geometry (128 threads): K row per 2 threads, V s-pair per 4 threads
    int kss = tid >> 1, kd2b = (tid & 1) * 16;
    int vrp = tid >> 2, vcb2 = (tid & 3) * 8;
    int vslot = 2176 + ((vrp >> 3) * 4 + (vrp & 3)) * 136 + ((vrp & 7) >> 2);

    // Q fragments for both m-tiles
    uint32_t qf[2][4][4];
    #pragma unroll
    for (int mt = 0; mt < 2; mt++) {
        const uint32_t* q0 = base + (size_t)(r0 + q0w + mt * 16 + lr) * QKV32;
        const uint32_t* q1 = q0 + 8 * QKV32;
        #pragma unroll
        for (int ks = 0; ks < 4; ks++) {
            qf[mt][ks][0] = q0[8 * ks + lc];
            qf[mt][ks][1] = q1[8 * ks + lc];
            qf[mt][ks][2] = q0[8 * ks + 4 + lc];
            qf[mt][ks][3] = q1[8 * ks + 4 + lc];
        }
    }

    float o[2][8][4];
    #pragma unroll
    for (int mt = 0; mt < 2; mt++)
        #pragma unroll
        for (int nj = 0; nj < 8; nj++)
            #pragma unroll
            for (int r = 0; r < 4; r++) o[mt][nj][r] = 0.f;
    float mr[2][2] = {{-INFINITY, -INFINITY}, {-INFINITY, -INFINITY}};
    float lv[2][2] = {{0.f, 0.f}, {0.f, 0.f}};

    int nkt = ((qt >> 1) + 1) << 2;   // (frame+1)*4 key tiles of 64

    #define AFILL(dst, ktile) do { \
        const uint32_t* kp = base + 384 + (size_t)((ktile) * 64 + kss) * QKV32 + kd2b; \
        uint4 kq0 = *(const uint4*)kp;        uint4 kq1 = *(const uint4*)(kp + 4); \
        uint4 kq2 = *(const uint4*)(kp + 8);  uint4 kq3 = *(const uint4*)(kp + 12); \
        uint32_t kv[16] = {kq0.x, kq0.y, kq0.z, kq0.w, kq1.x, kq1.y, kq1.z, kq1.w, \
                           kq2.x, kq2.y, kq2.z, kq2.w, kq3.x, kq3.y, kq3.z, kq3.w}; \
        _Pragma("unroll") \
        for (int j = 0; j < 16; j++) { \
            int k2 = kd2b + j; \
            (dst)[((k2 >> 3) * 4 + (k2 & 3)) * 136 + kss * 2 + ((k2 & 7) >> 2)] = kv[j]; \
        } \
        const uint32_t* vp = base + 768 + (size_t)((ktile) * 64 + 2 * vrp) * QKV32 + vcb2; \
        uint4 va0 = *(const uint4*)vp;            uint4 va1 = *(const uint4*)(vp + 4); \
        uint4 vb0 = *(const uint4*)(vp + QKV32);  uint4 vb1 = *(const uint4*)(vp + QKV32 + 4); \
        uint32_t a0[8] = {va0.x, va0.y, va0.z, va0.w, va1.x, va1.y, va1.z, va1.w}; \
        uint32_t a1[8] = {vb0.x, vb0.y, vb0.z, vb0.w, vb1.x, vb1.y, vb1.z, vb1.w}; \
        _Pragma("unroll") \
        for (int i = 0; i < 8; i++) { \
            int d0 = 2 * (vcb2 + i); \
            (dst)[vslot + d0 * 2]       = prmt(a0[i], a1[i], 0x5410u); \
            (dst)[vslot + (d0 + 1) * 2] = prmt(a0[i], a1[i], 0x7632u); \
        } \
    } while (0)

    AFILL(smu, 0);
    __syncthreads();

    for (int kt = 0; kt < nkt; kt++) {
        const uint32_t* cur = smu + (kt & 1) * 4352;
        uint32_t* nxt = smu + ((kt + 1) & 1) * 4352;
        bool more = (kt + 1 < nkt);

        // --- S = Q K^T: one K-fragment load feeds both m-tiles
        float s[2][8][4];
        #pragma unroll
        for (int mt = 0; mt < 2; mt++)
            #pragma unroll
            for (int nj = 0; nj < 8; nj++)
                #pragma unroll
                for (int r = 0; r < 4; r++) s[mt][nj][r] = 0.f;
        #pragma unroll
        for (int ks = 0; ks < 4; ks++)
            #pragma unroll
            for (int nj = 0; nj < 8; nj++) {
                uint2 kb = *(const uint2*)&cur[(ks * 4 + lc) * 136 + (8 * nj + lr) * 2];
                uint32_t bb[2] = {kb.x, kb.y};
                mma16(s[0][nj], qf[0][ks], bb);
                mma16(s[1][nj], qf[1][ks], bb);
            }

        // --- online softmax per m-tile (exp2 domain, scale folded into fma)
        float al[2][2];
        uint32_t pa[2][4][4];
        #pragma unroll
        for (int mt = 0; mt < 2; mt++) {
            float mx0 = -INFINITY, mx1 = -INFINITY;
            #pragma unroll
            for (int nj = 0; nj < 8; nj++) {
                mx0 = fmaxf(mx0, fmaxf(s[mt][nj][0], s[mt][nj][1]));
                mx1 = fmaxf(mx1, fmaxf(s[mt][nj][2], s[mt][nj][3]));
            }
            mx0 = fmaxf(mx0, __shfl_xor_sync(0xffffffffu, mx0, 1));
            mx0 = fmaxf(mx0, __shfl_xor_sync(0xffffffffu, mx0, 2));
            mx1 = fmaxf(mx1, __shfl_xor_sync(0xffffffffu, mx1, 1));
            mx1 = fmaxf(mx1, __shfl_xor_sync(0xffffffffu, mx1, 2));
            float nm0 = fmaxf(mr[mt][0], mx0 * QSC);
            float nm1 = fmaxf(mr[mt][1], mx1 * QSC);
            al[mt][0] = ex2(mr[mt][0] - nm0);
            al[mt][1] = ex2(mr[mt][1] - nm1);
            mr[mt][0] = nm0; mr[mt][1] = nm1;
            float sum0 = 0.f, sum1 = 0.f;
            #pragma unroll
            for (int ks = 0; ks < 4; ks++) {
                #pragma unroll
                for (int half = 0; half < 2; half++) {
                    int nj = 2 * ks + half;
                    float p0 = ex2(fmaf(s[mt][nj][0], QSC, -nm0));
                    float p1 = ex2(fmaf(s[mt][nj][1], QSC, -nm0));
                    float p2 = ex2(fmaf(s[mt][nj][2], QSC, -nm1));
                    float p3 = ex2(fmaf(s[mt][nj][3], QSC, -nm1));
                    sum0 += p0 + p1; sum1 += p2 + p3;
                    pa[mt][ks][2 * half]     = packh2(p0, p1);
                    pa[mt][ks][2 * half + 1] = packh2(p2, p3);
                }
            }
            sum0 += __shfl_xor_sync(0xffffffffu, sum0, 1);
            sum0 += __shfl_xor_sync(0xffffffffu, sum0, 2);
            sum1 += __shfl_xor_sync(0xffffffffu, sum1, 1);
            sum1 += __shfl_xor_sync(0xffffffffu, sum1, 2);
            lv[mt][0] = lv[mt][0] * al[mt][0] + sum0;
            lv[mt][1] = lv[mt][1] * al[mt][1] + sum1;
        }
        if (__any_sync(0xffffffffu,
                       (al[0][0] != 1.0f) | (al[0][1] != 1.0f) |
                       (al[1][0] != 1.0f) | (al[1][1] != 1.0f))) {
            #pragma unroll
            for (int mt = 0; mt < 2; mt++)
                #pragma unroll
                for (int nj = 0; nj < 8; nj++) {
                    o[mt][nj][0] *= al[mt][0]; o[mt][nj][1] *= al[mt][0];
                    o[mt][nj][2] *= al[mt][1]; o[mt][nj][3] *= al[mt][1];
                }
        }

        // --- O += P V: one V-fragment load feeds both m-tiles
        #pragma unroll
        for (int ks = 0; ks < 4; ks++)
            #pragma unroll
            for (int nj = 0; nj < 8; nj++) {
                uint2 vb = *(const uint2*)&cur[2176 + (ks * 4 + lc) * 136 + (8 * nj + lr) * 2];
                uint32_t bb[2] = {vb.x, vb.y};
                mma16(o[0][nj], pa[0][ks], bb);
                mma16(o[1][nj], pa[1][ks], bb);
            }

        // --- fill next stage, single barrier
        if (more) {
            AFILL(nxt, kt + 1);
            __syncthreads();
        }
    }

    // --- normalize + write packed (hi, lo) per m-tile
    #pragma unroll
    for (int mt = 0; mt < 2; mt++) {
        float inv0 = 1.0f / lv[mt][0], inv1 = 1.0f / lv[mt][1];
        int row = r0 + q0w + mt * 16 + lr;
        size_t off0 = ((size_t)(b * T_ + row)) * C2 + h * 32;
        size_t off1 = off0 + 8 * C2;
        #pragma unroll
        for (int nj = 0; nj < 8; nj++) {
            int d2 = 4 * nj + lc;
            float v00 = o[mt][nj][0] * inv0, v01 = o[mt][nj][1] * inv0;
            float v10 = o[mt][nj][2] * inv1, v11 = o[mt][nj][3] * inv1;
            oh[off0 + d2] = packh2(v00, v01);
            ol[off0 + d2] = packh2(v00 - h16(v00), v01 - h16(v01));
            oh[off1 + d2] = packh2(v10, v11);
            ol[off1 + d2] = packh2(v10 - h16(v10), v11 - h16(v11));
        }
    }
}

// ---------------------------------------------------------------------------
extern "C" void kernel_launch(void* const* d_in, const int* in_sizes, int n_in,
                              void* d_out, int out_size)
{
    const float* x     = (const float*)d_in[0];
    const float* gamma = (const float*)d_in[1];
    const float* beta  = (const float*)d_in[2];
    const float* w_qkv = (const float*)d_in[3];
    const float* w_out = (const float*)d_in[4];
    const float* b_out = (const float*)d_in[5];
    float* out = (float*)d_out;

    uint32_t *xh, *xl, *qh, *ah, *al, *wqh, *woh;
    cudaGetSymbolAddress((void**)&xh,  g_xh);
    cudaGetSymbolAddress((void**)&xl,  g_xl);
    cudaGetSymbolAddress((void**)&qh,  g_qh);
    cudaGetSymbolAddress((void**)&ah,  g_ah);
    cudaGetSymbolAddress((void**)&al,  g_al);
    cudaGetSymbolAddress((void**)&wqh, g_wqh);
    cudaGetSymbolAddress((void**)&woh, g_woh);

    // 0) weight pre-split (hi only — x2 paths don't use weight-lo)
    wsplit_kernel<<<(QKV3 * C2 + 255) / 256, 256>>>(w_qkv, wqh, nullptr, QKV3 * C2);
    wsplit_kernel<<<(C_ * C2 + 255) / 256, 256>>>(w_out, woh, nullptr, C_ * C2);

    // 1) LayerNorm -> packed (hi, lo)
    ln_kernel<<<NTOK / 8, 256>>>(x, gamma, beta, xh, xl);

    // 2) QKV projection -> packed fp16 (hi only); x2 split
    gemm_p<true><<<dim3(QKV3 / 128, NTOK / 128), 256>>>(
        xh, xl, wqh, nullptr, nullptr, qh, NTOK, QKV3, C2);

    // 3) Flash attention -> packed (hi, lo); 32 q-rows/warp
    attn_p<<<dim3(T_ / 128, B_ * H_), 128>>>(qh, ah, al);

    // 4) Output projection + bias -> fp32; x2 split
    gemm_p<false><<<dim3(C_ / 128, NTOK / 128), 256>>>(
        ah, al, woh, b_out, out, nullptr, NTOK, C_, C2);
}

// round 12
// speedup vs baseline: 4.0687x; 1.0223x over previous
#include <cuda_runtime.h>
#include <cuda_fp16.h>
#include <math.h>
#include <stdint.h>

#define B_    2
#define T_    4096
#define C_    768
#define H_    12
#define D_    64
#define QKV3  2304
#define NTOK  (B_ * T_)
#define C2    384      // C_/2  (u32-packed pairs)
#define QKV32 1152     // QKV3/2

// Packed fp16x2 scratch (allocation-free __device__ globals)
__device__ uint32_t g_xh[(size_t)NTOK * C2];
__device__ uint32_t g_qh[(size_t)NTOK * QKV32];   // qkv, fp16
__device__ uint32_t g_ah[(size_t)NTOK * C2];
__device__ uint32_t g_al[(size_t)NTOK * C2];
__device__ uint32_t g_wqh[(size_t)QKV3 * C2];
__device__ uint32_t g_woh[(size_t)C_ * C2];

__device__ __forceinline__ uint32_t packh2(float lo, float hi) {
    uint32_t r;
    asm("cvt.rn.f16x2.f32 %0, %1, %2;" : "=r"(r) : "f"(hi), "f"(lo));
    return r;
}
__device__ __forceinline__ float h16(float v) {
    return __half2float(__float2half_rn(v));
}
__device__ __forceinline__ float ex2(float x) {
    float y;
    asm("ex2.approx.f32 %0, %1;" : "=f"(y) : "f"(x));
    return y;
}
__device__ __forceinline__ uint32_t prmt(uint32_t a, uint32_t b, uint32_t sel) {
    uint32_t r;
    asm("prmt.b32 %0, %1, %2, %3;" : "=r"(r) : "r"(a), "r"(b), "r"(sel));
    return r;
}
__device__ __forceinline__ void mma16(float* d, const uint32_t* a, const uint32_t* b) {
    asm volatile(
        "mma.sync.aligned.m16n8k16.row.col.f32.f16.f16.f32 "
        "{%0,%1,%2,%3}, {%4,%5,%6,%7}, {%8,%9}, {%0,%1,%2,%3};\n"
        : "+f"(d[0]), "+f"(d[1]), "+f"(d[2]), "+f"(d[3])
        : "r"(a[0]), "r"(a[1]), "r"(a[2]), "r"(a[3]), "r"(b[0]), "r"(b[1]));
}

// ---------------------------------------------------------------------------
// Weight split: fp32 [O][768] -> packed hi fp16x2 u32 [O][384]
// ---------------------------------------------------------------------------
__global__ void wsplit_kernel(const float* __restrict__ w,
                              uint32_t* __restrict__ wh, int n2)
{
    int i = blockIdx.x * 256 + threadIdx.x;
    if (i < n2) {
        float2 v = *(const float2*)(w + 2 * i);
        wh[i] = packh2(v.x, v.y);
    }
}

// ---------------------------------------------------------------------------
// LayerNorm, warp-per-row -> packed hi fp16x2 output (x1 QKV path)
// ---------------------------------------------------------------------------
__global__ void __launch_bounds__(256) ln_kernel(
    const float* __restrict__ x, const float* __restrict__ gamma,
    const float* __restrict__ beta, uint32_t* __restrict__ oh)
{
    int row  = blockIdx.x * 8 + (threadIdx.x >> 5);
    int lane = threadIdx.x & 31;
    const float* xr = x + (size_t)row * C_;
    float4 v[6];
    float s = 0.f, ss = 0.f;
    #pragma unroll
    for (int j = 0; j < 6; j++) {
        v[j] = *(const float4*)(xr + j * 128 + lane * 4);
        s  += v[j].x + v[j].y + v[j].z + v[j].w;
        ss += v[j].x * v[j].x + v[j].y * v[j].y + v[j].z * v[j].z + v[j].w * v[j].w;
    }
    #pragma unroll
    for (int o = 16; o > 0; o >>= 1) {
        s  += __shfl_xor_sync(0xffffffffu, s,  o);
        ss += __shfl_xor_sync(0xffffffffu, ss, o);
    }
    float mean = s * (1.0f / C_);
    float var  = ss * (1.0f / C_) - mean * mean;
    float rstd = rsqrtf(var + 1e-5f);
    uint32_t* ohr = oh + (size_t)row * C2;
    #pragma unroll
    for (int j = 0; j < 6; j++) {
        int c = j * 128 + lane * 4;
        float4 g = *(const float4*)(gamma + c);
        float4 bt = *(const float4*)(beta + c);
        float rx = (v[j].x - mean) * rstd * g.x + bt.x;
        float ry = (v[j].y - mean) * rstd * g.y + bt.y;
        float rz = (v[j].z - mean) * rstd * g.z + bt.z;
        float rw = (v[j].w - mean) * rstd * g.w + bt.w;
        int c2 = j * 64 + lane * 2;
        ohr[c2]     = packh2(rx, ry);
        ohr[c2 + 1] = packh2(rz, rw);
    }
}

// ---------------------------------------------------------------------------
// QKV GEMM, pure fp16 (x1). Block 128x128, stage = 16k, double-buffered,
// 256 thr, warp 4(m)x2(n) -> 32x64 tile, 16 mma/warp-stage.
// Stage smem u32 (2112): Ah@0, Bh@1056, kslot stride 264.
// ---------------------------------------------------------------------------
__global__ void __launch_bounds__(256, 2) gemm_q(
    const uint32_t* __restrict__ Ah, const uint32_t* __restrict__ Bh,
    uint32_t* __restrict__ Cp, int M, int N, int K2)
{
    __shared__ uint32_t smu[4224];
    int tid  = threadIdx.x;
    int lane = tid & 31, warp = tid >> 5;
    int lr = lane >> 2, lc = lane & 3;
    int wm = (warp & 3) * 32, wn = (warp >> 2) * 64;
    int m0 = blockIdx.y * 128, n0 = blockIdx.x * 128;
    int lrow = tid >> 1, comp = tid & 1;
    int sbase = lrow * 2 + comp;
    const uint32_t* ApH = Ah + (size_t)(m0 + lrow) * K2 + comp * 4;
    const uint32_t* BpH = Bh + (size_t)(n0 + lrow) * K2 + comp * 4;

    float acc[2][8][4];
    #pragma unroll
    for (int i = 0; i < 2; i++)
        #pragma unroll
        for (int j = 0; j < 8; j++)
            #pragma unroll
            for (int r = 0; r < 4; r++) acc[i][j][r] = 0.f;

    uint4 vah, vbh;
    #define QLDG(k2o) do { \
        vah = *(const uint4*)(ApH + (k2o)); \
        vbh = *(const uint4*)(BpH + (k2o)); \
    } while (0)
    #define QSTS(W) do { \
        (W)[0 * 264 + sbase] = vah.x; (W)[1 * 264 + sbase] = vah.y; \
        (W)[2 * 264 + sbase] = vah.z; (W)[3 * 264 + sbase] = vah.w; \
        (W)[1056 + 0 * 264 + sbase] = vbh.x; (W)[1056 + 1 * 264 + sbase] = vbh.y; \
        (W)[1056 + 2 * 264 + sbase] = vbh.z; (W)[1056 + 3 * 264 + sbase] = vbh.w; \
    } while (0)

    QLDG(0);
    QSTS(smu);
    __syncthreads();

    int nk = K2 / 8;
    for (int it = 0; it < nk; it++) {
        if (it + 1 < nk) QLDG((it + 1) * 8);
        const uint32_t* S = smu + (it & 1) * 2112;
        uint32_t ra[2][4], rb[8][2];
        #pragma unroll
        for (int mi = 0; mi < 2; mi++) {
            int m = wm + 16 * mi;
            uint2 h0 = *(const uint2*)&S[lc * 264 + (m + lr) * 2];
            uint2 h1 = *(const uint2*)&S[lc * 264 + (m + 8 + lr) * 2];
            ra[mi][0] = h0.x; ra[mi][1] = h1.x; ra[mi][2] = h0.y; ra[mi][3] = h1.y;
        }
        #pragma unroll
        for (int nj = 0; nj < 8; nj++) {
            int n = wn + 8 * nj;
            uint2 hb2 = *(const uint2*)&S[1056 + lc * 264 + (n + lr) * 2];
            rb[nj][0] = hb2.x; rb[nj][1] = hb2.y;
        }
        #pragma unroll
        for (int mi = 0; mi < 2; mi++)
            #pragma unroll
            for (int nj = 0; nj < 8; nj++)
                mma16(acc[mi][nj], ra[mi], rb[nj]);
        if (it + 1 < nk) {
            uint32_t* W = smu + ((it + 1) & 1) * 2112;
            QSTS(W);
        }
        __syncthreads();
    }

    int N2 = N >> 1;
    #pragma unroll
    for (int mi = 0; mi < 2; mi++)
        #pragma unroll
        for (int nj = 0; nj < 8; nj++) {
            int row = m0 + wm + mi * 16 + lr;
            int col2 = ((n0 + wn) >> 1) + 4 * nj + lc;
            Cp[(size_t)row * N2 + col2] = packh2(acc[mi][nj][0], acc[mi][nj][1]);
            Cp[(size_t)(row + 8) * N2 + col2] = packh2(acc[mi][nj][2], acc[mi][nj][3]);
        }
}

// ---------------------------------------------------------------------------
// Out-projection GEMM, x2 split (exact-A x fp16-B), block tile 64(m)x128(n)
// for wave quantization (grid 768 vs 384). 256 thr, warp 2(m)x4(n) -> 32x32.
// Stage smem u32 (2144): Ah@0 (4x136), Al@544 (4x136), Bh@1088 (4x264).
// ---------------------------------------------------------------------------
__global__ void __launch_bounds__(256, 2) gemm_o64(
    const uint32_t* __restrict__ Ah, const uint32_t* __restrict__ Al,
    const uint32_t* __restrict__ Bh,
    const float* __restrict__ bias, float* __restrict__ Cf, int N, int K2)
{
    __shared__ uint32_t smu[4288];
    int tid  = threadIdx.x;
    int lane = tid & 31, warp = tid >> 5;
    int lr = lane >> 2, lc = lane & 3;
    int wm = (warp & 1) * 32, wn = (warp >> 1) * 32;
    int m0 = blockIdx.y * 64, n0 = blockIdx.x * 128;

    // A fill task: row 0..63, asel = hi/lo, acomp = k-half
    int arow = tid >> 2, asel = (tid >> 1) & 1, acomp = tid & 1;
    const uint32_t* ApX = (asel ? Al : Ah) + (size_t)(m0 + arow) * K2 + acomp * 4;
    int abase = asel * 544 + arow * 2 + acomp;
    // B fill task: row 0..127
    int brow = tid >> 1, bcomp = tid & 1;
    const uint32_t* BpH = Bh + (size_t)(n0 + brow) * K2 + bcomp * 4;
    int bbase = 1088 + brow * 2 + bcomp;

    float acc[2][4][4];
    #pragma unroll
    for (int i = 0; i < 2; i++)
        #pragma unroll
        for (int j = 0; j < 4; j++)
            #pragma unroll
            for (int r = 0; r < 4; r++) acc[i][j][r] = 0.f;

    uint4 va, vb;
    #define OLDG(k2o) do { \
        va = *(const uint4*)(ApX + (k2o)); \
        vb = *(const uint4*)(BpH + (k2o)); \
    } while (0)
    #define OSTS(W) do { \
        (W)[0 * 136 + abase] = va.x; (W)[1 * 136 + abase] = va.y; \
        (W)[2 * 136 + abase] = va.z; (W)[3 * 136 + abase] = va.w; \
        (W)[0 * 264 + bbase] = vb.x; (W)[1 * 264 + bbase] = vb.y; \
        (W)[2 * 264 + bbase] = vb.z; (W)[3 * 264 + bbase] = vb.w; \
    } while (0)

    OLDG(0);
    OSTS(smu);
    __syncthreads();

    int nk = K2 / 8;
    for (int it = 0; it < nk; it++) {
        if (it + 1 < nk) OLDG((it + 1) * 8);
        const uint32_t* S = smu + (it & 1) * 2144;
        uint32_t ra[2][4], la[2][4], rb[4][2];
        #pragma unroll
        for (int mi = 0; mi < 2; mi++) {
            int m = wm + 16 * mi;
            uint2 h0 = *(const uint2*)&S[lc * 136 + (m + lr) * 2];
            uint2 h1 = *(const uint2*)&S[lc * 136 + (m + 8 + lr) * 2];
            uint2 l0 = *(const uint2*)&S[544 + lc * 136 + (m + lr) * 2];
            uint2 l1 = *(const uint2*)&S[544 + lc * 136 + (m + 8 + lr) * 2];
            ra[mi][0] = h0.x; ra[mi][1] = h1.x; ra[mi][2] = h0.y; ra[mi][3] = h1.y;
            la[mi][0] = l0.x; la[mi][1] = l1.x; la[mi][2] = l0.y; la[mi][3] = l1.y;
        }
        #pragma unroll
        for (int nj = 0; nj < 4; nj++) {
            int n = wn + 8 * nj;
            uint2 hb2 = *(const uint2*)&S[1088 + lc * 264 + (n + lr) * 2];
            rb[nj][0] = hb2.x; rb[nj][1] = hb2.y;
        }
        #pragma unroll
        for (int mi = 0; mi < 2; mi++)
            #pragma unroll
            for (int nj = 0; nj < 4; nj++) {
                mma16(acc[mi][nj], ra[mi], rb[nj]);
                mma16(acc[mi][nj], la[mi], rb[nj]);
            }
        if (it + 1 < nk) {
            uint32_t* W = smu + ((it + 1) & 1) * 2144;
            OSTS(W);
        }
        __syncthreads();
    }

    #pragma unroll
    for (int mi = 0; mi < 2; mi++)
        #pragma unroll
        for (int nj = 0; nj < 4; nj++) {
            int row = m0 + wm + mi * 16 + lr;
            int col = n0 + wn + nj * 8 + 2 * lc;
            float bb0 = bias[col], bb1 = bias[col + 1];
            *(float2*)(Cf + (size_t)row * N + col) =
                make_float2(acc[mi][nj][0] + bb0, acc[mi][nj][1] + bb1);
            *(float2*)(Cf + (size_t)(row + 8) * N + col) =
                make_float2(acc[mi][nj][2] + bb0, acc[mi][nj][3] + bb1);
        }
}

// ---------------------------------------------------------------------------
// Flash attention — unchanged from R11 (validated).
// 128 threads (4 warps), q-tile 128, 32 q-rows per warp (2 m-tiles per K/V
// fragment load). Double-buffered K/V (stage 4352 u32). P register-resident.
// ---------------------------------------------------------------------------
__global__ void __launch_bounds__(128, 2) attn_p(
    const uint32_t* __restrict__ qh,
    uint32_t* __restrict__ oh, uint32_t* __restrict__ ol)
{
    __shared__ uint32_t smu[8704];   // 2 stages x 4352

    int tid  = threadIdx.x;
    int lane = tid & 31, warp = tid >> 5;
    int lr = lane >> 2, lc = lane & 3;
    int qt = (gridDim.x - 1) - blockIdx.x;
    int bh = blockIdx.y;
    int b = bh / H_, h = bh % H_;
    int r0 = qt * 128;
    int q0w = warp * 32;
    const uint32_t* base = qh + (size_t)b * T_ * QKV32 + h * 32;
    const float QSC = 0.125f * 1.4426950408889634f;

    int kss = tid >> 1, kd2b = (tid & 1) * 16;
    int vrp = tid >> 2, vcb2 = (tid & 3) * 8;
    int vslot = 2176 + ((vrp >> 3) * 4 + (vrp & 3)) * 136 + ((vrp & 7) >> 2);

    uint32_t qf[2][4][4];
    #pragma unroll
    for (int mt = 0; mt < 2; mt++) {
        const uint32_t* q0 = base + (size_t)(r0 + q0w + mt * 16 + lr) * QKV32;
        const uint32_t* q1 = q0 + 8 * QKV32;
        #pragma unroll
        for (int ks = 0; ks < 4; ks++) {
            qf[mt][ks][0] = q0[8 * ks + lc];
            qf[mt][ks][1] = q1[8 * ks + lc];
            qf[mt][ks][2] = q0[8 * ks + 4 + lc];
            qf[mt][ks][3] = q1[8 * ks + 4 + lc];
        }
    }

    float o[2][8][4];
    #pragma unroll
    for (int mt = 0; mt < 2; mt++)
        #pragma unroll
        for (int nj = 0; nj < 8; nj++)
            #pragma unroll
            for (int r = 0; r < 4; r++) o[mt][nj][r] = 0.f;
    float mr[2][2] = {{-INFINITY, -INFINITY}, {-INFINITY, -INFINITY}};
    float lv[2][2] = {{0.f, 0.f}, {0.f, 0.f}};

    int nkt = ((qt >> 1) + 1) << 2;

    #define AFILL(dst, ktile) do { \
        const uint32_t* kp = base + 384 + (size_t)((ktile) * 64 + kss) * QKV32 + kd2b; \
        uint4 kq0 = *(const uint4*)kp;        uint4 kq1 = *(const uint4*)(kp + 4); \
        uint4 kq2 = *(const uint4*)(kp + 8);  uint4 kq3 = *(const uint4*)(kp + 12); \
        uint32_t kv[16] = {kq0.x, kq0.y, kq0.z, kq0.w, kq1.x, kq1.y, kq1.z, kq1.w, \
                           kq2.x, kq2.y, kq2.z, kq2.w, kq3.x, kq3.y, kq3.z, kq3.w}; \
        _Pragma("unroll") \
        for (int j = 0; j < 16; j++) { \
            int k2 = kd2b + j; \
            (dst)[((k2 >> 3) * 4 + (k2 & 3)) * 136 + kss * 2 + ((k2 & 7) >> 2)] = kv[j]; \
        } \
        const uint32_t* vp = base + 768 + (size_t)((ktile) * 64 + 2 * vrp) * QKV32 + vcb2; \
        uint4 va0 = *(const uint4*)vp;            uint4 va1 = *(const uint4*)(vp + 4); \
        uint4 vb0 = *(const uint4*)(vp + QKV32);  uint4 vb1 = *(const uint4*)(vp + QKV32 + 4); \
        uint32_t a0[8] = {va0.x, va0.y, va0.z, va0.w, va1.x, va1.y, va1.z, va1.w}; \
        uint32_t a1[8] = {vb0.x, vb0.y, vb0.z, vb0.w, vb1.x, vb1.y, vb1.z, vb1.w}; \
        _Pragma("unroll") \
        for (int i = 0; i < 8; i++) { \
            int d0 = 2 * (vcb2 + i); \
            (dst)[vslot + d0 * 2]       = prmt(a0[i], a1[i], 0x5410u); \
            (dst)[vslot + (d0 + 1) * 2] = prmt(a0[i], a1[i], 0x7632u); \
        } \
    } while (0)

    AFILL(smu, 0);
    __syncthreads();

    for (int kt = 0; kt < nkt; kt++) {
        const uint32_t* cur = smu + (kt & 1) * 4352;
        uint32_t* nxt = smu + ((kt + 1) & 1) * 4352;
        bool more = (kt + 1 < nkt);

        float s[2][8][4];
        #pragma unroll
        for (int mt = 0; mt < 2; mt++)
            #pragma unroll
            for (int nj = 0; nj < 8; nj++)
                #pragma unroll
                for (int r = 0; r < 4; r++) s[mt][nj][r] = 0.f;
        #pragma unroll
        for (int ks = 0; ks < 4; ks++)
            #pragma unroll
            for (int nj = 0; nj < 8; nj++) {
                uint2 kb = *(const uint2*)&cur[(ks * 4 + lc) * 136 + (8 * nj + lr) * 2];
                uint32_t bb[2] = {kb.x, kb.y};
                mma16(s[0][nj], qf[0][ks], bb);
                mma16(s[1][nj], qf[1][ks], bb);
            }

        float al[2][2];
        uint32_t pa[2][4][4];
        #pragma unroll
        for (int mt = 0; mt < 2; mt++) {
            float mx0 = -INFINITY, mx1 = -INFINITY;
            #pragma unroll
            for (int nj = 0; nj < 8; nj++) {
                mx0 = fmaxf(mx0, fmaxf(s[mt][nj][0], s[mt][nj][1]));
                mx1 = fmaxf(mx1, fmaxf(s[mt][nj][2], s[mt][nj][3]));
            }
            mx0 = fmaxf(mx0, __shfl_xor_sync(0xffffffffu, mx0, 1));
            mx0 = fmaxf(mx0, __shfl_xor_sync(0xffffffffu, mx0, 2));
            mx1 = fmaxf(mx1, __shfl_xor_sync(0xffffffffu, mx1, 1));
            mx1 = fmaxf(mx1, __shfl_xor_sync(0xffffffffu, mx1, 2));
            float nm0 = fmaxf(mr[mt][0], mx0 * QSC);
            float nm1 = fmaxf(mr[mt][1], mx1 * QSC);
            al[mt][0] = ex2(mr[mt][0] - nm0);
            al[mt][1] = ex2(mr[mt][1] - nm1);
            mr[mt][0] = nm0; mr[mt][1] = nm1;
            float sum0 = 0.f, sum1 = 0.f;
            #pragma unroll
            for (int ks = 0; ks < 4; ks++) {
                #pragma unroll
                for (int half = 0; half < 2; half++) {
                    int nj = 2 * ks + half;
                    float p0 = ex2(fmaf(s[mt][nj][0], QSC, -nm0));
                    float p1 = ex2(fmaf(s[mt][nj][1], QSC, -nm0));
                    float p2 = ex2(fmaf(s[mt][nj][2], QSC, -nm1));
                    float p3 = ex2(fmaf(s[mt][nj][3], QSC, -nm1));
                    sum0 += p0 + p1; sum1 += p2 + p3;
                    pa[mt][ks][2 * half]     = packh2(p0, p1);
                    pa[mt][ks][2 * half + 1] = packh2(p2, p3);
                }
            }
            sum0 += __shfl_xor_sync(0xffffffffu, sum0, 1);
            sum0 += __shfl_xor_sync(0xffffffffu, sum0, 2);
            sum1 += __shfl_xor_sync(0xffffffffu, sum1, 1);
            sum1 += __shfl_xor_sync(0xffffffffu, sum1, 2);
            lv[mt][0] = lv[mt][0] * al[mt][0] + sum0;
            lv[mt][1] = lv[mt][1] * al[mt][1] + sum1;
        }
        if (__any_sync(0xffffffffu,
                       (al[0][0] != 1.0f) | (al[0][1] != 1.0f) |
                       (al[1][0] != 1.0f) | (al[1][1] != 1.0f))) {
            #pragma unroll
            for (int mt = 0; mt < 2; mt++)
                #pragma unroll
                for (int nj = 0; nj < 8; nj++) {
                    o[mt][nj][0] *= al[mt][0]; o[mt][nj][1] *= al[mt][0];
                    o[mt][nj][2] *= al[mt][1]; o[mt][nj][3] *= al[mt][1];
                }
        }

        #pragma unroll
        for (int ks = 0; ks < 4; ks++)
            #pragma unroll
            for (int nj = 0; nj < 8; nj++) {
                uint2 vb = *(const uint2*)&cur[2176 + (ks * 4 + lc) * 136 + (8 * nj + lr) * 2];
                uint32_t bb[2] = {vb.x, vb.y};
                mma16(o[0][nj], pa[0][ks], bb);
                mma16(o[1][nj], pa[1][ks], bb);
            }

        if (more) {
            AFILL(nxt, kt + 1);
            __syncthreads();
        }
    }

    #pragma unroll
    for (int mt = 0; mt < 2; mt++) {
        float inv0 = 1.0f / lv[mt][0], inv1 = 1.0f / lv[mt][1];
        int row = r0 + q0w + mt * 16 + lr;
        size_t off0 = ((size_t)(b * T_ + row)) * C2 + h * 32;
        size_t off1 = off0 + 8 * C2;
        #pragma unroll
        for (int nj = 0; nj < 8; nj++) {
            int d2 = 4 * nj + lc;
            float v00 = o[mt][nj][0] * inv0, v01 = o[mt][nj][1] * inv0;
            float v10 = o[mt][nj][2] * inv1, v11 = o[mt][nj][3] * inv1;
            oh[off0 + d2] = packh2(v00, v01);
            ol[off0 + d2] = packh2(v00 - h16(v00), v01 - h16(v01));
            oh[off1 + d2] = packh2(v10, v11);
            ol[off1 + d2] = packh2(v10 - h16(v10), v11 - h16(v11));
        }
    }
}

// ---------------------------------------------------------------------------
extern "C" void kernel_launch(void* const* d_in, const int* in_sizes, int n_in,
                              void* d_out, int out_size)
{
    const float* x     = (const float*)d_in[0];
    const float* gamma = (const float*)d_in[1];
    const float* beta  = (const float*)d_in[2];
    const float* w_qkv = (const float*)d_in[3];
    const float* w_out = (const float*)d_in[4];
    const float* b_out = (const float*)d_in[5];
    float* out = (float*)d_out;

    uint32_t *xh, *qh, *ah, *al, *wqh, *woh;
    cudaGetSymbolAddress((void**)&xh,  g_xh);
    cudaGetSymbolAddress((void**)&qh,  g_qh);
    cudaGetSymbolAddress((void**)&ah,  g_ah);
    cudaGetSymbolAddress((void**)&al,  g_al);
    cudaGetSymbolAddress((void**)&wqh, g_wqh);
    cudaGetSymbolAddress((void**)&woh, g_woh);

    // 0) weight pre-split (hi only)
    wsplit_kernel<<<(QKV3 * C2 + 255) / 256, 256>>>(w_qkv, wqh, QKV3 * C2);
    wsplit_kernel<<<(C_ * C2 + 255) / 256, 256>>>(w_out, woh, C_ * C2);

    // 1) LayerNorm -> packed fp16 (hi)
    ln_kernel<<<NTOK / 8, 256>>>(x, gamma, beta, xh);

    // 2) QKV projection, pure fp16 -> packed fp16
    gemm_q<<<dim3(QKV3 / 128, NTOK / 128), 256>>>(
        xh, wqh, qh, NTOK, QKV3, C2);

    // 3) Flash attention -> packed (hi, lo)
    attn_p<<<dim3(T_ / 128, B_ * H_), 128>>>(qh, ah, al);

    // 4) Output projection + bias -> fp32; x2 split, 64x128 tiles
    gemm_o64<<<dim3(C_ / 128, NTOK / 64), 256>>>(
        ah, al, woh, b_out, out, C_, C2);
}

// round 13
// speedup vs baseline: 4.3127x; 1.0600x over previous
#include <cuda_runtime.h>
#include <cuda_fp16.h>
#include <math.h>
#include <stdint.h>

#define B_    2
#define T_    4096
#define C_    768
#define H_    12
#define D_    64
#define QKV3  2304
#define NTOK  (B_ * T_)
#define C2    384      // C_/2  (u32-packed pairs)
#define QKV32 1152     // QKV3/2

// Packed fp16x2 scratch (allocation-free __device__ globals)
__device__ uint32_t g_xh[(size_t)NTOK * C2];
__device__ uint32_t g_qh[(size_t)NTOK * QKV32];   // qkv, fp16
__device__ uint32_t g_ah[(size_t)NTOK * C2];
__device__ uint32_t g_al[(size_t)NTOK * C2];
__device__ uint32_t g_wqh[(size_t)QKV3 * C2];
__device__ uint32_t g_woh[(size_t)C_ * C2];

__device__ __forceinline__ uint32_t packh2(float lo, float hi) {
    uint32_t r;
    asm("cvt.rn.f16x2.f32 %0, %1, %2;" : "=r"(r) : "f"(hi), "f"(lo));
    return r;
}
__device__ __forceinline__ float h16(float v) {
    return __half2float(__float2half_rn(v));
}
__device__ __forceinline__ float ex2(float x) {
    float y;
    asm("ex2.approx.f32 %0, %1;" : "=f"(y) : "f"(x));
    return y;
}
__device__ __forceinline__ uint32_t prmt(uint32_t a, uint32_t b, uint32_t sel) {
    uint32_t r;
    asm("prmt.b32 %0, %1, %2, %3;" : "=r"(r) : "r"(a), "r"(b), "r"(sel));
    return r;
}
__device__ __forceinline__ void mma16(float* d, const uint32_t* a, const uint32_t* b) {
    asm volatile(
        "mma.sync.aligned.m16n8k16.row.col.f32.f16.f16.f32 "
        "{%0,%1,%2,%3}, {%4,%5,%6,%7}, {%8,%9}, {%0,%1,%2,%3};\n"
        : "+f"(d[0]), "+f"(d[1]), "+f"(d[2]), "+f"(d[3])
        : "r"(a[0]), "r"(a[1]), "r"(a[2]), "r"(a[3]), "r"(b[0]), "r"(b[1]));
}

// ---------------------------------------------------------------------------
// Weight split: fp32 [O][768] -> packed hi fp16x2 u32 [O][384]
// ---------------------------------------------------------------------------
__global__ void wsplit_kernel(const float* __restrict__ w,
                              uint32_t* __restrict__ wh, int n2)
{
    int i = blockIdx.x * 256 + threadIdx.x;
    if (i < n2) {
        float2 v = *(const float2*)(w + 2 * i);
        wh[i] = packh2(v.x, v.y);
    }
}

// ---------------------------------------------------------------------------
// LayerNorm, warp-per-row -> packed hi fp16x2 output (x1 QKV path)
// ---------------------------------------------------------------------------
__global__ void __launch_bounds__(256) ln_kernel(
    const float* __restrict__ x, const float* __restrict__ gamma,
    const float* __restrict__ beta, uint32_t* __restrict__ oh)
{
    int row  = blockIdx.x * 8 + (threadIdx.x >> 5);
    int lane = threadIdx.x & 31;
    const float* xr = x + (size_t)row * C_;
    float4 v[6];
    float s = 0.f, ss = 0.f;
    #pragma unroll
    for (int j = 0; j < 6; j++) {
        v[j] = *(const float4*)(xr + j * 128 + lane * 4);
        s  += v[j].x + v[j].y + v[j].z + v[j].w;
        ss += v[j].x * v[j].x + v[j].y * v[j].y + v[j].z * v[j].z + v[j].w * v[j].w;
    }
    #pragma unroll
    for (int o = 16; o > 0; o >>= 1) {
        s  += __shfl_xor_sync(0xffffffffu, s,  o);
        ss += __shfl_xor_sync(0xffffffffu, ss, o);
    }
    float mean = s * (1.0f / C_);
    float var  = ss * (1.0f / C_) - mean * mean;
    float rstd = rsqrtf(var + 1e-5f);
    uint32_t* ohr = oh + (size_t)row * C2;
    #pragma unroll
    for (int j = 0; j < 6; j++) {
        int c = j * 128 + lane * 4;
        float4 g = *(const float4*)(gamma + c);
        float4 bt = *(const float4*)(beta + c);
        float rx = (v[j].x - mean) * rstd * g.x + bt.x;
        float ry = (v[j].y - mean) * rstd * g.y + bt.y;
        float rz = (v[j].z - mean) * rstd * g.z + bt.z;
        float rw = (v[j].w - mean) * rstd * g.w + bt.w;
        int c2 = j * 64 + lane * 2;
        ohr[c2]     = packh2(rx, ry);
        ohr[c2 + 1] = packh2(rz, rw);
    }
}

// ---------------------------------------------------------------------------
// QKV GEMM, pure fp16 (x1). Block 128x128, stage = 16k, double-buffered,
// 256 thr, warp 4(m)x2(n) -> 32x64 tile, 16 mma/warp-stage.
// Stage smem u32 (2112): Ah@0, Bh@1056, kslot stride 264.  (R12, measured 150us)
// ---------------------------------------------------------------------------
__global__ void __launch_bounds__(256, 2) gemm_q(
    const uint32_t* __restrict__ Ah, const uint32_t* __restrict__ Bh,
    uint32_t* __restrict__ Cp, int M, int N, int K2)
{
    __shared__ uint32_t smu[4224];
    int tid  = threadIdx.x;
    int lane = tid & 31, warp = tid >> 5;
    int lr = lane >> 2, lc = lane & 3;
    int wm = (warp & 3) * 32, wn = (warp >> 2) * 64;
    int m0 = blockIdx.y * 128, n0 = blockIdx.x * 128;
    int lrow = tid >> 1, comp = tid & 1;
    int sbase = lrow * 2 + comp;
    const uint32_t* ApH = Ah + (size_t)(m0 + lrow) * K2 + comp * 4;
    const uint32_t* BpH = Bh + (size_t)(n0 + lrow) * K2 + comp * 4;

    float acc[2][8][4];
    #pragma unroll
    for (int i = 0; i < 2; i++)
        #pragma unroll
        for (int j = 0; j < 8; j++)
            #pragma unroll
            for (int r = 0; r < 4; r++) acc[i][j][r] = 0.f;

    uint4 vah, vbh;
    #define QLDG(k2o) do { \
        vah = *(const uint4*)(ApH + (k2o)); \
        vbh = *(const uint4*)(BpH + (k2o)); \
    } while (0)
    #define QSTS(W) do { \
        (W)[0 * 264 + sbase] = vah.x; (W)[1 * 264 + sbase] = vah.y; \
        (W)[2 * 264 + sbase] = vah.z; (W)[3 * 264 + sbase] = vah.w; \
        (W)[1056 + 0 * 264 + sbase] = vbh.x; (W)[1056 + 1 * 264 + sbase] = vbh.y; \
        (W)[1056 + 2 * 264 + sbase] = vbh.z; (W)[1056 + 3 * 264 + sbase] = vbh.w; \
    } while (0)

    QLDG(0);
    QSTS(smu);
    __syncthreads();

    int nk = K2 / 8;
    for (int it = 0; it < nk; it++) {
        if (it + 1 < nk) QLDG((it + 1) * 8);
        const uint32_t* S = smu + (it & 1) * 2112;
        uint32_t ra[2][4], rb[8][2];
        #pragma unroll
        for (int mi = 0; mi < 2; mi++) {
            int m = wm + 16 * mi;
            uint2 h0 = *(const uint2*)&S[lc * 264 + (m + lr) * 2];
            uint2 h1 = *(const uint2*)&S[lc * 264 + (m + 8 + lr) * 2];
            ra[mi][0] = h0.x; ra[mi][1] = h1.x; ra[mi][2] = h0.y; ra[mi][3] = h1.y;
        }
        #pragma unroll
        for (int nj = 0; nj < 8; nj++) {
            int n = wn + 8 * nj;
            uint2 hb2 = *(const uint2*)&S[1056 + lc * 264 + (n + lr) * 2];
            rb[nj][0] = hb2.x; rb[nj][1] = hb2.y;
        }
        #pragma unroll
        for (int mi = 0; mi < 2; mi++)
            #pragma unroll
            for (int nj = 0; nj < 8; nj++)
                mma16(acc[mi][nj], ra[mi], rb[nj]);
        if (it + 1 < nk) {
            uint32_t* W = smu + ((it + 1) & 1) * 2112;
            QSTS(W);
        }
        __syncthreads();
    }

    int N2 = N >> 1;
    #pragma unroll
    for (int mi = 0; mi < 2; mi++)
        #pragma unroll
        for (int nj = 0; nj < 8; nj++) {
            int row = m0 + wm + mi * 16 + lr;
            int col2 = ((n0 + wn) >> 1) + 4 * nj + lc;
            Cp[(size_t)row * N2 + col2] = packh2(acc[mi][nj][0], acc[mi][nj][1]);
            Cp[(size_t)(row + 8) * N2 + col2] = packh2(acc[mi][nj][2], acc[mi][nj][3]);
        }
}

// ---------------------------------------------------------------------------
// Out-projection GEMM (R11 form, measured ~95us): x2 split (exact-A x fp16-B),
// block 128x128, stage = 16k double-buffered, warp 4(m)x2(n) -> 32x64.
// Stage smem u32 (3168): Ah@0 Al@1056 Bh@2112, kslot stride 264.
// ---------------------------------------------------------------------------
__global__ void __launch_bounds__(256, 2) gemm_o(
    const uint32_t* __restrict__ Ah, const uint32_t* __restrict__ Al,
    const uint32_t* __restrict__ Bh,
    const float* __restrict__ bias, float* __restrict__ Cf, int M, int N, int K2)
{
    __shared__ uint32_t smu[6336];
    int tid  = threadIdx.x;
    int lane = tid & 31, warp = tid >> 5;
    int lr = lane >> 2, lc = lane & 3;
    int wm = (warp & 3) * 32, wn = (warp >> 2) * 64;
    int m0 = blockIdx.y * 128, n0 = blockIdx.x * 128;
    int lrow = tid >> 1, comp = tid & 1;
    int sbase = lrow * 2 + comp;
    const uint32_t* ApH = Ah + (size_t)(m0 + lrow) * K2 + comp * 4;
    const uint32_t* ApL = Al + (size_t)(m0 + lrow) * K2 + comp * 4;
    const uint32_t* BpH = Bh + (size_t)(n0 + lrow) * K2 + comp * 4;

    float acc[2][8][4];
    #pragma unroll
    for (int i = 0; i < 2; i++)
        #pragma unroll
        for (int j = 0; j < 8; j++)
            #pragma unroll
            for (int r = 0; r < 4; r++) acc[i][j][r] = 0.f;

    uint4 vah, val, vbh;
    #define OLDG(k2o) do { \
        vah = *(const uint4*)(ApH + (k2o)); val = *(const uint4*)(ApL + (k2o)); \
        vbh = *(const uint4*)(BpH + (k2o)); \
    } while (0)
    #define OSTS(W) do { \
        (W)[0 * 264 + sbase] = vah.x; (W)[1 * 264 + sbase] = vah.y; \
        (W)[2 * 264 + sbase] = vah.z; (W)[3 * 264 + sbase] = vah.w; \
        (W)[1056 + 0 * 264 + sbase] = val.x; (W)[1056 + 1 * 264 + sbase] = val.y; \
        (W)[1056 + 2 * 264 + sbase] = val.z; (W)[1056 + 3 * 264 + sbase] = val.w; \
        (W)[2112 + 0 * 264 + sbase] = vbh.x; (W)[2112 + 1 * 264 + sbase] = vbh.y; \
        (W)[2112 + 2 * 264 + sbase] = vbh.z; (W)[2112 + 3 * 264 + sbase] = vbh.w; \
    } while (0)

    OLDG(0);
    OSTS(smu);
    __syncthreads();

    int nk = K2 / 8;
    for (int it = 0; it < nk; it++) {
        if (it + 1 < nk) OLDG((it + 1) * 8);
        const uint32_t* S = smu + (it & 1) * 3168;
        uint32_t ra[2][4], la[2][4], rb[8][2];
        #pragma unroll
        for (int mi = 0; mi < 2; mi++) {
            int m = wm + 16 * mi;
            uint2 h0 = *(const uint2*)&S[lc * 264 + (m + lr) * 2];
            uint2 h1 = *(const uint2*)&S[lc * 264 + (m + 8 + lr) * 2];
            uint2 l0 = *(const uint2*)&S[1056 + lc * 264 + (m + lr) * 2];
            uint2 l1 = *(const uint2*)&S[1056 + lc * 264 + (m + 8 + lr) * 2];
            ra[mi][0] = h0.x; ra[mi][1] = h1.x; ra[mi][2] = h0.y; ra[mi][3] = h1.y;
            la[mi][0] = l0.x; la[mi][1] = l1.x; la[mi][2] = l0.y; la[mi][3] = l1.y;
        }
        #pragma unroll
        for (int nj = 0; nj < 8; nj++) {
            int n = wn + 8 * nj;
            uint2 hb2 = *(const uint2*)&S[2112 + lc * 264 + (n + lr) * 2];
            rb[nj][0] = hb2.x; rb[nj][1] = hb2.y;
        }
        #pragma unroll
        for (int mi = 0; mi < 2; mi++)
            #pragma unroll
            for (int nj = 0; nj < 8; nj++) {
                mma16(acc[mi][nj], ra[mi], rb[nj]);
                mma16(acc[mi][nj], la[mi], rb[nj]);
            }
        if (it + 1 < nk) {
            uint32_t* W = smu + ((it + 1) & 1) * 3168;
            OSTS(W);
        }
        __syncthreads();
    }

    #pragma unroll
    for (int mi = 0; mi < 2; mi++)
        #pragma unroll
        for (int nj = 0; nj < 8; nj++) {
            int row = m0 + wm + mi * 16 + lr;
            int col = n0 + wn + nj * 8 + 2 * lc;
            float bb0 = bias[col], bb1 = bias[col + 1];
            *(float2*)(Cf + (size_t)row * N + col) =
                make_float2(acc[mi][nj][0] + bb0, acc[mi][nj][1] + bb1);
            *(float2*)(Cf + (size_t)(row + 8) * N + col) =
                make_float2(acc[mi][nj][2] + bb0, acc[mi][nj][3] + bb1);
        }
}

// ---------------------------------------------------------------------------
// Flash attention — unchanged from R11/R12 (validated).
// 128 threads (4 warps), q-tile 128, 32 q-rows per warp (2 m-tiles per K/V
// fragment load). Double-buffered K/V (stage 4352 u32). P register-resident.
// ---------------------------------------------------------------------------
__global__ void __launch_bounds__(128, 2) attn_p(
    const uint32_t* __restrict__ qh,
    uint32_t* __restrict__ oh, uint32_t* __restrict__ ol)
{
    __shared__ uint32_t smu[8704];   // 2 stages x 4352

    int tid  = threadIdx.x;
    int lane = tid & 31, warp = tid >> 5;
    int lr = lane >> 2, lc = lane & 3;
    int qt = (gridDim.x - 1) - blockIdx.x;
    int bh = blockIdx.y;
    int b = bh / H_, h = bh % H_;
    int r0 = qt * 128;
    int q0w = warp * 32;
    const uint32_t* base = qh + (size_t)b * T_ * QKV32 + h * 32;
    const float QSC = 0.125f * 1.4426950408889634f;

    int kss = tid >> 1, kd2b = (tid & 1) * 16;
    int vrp = tid >> 2, vcb2 = (tid & 3) * 8;
    int vslot = 2176 + ((vrp >> 3) * 4 + (vrp & 3)) * 136 + ((vrp & 7) >> 2);

    uint32_t qf[2][4][4];
    #pragma unroll
    for (int mt = 0; mt < 2; mt++) {
        const uint32_t* q0 = base + (size_t)(r0 + q0w + mt * 16 + lr) * QKV32;
        const uint32_t* q1 = q0 + 8 * QKV32;
        #pragma unroll
        for (int ks = 0; ks < 4; ks++) {
            qf[mt][ks][0] = q0[8 * ks + lc];
            qf[mt][ks][1] = q1[8 * ks + lc];
            qf[mt][ks][2] = q0[8 * ks + 4 + lc];
            qf[mt][ks][3] = q1[8 * ks + 4 + lc];
        }
    }

    float o[2][8][4];
    #pragma unroll
    for (int mt = 0; mt < 2; mt++)
        #pragma unroll
        for (int nj = 0; nj < 8; nj++)
            #pragma unroll
            for (int r = 0; r < 4; r++) o[mt][nj][r] = 0.f;
    float mr[2][2] = {{-INFINITY, -INFINITY}, {-INFINITY, -INFINITY}};
    float lv[2][2] = {{0.f, 0.f}, {0.f, 0.f}};

    int nkt = ((qt >> 1) + 1) << 2;

    #define AFILL(dst, ktile) do { \
        const uint32_t* kp = base + 384 + (size_t)((ktile) * 64 + kss) * QKV32 + kd2b; \
        uint4 kq0 = *(const uint4*)kp;        uint4 kq1 = *(const uint4*)(kp + 4); \
        uint4 kq2 = *(const uint4*)(kp + 8);  uint4 kq3 = *(const uint4*)(kp + 12); \
        uint32_t kv[16] = {kq0.x, kq0.y, kq0.z, kq0.w, kq1.x, kq1.y, kq1.z, kq1.w, \
                           kq2.x, kq2.y, kq2.z, kq2.w, kq3.x, kq3.y, kq3.z, kq3.w}; \
        _Pragma("unroll") \
        for (int j = 0; j < 16; j++) { \
            int k2 = kd2b + j; \
            (dst)[((k2 >> 3) * 4 + (k2 & 3)) * 136 + kss * 2 + ((k2 & 7) >> 2)] = kv[j]; \
        } \
        const uint32_t* vp = base + 768 + (size_t)((ktile) * 64 + 2 * vrp) * QKV32 + vcb2; \
        uint4 va0 = *(const uint4*)vp;            uint4 va1 = *(const uint4*)(vp + 4); \
        uint4 vb0 = *(const uint4*)(vp + QKV32);  uint4 vb1 = *(const uint4*)(vp + QKV32 + 4); \
        uint32_t a0[8] = {va0.x, va0.y, va0.z, va0.w, va1.x, va1.y, va1.z, va1.w}; \
        uint32_t a1[8] = {vb0.x, vb0.y, vb0.z, vb0.w, vb1.x, vb1.y, vb1.z, vb1.w}; \
        _Pragma("unroll") \
        for (int i = 0; i < 8; i++) { \
            int d0 = 2 * (vcb2 + i); \
            (dst)[vslot + d0 * 2]       = prmt(a0[i], a1[i], 0x5410u); \
            (dst)[vslot + (d0 + 1) * 2] = prmt(a0[i], a1[i], 0x7632u); \
        } \
    } while (0)

    AFILL(smu, 0);
    __syncthreads();

    for (int kt = 0; kt < nkt; kt++) {
        const uint32_t* cur = smu + (kt & 1) * 4352;
        uint32_t* nxt = smu + ((kt + 1) & 1) * 4352;
        bool more = (kt + 1 < nkt);

        float s[2][8][4];
        #pragma unroll
        for (int mt = 0; mt < 2; mt++)
            #pragma unroll
            for (int nj = 0; nj < 8; nj++)
                #pragma unroll
                for (int r = 0; r < 4; r++) s[mt][nj][r] = 0.f;
        #pragma unroll
        for (int ks = 0; ks < 4; ks++)
            #pragma unroll
            for (int nj = 0; nj < 8; nj++) {
                uint2 kb = *(const uint2*)&cur[(ks * 4 + lc) * 136 + (8 * nj + lr) * 2];
                uint32_t bb[2] = {kb.x, kb.y};
                mma16(s[0][nj], qf[0][ks], bb);
                mma16(s[1][nj], qf[1][ks], bb);
            }

        float al[2][2];
        uint32_t pa[2][4][4];
        #pragma unroll
        for (int mt = 0; mt < 2; mt++) {
            float mx0 = -INFINITY, mx1 = -INFINITY;
            #pragma unroll
            for (int nj = 0; nj < 8; nj++) {
                mx0 = fmaxf(mx0, fmaxf(s[mt][nj][0], s[mt][nj][1]));
                mx1 = fmaxf(mx1, fmaxf(s[mt][nj][2], s[mt][nj][3]));
            }
            mx0 = fmaxf(mx0, __shfl_xor_sync(0xffffffffu, mx0, 1));
            mx0 = fmaxf(mx0, __shfl_xor_sync(0xffffffffu, mx0, 2));
            mx1 = fmaxf(mx1, __shfl_xor_sync(0xffffffffu, mx1, 1));
            mx1 = fmaxf(mx1, __shfl_xor_sync(0xffffffffu, mx1, 2));
            float nm0 = fmaxf(mr[mt][0], mx0 * QSC);
            float nm1 = fmaxf(mr[mt][1], mx1 * QSC);
            al[mt][0] = ex2(mr[mt][0] - nm0);
            al[mt][1] = ex2(mr[mt][1] - nm1);
            mr[mt][0] = nm0; mr[mt][1] = nm1;
            float sum0 = 0.f, sum1 = 0.f;
            #pragma unroll
            for (int ks = 0; ks < 4; ks++) {
                #pragma unroll
                for (int half = 0; half < 2; half++) {
                    int nj = 2 * ks + half;
                    float p0 = ex2(fmaf(s[mt][nj][0], QSC, -nm0));
                    float p1 = ex2(fmaf(s[mt][nj][1], QSC, -nm0));
                    float p2 = ex2(fmaf(s[mt][nj][2], QSC, -nm1));
                    float p3 = ex2(fmaf(s[mt][nj][3], QSC, -nm1));
                    sum0 += p0 + p1; sum1 += p2 + p3;
                    pa[mt][ks][2 * half]     = packh2(p0, p1);
                    pa[mt][ks][2 * half + 1] = packh2(p2, p3);
                }
            }
            sum0 += __shfl_xor_sync(0xffffffffu, sum0, 1);
            sum0 += __shfl_xor_sync(0xffffffffu, sum0, 2);
            sum1 += __shfl_xor_sync(0xffffffffu, sum1, 1);
            sum1 += __shfl_xor_sync(0xffffffffu, sum1, 2);
            lv[mt][0] = lv[mt][0] * al[mt][0] + sum0;
            lv[mt][1] = lv[mt][1] * al[mt][1] + sum1;
        }
        if (__any_sync(0xffffffffu,
                       (al[0][0] != 1.0f) | (al[0][1] != 1.0f) |
                       (al[1][0] != 1.0f) | (al[1][1] != 1.0f))) {
            #pragma unroll
            for (int mt = 0; mt < 2; mt++)
                #pragma unroll
                for (int nj = 0; nj < 8; nj++) {
                    o[mt][nj][0] *= al[mt][0]; o[mt][nj][1] *= al[mt][0];
                    o[mt][nj][2] *= al[mt][1]; o[mt][nj][3] *= al[mt][1];
                }
        }

        #pragma unroll
        for (int ks = 0; ks < 4; ks++)
            #pragma unroll
            for (int nj = 0; nj < 8; nj++) {
                uint2 vb = *(const uint2*)&cur[2176 + (ks * 4 + lc) * 136 + (8 * nj + lr) * 2];
                uint32_t bb[2] = {vb.x, vb.y};
                mma16(o[0][nj], pa[0][ks], bb);
                mma16(o[1][nj], pa[1][ks], bb);
            }

        if (more) {
            AFILL(nxt, kt + 1);
            __syncthreads();
        }
    }

    #pragma unroll
    for (int mt = 0; mt < 2; mt++) {
        float inv0 = 1.0f / lv[mt][0], inv1 = 1.0f / lv[mt][1];
        int row = r0 + q0w + mt * 16 + lr;
        size_t off0 = ((size_t)(b * T_ + row)) * C2 + h * 32;
        size_t off1 = off0 + 8 * C2;
        #pragma unroll
        for (int nj = 0; nj < 8; nj++) {
            int d2 = 4 * nj + lc;
            float v00 = o[mt][nj][0] * inv0, v01 = o[mt][nj][1] * inv0;
            float v10 = o[mt][nj][2] * inv1, v11 = o[mt][nj][3] * inv1;
            oh[off0 + d2] = packh2(v00, v01);
            ol[off0 + d2] = packh2(v00 - h16(v00), v01 - h16(v01));
            oh[off1 + d2] = packh2(v10, v11);
            ol[off1 + d2] = packh2(v10 - h16(v10), v11 - h16(v11));
        }
    }
}

// ---------------------------------------------------------------------------
extern "C" void kernel_launch(void* const* d_in, const int* in_sizes, int n_in,
                              void* d_out, int out_size)
{
    const float* x     = (const float*)d_in[0];
    const float* gamma = (const float*)d_in[1];
    const float* beta  = (const float*)d_in[2];
    const float* w_qkv = (const float*)d_in[3];
    const float* w_out = (const float*)d_in[4];
    const float* b_out = (const float*)d_in[5];
    float* out = (float*)d_out;

    uint32_t *xh, *qh, *ah, *al, *wqh, *woh;
    cudaGetSymbolAddress((void**)&xh,  g_xh);
    cudaGetSymbolAddress((void**)&qh,  g_qh);
    cudaGetSymbolAddress((void**)&ah,  g_ah);
    cudaGetSymbolAddress((void**)&al,  g_al);
    cudaGetSymbolAddress((void**)&wqh, g_wqh);
    cudaGetSymbolAddress((void**)&woh, g_woh);

    // 0) weight pre-split (hi only)
    wsplit_kernel<<<(QKV3 * C2 + 255) / 256, 256>>>(w_qkv, wqh, QKV3 * C2);
    wsplit_kernel<<<(C_ * C2 + 255) / 256, 256>>>(w_out, woh, C_ * C2);

    // 1) LayerNorm -> packed fp16 (hi)
    ln_kernel<<<NTOK / 8, 256>>>(x, gamma, beta, xh);

    // 2) QKV projection, pure fp16 -> packed fp16
    gemm_q<<<dim3(QKV3 / 128, NTOK / 128), 256>>>(
        xh, wqh, qh, NTOK, QKV3, C2);

    // 3) Flash attention -> packed (hi, lo)
    attn_p<<<dim3(T_ / 128, B_ * H_), 128>>>(qh, ah, al);

    // 4) Output projection + bias -> fp32; x2 split, 128x128 tiles (R11 form)
    gemm_o<<<dim3(C_ / 128, NTOK / 128), 256>>>(
        ah, al, woh, b_out, out, NTOK, C_, C2);
}